// round 1
// baseline (speedup 1.0000x reference)
#include <cuda_runtime.h>
#include <math.h>

#define N_ART 50000
#define N_ENT 100000
#define N_FACT 50000
#define NEDGE 200000
#define FEATD 769
#define HIDD 128

// Scratch (static device arrays; no allocation allowed)
__device__ float g_B[12800000];    // lin_l output, up to 100k x 128
__device__ float g_P[12800000];    // projected src features, up to 100k x 128
__device__ float g_A[12800000];    // aggregation accumulator, up to 100k x 128
__device__ float g_h1[25600000];   // layer-1 hidden: art | ent | fact
__device__ float g_cnt[500000];    // per-edge-type in-degree counts
__device__ float g_z[3200000];     // head hidden 50000 x 64

// ---------------------------------------------------------------------------
// C[M,N] = act(A)[M,K] @ W[N,K]^T (+bias), 128x128x8 SIMT tile, 256 threads
// ---------------------------------------------------------------------------
template<bool RELU_IN, bool RELU_OUT, bool HAS_BIAS>
__global__ __launch_bounds__(256) void gemm_tn(
    const float* __restrict__ A, const float* __restrict__ W,
    const float* __restrict__ bias, float* __restrict__ C,
    int M, int N, int K)
{
    __shared__ float As[8][128];
    __shared__ float Ws[8][128];
    const int tid = threadIdx.x;
    const int tx = tid & 15, ty = tid >> 4;
    const int rowBase = blockIdx.y * 128, colBase = blockIdx.x * 128;

    float acc[8][8];
#pragma unroll
    for (int i = 0; i < 8; i++)
#pragma unroll
        for (int j = 0; j < 8; j++) acc[i][j] = 0.f;

    for (int k0 = 0; k0 < K; k0 += 8) {
#pragma unroll
        for (int t = 0; t < 4; t++) {
            int idx = tid + t * 256;
            int k = idx & 7, r = idx >> 3;
            int row = rowBase + r, kk = k0 + k;
            float v = 0.f;
            if (row < M && kk < K) {
                v = A[(size_t)row * K + kk];
                if (RELU_IN) v = fmaxf(v, 0.f);
            }
            As[k][r] = v;
        }
#pragma unroll
        for (int t = 0; t < 4; t++) {
            int idx = tid + t * 256;
            int k = idx & 7, c = idx >> 3;
            int col = colBase + c, kk = k0 + k;
            float v = 0.f;
            if (col < N && kk < K) v = W[(size_t)col * K + kk];
            Ws[k][c] = v;
        }
        __syncthreads();
#pragma unroll
        for (int k = 0; k < 8; k++) {
            float4 a0 = *(const float4*)&As[k][ty * 8];
            float4 a1 = *(const float4*)&As[k][ty * 8 + 4];
            float4 b0 = *(const float4*)&Ws[k][tx * 8];
            float4 b1 = *(const float4*)&Ws[k][tx * 8 + 4];
            float av[8] = {a0.x, a0.y, a0.z, a0.w, a1.x, a1.y, a1.z, a1.w};
            float bv[8] = {b0.x, b0.y, b0.z, b0.w, b1.x, b1.y, b1.z, b1.w};
#pragma unroll
            for (int i = 0; i < 8; i++)
#pragma unroll
                for (int j = 0; j < 8; j++) acc[i][j] += av[i] * bv[j];
        }
        __syncthreads();
    }

#pragma unroll
    for (int i = 0; i < 8; i++) {
        int row = rowBase + ty * 8 + i;
        if (row < M) {
#pragma unroll
            for (int j = 0; j < 8; j++) {
                int col = colBase + tx * 8 + j;
                if (col < N) {
                    float v = acc[i][j];
                    if (HAS_BIAS) v += bias[col];
                    if (RELU_OUT) v = fmaxf(v, 0.f);
                    C[(size_t)row * N + col] = v;
                }
            }
        }
    }
}

// ---------------------------------------------------------------------------
// In-degree counts (as float; exact for counts < 2^24)
// ---------------------------------------------------------------------------
__global__ void count_k(const int* __restrict__ di, float* __restrict__ cnt, int E)
{
    int e = blockIdx.x * blockDim.x + threadIdx.x;
    if (e < E) atomicAdd(&cnt[di[e]], 1.0f);
}

// ---------------------------------------------------------------------------
// Scatter: A[di[e]] += P[si[e]]  (one warp per edge, 128 floats each)
// ---------------------------------------------------------------------------
__global__ void scatter_k(const float* __restrict__ P, const int* __restrict__ si,
                          const int* __restrict__ di, float* __restrict__ Acc, int E)
{
    int w = (blockIdx.x * blockDim.x + threadIdx.x) >> 5;
    int lane = threadIdx.x & 31;
    if (w >= E) return;
    int s = __ldg(si + w), d = __ldg(di + w);
    float4 v = *(const float4*)(P + (size_t)s * HIDD + lane * 4);
    float* dst = Acc + (size_t)d * HIDD + lane * 4;
    atomicAdd(dst + 0, v.x);
    atomicAdd(dst + 1, v.y);
    atomicAdd(dst + 2, v.z);
    atomicAdd(dst + 3, v.w);
}

// ---------------------------------------------------------------------------
// Combine: o = B[row] + A[row]/max(cnt,1); H[row] += o / max(||o||, 1e-12)
// one warp per row (128 floats = 32 lanes x float4)
// ---------------------------------------------------------------------------
__global__ void combine_norm_add(const float* __restrict__ B, const float* __restrict__ Acc,
                                 const float* __restrict__ cnt, float* __restrict__ H, int n)
{
    int w = (blockIdx.x * blockDim.x + threadIdx.x) >> 5;
    int lane = threadIdx.x & 31;
    if (w >= n) return;
    float inv = 1.0f / fmaxf(cnt[w], 1.0f);
    size_t off = (size_t)w * HIDD + lane * 4;
    float4 b = *(const float4*)(B + off);
    float4 a = *(const float4*)(Acc + off);
    float4 o;
    o.x = b.x + a.x * inv;
    o.y = b.y + a.y * inv;
    o.z = b.z + a.z * inv;
    o.w = b.w + a.w * inv;
    float ss = o.x * o.x + o.y * o.y + o.z * o.z + o.w * o.w;
#pragma unroll
    for (int sh = 16; sh; sh >>= 1) ss += __shfl_xor_sync(0xffffffffu, ss, sh);
    float scale = 1.0f / fmaxf(sqrtf(ss), 1e-12f);
    float4 h = *(float4*)(H + off);
    h.x += o.x * scale;
    h.y += o.y * scale;
    h.z += o.z * scale;
    h.w += o.w * scale;
    *(float4*)(H + off) = h;
}

__global__ void relu_k(float* __restrict__ p, size_t n)
{
    size_t i = (size_t)blockIdx.x * blockDim.x + threadIdx.x;
    if (i < n) p[i] = fmaxf(p[i], 0.f);
}

// logits[row] = z[row] @ W2^T + b2   (W2: [2,64])
__global__ void head2_k(const float* __restrict__ Z, const float* __restrict__ W2,
                        const float* __restrict__ b2, float* __restrict__ out, int n)
{
    int row = blockIdx.x * blockDim.x + threadIdx.x;
    if (row >= n) return;
    float acc0 = b2[0], acc1 = b2[1];
    const float* z = Z + (size_t)row * 64;
#pragma unroll
    for (int k = 0; k < 64; k++) {
        float zv = z[k];
        acc0 += zv * __ldg(W2 + k);
        acc1 += zv * __ldg(W2 + 64 + k);
    }
    out[row * 2 + 0] = acc0;
    out[row * 2 + 1] = acc1;
}

// ---------------------------------------------------------------------------
extern "C" void kernel_launch(void* const* d_in, const int* in_sizes, int n_in,
                              void* d_out_, int out_size)
{
    const float* x[3] = {(const float*)d_in[0], (const float*)d_in[1], (const float*)d_in[2]};
    const int nn[3] = {N_ART, N_ENT, N_FACT};
    const int* ei[5];
    for (int i = 0; i < 5; i++) ei[i] = (const int*)d_in[3 + i];
    const float* c1llw = (const float*)d_in[8];
    const float* c1llb = (const float*)d_in[9];
    const float* c1lrw = (const float*)d_in[10];
    const float* c2llw = (const float*)d_in[11];
    const float* c2llb = (const float*)d_in[12];
    const float* c2lrw = (const float*)d_in[13];
    const float* hw1 = (const float*)d_in[14];
    const float* hb1 = (const float*)d_in[15];
    const float* hw2 = (const float*)d_in[16];
    const float* hb2 = (const float*)d_in[17];
    float* out = (float*)d_out_;

    // edge types: (src node type, dst node type); 0=art, 1=ent, 2=fact
    static const int SRC[5] = {0, 0, 1, 1, 2};
    static const int DST[5] = {1, 2, 0, 2, 1};

    float *B, *P, *Acc, *H1, *CNT, *Z;
    cudaGetSymbolAddress((void**)&B, g_B);
    cudaGetSymbolAddress((void**)&P, g_P);
    cudaGetSymbolAddress((void**)&Acc, g_A);
    cudaGetSymbolAddress((void**)&H1, g_h1);
    cudaGetSymbolAddress((void**)&CNT, g_cnt);
    cudaGetSymbolAddress((void**)&Z, g_z);

    float* h1p[3] = {H1, H1 + (size_t)N_ART * HIDD, H1 + (size_t)(N_ART + N_ENT) * HIDD};
    float* h2p[3] = {out + 100000,
                     out + 100000 + (size_t)N_ART * HIDD,
                     out + 100000 + (size_t)(N_ART + N_ENT) * HIDD};

    dim3 blk(256);

    // --- in-degree counts per edge type (reused by both layers) ---
    cudaMemsetAsync(CNT, 0, 500000 * sizeof(float));
    for (int i = 0; i < 5; i++)
        count_k<<<(NEDGE + 255) / 256, 256>>>(ei[i] + NEDGE, CNT + i * 100000, NEDGE);

    // --- layer 1: FEAT(769) -> HID(128) ---
    cudaMemsetAsync(H1, 0, (size_t)25600000 * sizeof(float));
    for (int i = 0; i < 5; i++) {
        int s = SRC[i], d = DST[i];
        dim3 gd(1, (nn[d] + 127) / 128), gs(1, (nn[s] + 127) / 128);
        gemm_tn<false, false, true><<<gd, blk>>>(
            x[d], c1llw + (size_t)i * HIDD * FEATD, c1llb + i * HIDD, B, nn[d], HIDD, FEATD);
        gemm_tn<false, false, false><<<gs, blk>>>(
            x[s], c1lrw + (size_t)i * HIDD * FEATD, nullptr, P, nn[s], HIDD, FEATD);
        cudaMemsetAsync(Acc, 0, (size_t)nn[d] * HIDD * sizeof(float));
        scatter_k<<<(NEDGE * 32 + 255) / 256, 256>>>(P, ei[i], ei[i] + NEDGE, Acc, NEDGE);
        combine_norm_add<<<(nn[d] + 7) / 8, 256>>>(B, Acc, CNT + i * 100000, h1p[d], nn[d]);
    }

    // --- layer 2: HID -> HID (relu applied on input inside GEMM) ---
    cudaMemsetAsync(out + 100000, 0, (size_t)25600000 * sizeof(float));
    for (int i = 0; i < 5; i++) {
        int s = SRC[i], d = DST[i];
        dim3 gd(1, (nn[d] + 127) / 128), gs(1, (nn[s] + 127) / 128);
        gemm_tn<true, false, true><<<gd, blk>>>(
            h1p[d], c2llw + (size_t)i * HIDD * HIDD, c2llb + i * HIDD, B, nn[d], HIDD, HIDD);
        gemm_tn<true, false, false><<<gs, blk>>>(
            h1p[s], c2lrw + (size_t)i * HIDD * HIDD, nullptr, P, nn[s], HIDD, HIDD);
        cudaMemsetAsync(Acc, 0, (size_t)nn[d] * HIDD * sizeof(float));
        scatter_k<<<(NEDGE * 32 + 255) / 256, 256>>>(P, ei[i], ei[i] + NEDGE, Acc, NEDGE);
        combine_norm_add<<<(nn[d] + 7) / 8, 256>>>(B, Acc, CNT + i * 100000, h2p[d], nn[d]);
    }

    // --- final relu on all h2 outputs (in-place in d_out) ---
    relu_k<<<(25600000 + 255) / 256, 256>>>(out + 100000, (size_t)25600000);

    // --- head MLP on h_art ---
    gemm_tn<false, true, true><<<dim3(1, (N_ART + 127) / 128), blk>>>(
        out + 100000, hw1, hb1, Z, N_ART, 64, HIDD);
    head2_k<<<(N_ART + 255) / 256, 256>>>(Z, hw2, hb2, out, N_ART);
}

// round 3
// speedup vs baseline: 2.2200x; 2.2200x over previous
#include <cuda_runtime.h>
#include <cuda_bf16.h>
#include <math.h>
#include <stdint.h>

#define N_ART 50000
#define N_ENT 100000
#define N_FACT 50000
#define NEDGE 200000
#define FEATD 769
#define HIDD 128

// 3-way split: A3=[hi|lo|hi], W3=[hi|hi|lo]; section stride S, total 3S
#define K1S 800
#define K1P 2400
#define K2S 128
#define K2P 384

// ---------------------------------------------------------------------------
// Scratch (static device arrays; no allocation allowed)
// ---------------------------------------------------------------------------
__device__ float g_B[12800000];                 // lin_l output, up to 100k x 128
__device__ float g_P[12800000];                 // lin_r projected src
__device__ float g_A[12800000];                 // aggregation accumulator
__device__ float g_h1[25600000];                // layer-1 hidden: art|ent|fact
__device__ float g_cnt[500000];                 // per-edge-type in-degree counts
__device__ float g_z[3200000];                  // head hidden 50000 x 64
__device__ __nv_bfloat16 g_X2[480000000];       // split features: 200k x 2400
__device__ __nv_bfloat16 g_H1s[76800000];       // split relu(h1): 200k x 384
__device__ __nv_bfloat16 g_W1L[1536000];        // c1 lin_l split: 640 x 2400
__device__ __nv_bfloat16 g_W1R[1536000];        // c1 lin_r split
__device__ __nv_bfloat16 g_W2L[245760];         // c2 lin_l split: 640 x 384
__device__ __nv_bfloat16 g_W2R[245760];         // c2 lin_r split

// ---------------------------------------------------------------------------
__device__ __forceinline__ uint32_t smem_u32(const void* p) {
    uint32_t a;
    asm("{ .reg .u64 t; cvta.to.shared.u64 t, %1; cvt.u32.u64 %0, t; }"
        : "=r"(a) : "l"(p));
    return a;
}

#define CP_ASYNC16(dst, src) \
    asm volatile("cp.async.cg.shared.global [%0], [%1], 16;" :: "r"(dst), "l"(src))
#define CP_COMMIT() asm volatile("cp.async.commit_group;" ::: "memory")
#define CP_WAIT1()  asm volatile("cp.async.wait_group 1;" ::: "memory")

// ---------------------------------------------------------------------------
// Tensor-core GEMM via mma.sync: C[M,128] = A3[M,Kp] @ W3[128,Kp]^T (+bias)
// CTA: 128 threads (4 warps, 2x2), tile 128x128, K-chunk 32, double-buffered.
// SMEM row stride 40 bf16 (80B) -> conflict-free ldmatrix.
// ---------------------------------------------------------------------------
#define SSTR 40
#define BUFB 10240  // 128*40*2 bytes

__global__ __launch_bounds__(128) void gemm_mma(
    const __nv_bfloat16* __restrict__ A, const __nv_bfloat16* __restrict__ W,
    const float* __restrict__ bias, float* __restrict__ C, int M, int Kp)
{
    __shared__ __align__(16) __nv_bfloat16 As[2][128 * SSTR];
    __shared__ __align__(16) __nv_bfloat16 Ws[2][128 * SSTR];
    const int tid = threadIdx.x, lane = tid & 31, warp = tid >> 5;
    const int mW = (warp >> 1) * 64, nW = (warp & 1) * 64;
    const int rowBase = blockIdx.x * 128;
    const int NC = Kp >> 5;
    const uint32_t asu = smem_u32(As), wsu = smem_u32(Ws);

    float acc[4][8][4];
#pragma unroll
    for (int i = 0; i < 4; i++)
#pragma unroll
        for (int j = 0; j < 8; j++)
#pragma unroll
            for (int q = 0; q < 4; q++) acc[i][j][q] = 0.f;

    // per-thread load slots: idx = tid + i*128 -> row idx>>2, quad idx&3
    const int lr = tid >> 2, lq = tid & 3;

#define LOAD_A(c, buf) do { \
    int k0 = (c) * 32; \
    _Pragma("unroll") \
    for (int i = 0; i < 4; i++) { \
        int r = lr + i * 32; \
        int grow = rowBase + r; if (grow >= M) grow = M - 1; \
        CP_ASYNC16(asu + (buf) * BUFB + r * 80 + lq * 16, \
                   A + (size_t)grow * Kp + k0 + lq * 8); \
    } } while (0)

#define LOAD_W(c, buf) do { \
    int k0 = (c) * 32; \
    _Pragma("unroll") \
    for (int i = 0; i < 4; i++) { \
        int r = lr + i * 32; \
        CP_ASYNC16(wsu + (buf) * BUFB + r * 80 + lq * 16, \
                   W + (size_t)r * Kp + k0 + lq * 8); \
    } } while (0)

    LOAD_A(0, 0); LOAD_W(0, 0); CP_COMMIT();
    LOAD_A(1, 1); LOAD_W(1, 1); CP_COMMIT();

    // ldmatrix address lanes
    const int a_row = (lane & 15);
    const int a_sel = (lane >> 4) & 1;             // col +8 elems
    const int b_row = (lane & 7) + ((lane & 16) >> 1);  // +8 rows for m2/m3
    const int b_sel = (lane >> 3) & 1;             // col +8 elems

    for (int c = 0; c < NC; c++) {
        CP_WAIT1();
        __syncthreads();
        int buf = c & 1;
        uint32_t abase = asu + buf * BUFB;
        uint32_t wbase = wsu + buf * BUFB;
#pragma unroll
        for (int kh = 0; kh < 2; kh++) {
            uint32_t ar[4][4], br[8][2];
#pragma unroll
            for (int mi = 0; mi < 4; mi++) {
                uint32_t addr = abase + (mW + mi * 16 + a_row) * 80 + kh * 32 + a_sel * 16;
                asm volatile(
                    "ldmatrix.sync.aligned.m8n8.x4.shared.b16 {%0,%1,%2,%3}, [%4];"
                    : "=r"(ar[mi][0]), "=r"(ar[mi][1]), "=r"(ar[mi][2]), "=r"(ar[mi][3])
                    : "r"(addr));
            }
#pragma unroll
            for (int pi = 0; pi < 4; pi++) {
                uint32_t addr = wbase + (nW + pi * 16 + b_row) * 80 + kh * 32 + b_sel * 16;
                asm volatile(
                    "ldmatrix.sync.aligned.m8n8.x4.shared.b16 {%0,%1,%2,%3}, [%4];"
                    : "=r"(br[2 * pi][0]), "=r"(br[2 * pi][1]),
                      "=r"(br[2 * pi + 1][0]), "=r"(br[2 * pi + 1][1])
                    : "r"(addr));
            }
#pragma unroll
            for (int mi = 0; mi < 4; mi++)
#pragma unroll
                for (int ni = 0; ni < 8; ni++) {
                    asm volatile(
                        "mma.sync.aligned.m16n8k16.row.col.f32.bf16.bf16.f32 "
                        "{%0,%1,%2,%3}, {%4,%5,%6,%7}, {%8,%9}, {%0,%1,%2,%3};"
                        : "+f"(acc[mi][ni][0]), "+f"(acc[mi][ni][1]),
                          "+f"(acc[mi][ni][2]), "+f"(acc[mi][ni][3])
                        : "r"(ar[mi][0]), "r"(ar[mi][1]), "r"(ar[mi][2]), "r"(ar[mi][3]),
                          "r"(br[ni][0]), "r"(br[ni][1]));
                }
        }
        __syncthreads();
        if (c + 2 < NC) { LOAD_A(c + 2, buf); LOAD_W(c + 2, buf); }
        CP_COMMIT();
    }
#undef LOAD_A
#undef LOAD_W

    // epilogue
    const int g = lane >> 2, t = lane & 3;
#pragma unroll
    for (int mi = 0; mi < 4; mi++) {
        int r0 = rowBase + mW + mi * 16 + g;
#pragma unroll
        for (int ni = 0; ni < 8; ni++) {
            int col = nW + ni * 8 + t * 2;
            float bx = 0.f, by = 0.f;
            if (bias) { bx = bias[col]; by = bias[col + 1]; }
            if (r0 < M) {
                float2 v = make_float2(acc[mi][ni][0] + bx, acc[mi][ni][1] + by);
                *(float2*)(C + (size_t)r0 * 128 + col) = v;
            }
            if (r0 + 8 < M) {
                float2 v = make_float2(acc[mi][ni][2] + bx, acc[mi][ni][3] + by);
                *(float2*)(C + (size_t)(r0 + 8) * 128 + col) = v;
            }
        }
    }
}

// ---------------------------------------------------------------------------
// 3-way splits: A3 = [hi | lo | hi], W3 = [hi | hi | lo]; pads zeroed.
// ---------------------------------------------------------------------------
template<bool RELU>
__global__ void split3_A(const float* __restrict__ in, __nv_bfloat16* __restrict__ out,
                         int M, int K, int S)
{
    long long idx = (long long)blockIdx.x * blockDim.x + threadIdx.x;
    if (idx >= (long long)M * S) return;
    int row = (int)(idx / S);
    int k = (int)(idx - (long long)row * S);
    __nv_bfloat16 hi = __float2bfloat16(0.f), lo = hi;
    if (k < K) {
        float v = in[(size_t)row * K + k];
        if (RELU) v = fmaxf(v, 0.f);
        hi = __float2bfloat16(v);
        lo = __float2bfloat16(v - __bfloat162float(hi));
    }
    size_t o = (size_t)row * (3 * S) + k;
    out[o] = hi;
    out[o + S] = lo;
    out[o + 2 * S] = hi;
}

__global__ void split3_W(const float* __restrict__ in, __nv_bfloat16* __restrict__ out,
                         int M, int K, int S)
{
    long long idx = (long long)blockIdx.x * blockDim.x + threadIdx.x;
    if (idx >= (long long)M * S) return;
    int row = (int)(idx / S);
    int k = (int)(idx - (long long)row * S);
    __nv_bfloat16 hi = __float2bfloat16(0.f), lo = hi;
    if (k < K) {
        float v = in[(size_t)row * K + k];
        hi = __float2bfloat16(v);
        lo = __float2bfloat16(v - __bfloat162float(hi));
    }
    size_t o = (size_t)row * (3 * S) + k;
    out[o] = hi;
    out[o + S] = hi;
    out[o + 2 * S] = lo;
}

// ---------------------------------------------------------------------------
// SIMT GEMM for the 64-wide head: C = A @ W^T (+bias, relu-out)
// ---------------------------------------------------------------------------
template<bool RELU_OUT>
__global__ __launch_bounds__(256) void gemm_tn(
    const float* __restrict__ A, const float* __restrict__ W,
    const float* __restrict__ bias, float* __restrict__ C,
    int M, int N, int K)
{
    __shared__ float As[8][128];
    __shared__ float Ws[8][128];
    const int tid = threadIdx.x;
    const int tx = tid & 15, ty = tid >> 4;
    const int rowBase = blockIdx.y * 128, colBase = 0;

    float acc[8][8];
#pragma unroll
    for (int i = 0; i < 8; i++)
#pragma unroll
        for (int j = 0; j < 8; j++) acc[i][j] = 0.f;

    for (int k0 = 0; k0 < K; k0 += 8) {
#pragma unroll
        for (int t = 0; t < 4; t++) {
            int idx = tid + t * 256;
            int k = idx & 7, r = idx >> 3;
            int row = rowBase + r, kk = k0 + k;
            float v = 0.f;
            if (row < M && kk < K) v = A[(size_t)row * K + kk];
            As[k][r] = v;
        }
#pragma unroll
        for (int t = 0; t < 4; t++) {
            int idx = tid + t * 256;
            int k = idx & 7, c = idx >> 3;
            int col = colBase + c, kk = k0 + k;
            float v = 0.f;
            if (col < N && kk < K) v = W[(size_t)col * K + kk];
            Ws[k][c] = v;
        }
        __syncthreads();
#pragma unroll
        for (int k = 0; k < 8; k++) {
            float4 a0 = *(const float4*)&As[k][ty * 8];
            float4 a1 = *(const float4*)&As[k][ty * 8 + 4];
            float4 b0 = *(const float4*)&Ws[k][tx * 8];
            float4 b1 = *(const float4*)&Ws[k][tx * 8 + 4];
            float av[8] = {a0.x, a0.y, a0.z, a0.w, a1.x, a1.y, a1.z, a1.w};
            float bv[8] = {b0.x, b0.y, b0.z, b0.w, b1.x, b1.y, b1.z, b1.w};
#pragma unroll
            for (int i = 0; i < 8; i++)
#pragma unroll
                for (int j = 0; j < 8; j++) acc[i][j] += av[i] * bv[j];
        }
        __syncthreads();
    }

#pragma unroll
    for (int i = 0; i < 8; i++) {
        int row = rowBase + ty * 8 + i;
        if (row < M) {
#pragma unroll
            for (int j = 0; j < 8; j++) {
                int col = colBase + tx * 8 + j;
                if (col < N) {
                    float v = acc[i][j] + bias[col];
                    if (RELU_OUT) v = fmaxf(v, 0.f);
                    C[(size_t)row * N + col] = v;
                }
            }
        }
    }
}

// ---------------------------------------------------------------------------
__global__ void count_k(const int* __restrict__ di, float* __restrict__ cnt, int E)
{
    int e = blockIdx.x * blockDim.x + threadIdx.x;
    if (e < E) atomicAdd(&cnt[di[e]], 1.0f);
}

__global__ void scatter_k(const float* __restrict__ P, const int* __restrict__ si,
                          const int* __restrict__ di, float* __restrict__ Acc, int E)
{
    int w = (blockIdx.x * blockDim.x + threadIdx.x) >> 5;
    int lane = threadIdx.x & 31;
    if (w >= E) return;
    int s = __ldg(si + w), d = __ldg(di + w);
    float4 v = *(const float4*)(P + (size_t)s * HIDD + lane * 4);
    float* dst = Acc + (size_t)d * HIDD + lane * 4;
    atomicAdd(dst + 0, v.x);
    atomicAdd(dst + 1, v.y);
    atomicAdd(dst + 2, v.z);
    atomicAdd(dst + 3, v.w);
}

__global__ void combine_norm_add(const float* __restrict__ B, const float* __restrict__ Acc,
                                 const float* __restrict__ cnt, float* __restrict__ H, int n)
{
    int w = (blockIdx.x * blockDim.x + threadIdx.x) >> 5;
    int lane = threadIdx.x & 31;
    if (w >= n) return;
    float inv = 1.0f / fmaxf(cnt[w], 1.0f);
    size_t off = (size_t)w * HIDD + lane * 4;
    float4 b = *(const float4*)(B + off);
    float4 a = *(const float4*)(Acc + off);
    float4 o;
    o.x = b.x + a.x * inv;
    o.y = b.y + a.y * inv;
    o.z = b.z + a.z * inv;
    o.w = b.w + a.w * inv;
    float ss = o.x * o.x + o.y * o.y + o.z * o.z + o.w * o.w;
#pragma unroll
    for (int sh = 16; sh; sh >>= 1) ss += __shfl_xor_sync(0xffffffffu, ss, sh);
    float scale = 1.0f / fmaxf(sqrtf(ss), 1e-12f);
    float4 h = *(float4*)(H + off);
    h.x += o.x * scale;
    h.y += o.y * scale;
    h.z += o.z * scale;
    h.w += o.w * scale;
    *(float4*)(H + off) = h;
}

__global__ void relu_k(float* __restrict__ p, size_t n)
{
    size_t i = (size_t)blockIdx.x * blockDim.x + threadIdx.x;
    if (i < n) p[i] = fmaxf(p[i], 0.f);
}

__global__ void head2_k(const float* __restrict__ Z, const float* __restrict__ W2,
                        const float* __restrict__ b2, float* __restrict__ out, int n)
{
    int row = blockIdx.x * blockDim.x + threadIdx.x;
    if (row >= n) return;
    float acc0 = b2[0], acc1 = b2[1];
    const float* z = Z + (size_t)row * 64;
#pragma unroll
    for (int k = 0; k < 64; k++) {
        float zv = z[k];
        acc0 += zv * __ldg(W2 + k);
        acc1 += zv * __ldg(W2 + 64 + k);
    }
    out[row * 2 + 0] = acc0;
    out[row * 2 + 1] = acc1;
}

// ---------------------------------------------------------------------------
extern "C" void kernel_launch(void* const* d_in, const int* in_sizes, int n_in,
                              void* d_out_, int out_size)
{
    const float* x[3] = {(const float*)d_in[0], (const float*)d_in[1], (const float*)d_in[2]};
    const int nn[3] = {N_ART, N_ENT, N_FACT};
    const int* ei[5];
    for (int i = 0; i < 5; i++) ei[i] = (const int*)d_in[3 + i];
    const float* c1llw = (const float*)d_in[8];
    const float* c1llb = (const float*)d_in[9];
    const float* c1lrw = (const float*)d_in[10];
    const float* c2llw = (const float*)d_in[11];
    const float* c2llb = (const float*)d_in[12];
    const float* c2lrw = (const float*)d_in[13];
    const float* hw1 = (const float*)d_in[14];
    const float* hb1 = (const float*)d_in[15];
    const float* hw2 = (const float*)d_in[16];
    const float* hb2 = (const float*)d_in[17];
    float* out = (float*)d_out_;

    static const int SRC[5] = {0, 0, 1, 1, 2};
    static const int DST[5] = {1, 2, 0, 2, 1};

    float *B, *P, *Acc, *H1, *CNT, *Z;
    __nv_bfloat16 *X2, *H1s, *W1L, *W1R, *W2L, *W2R;
    cudaGetSymbolAddress((void**)&B, g_B);
    cudaGetSymbolAddress((void**)&P, g_P);
    cudaGetSymbolAddress((void**)&Acc, g_A);
    cudaGetSymbolAddress((void**)&H1, g_h1);
    cudaGetSymbolAddress((void**)&CNT, g_cnt);
    cudaGetSymbolAddress((void**)&Z, g_z);
    cudaGetSymbolAddress((void**)&X2, g_X2);
    cudaGetSymbolAddress((void**)&H1s, g_H1s);
    cudaGetSymbolAddress((void**)&W1L, g_W1L);
    cudaGetSymbolAddress((void**)&W1R, g_W1R);
    cudaGetSymbolAddress((void**)&W2L, g_W2L);
    cudaGetSymbolAddress((void**)&W2R, g_W2R);

    const size_t X2OFF[3] = {0, (size_t)N_ART * K1P, (size_t)(N_ART + N_ENT) * K1P};
    const size_t H1SOFF[3] = {0, (size_t)N_ART * K2P, (size_t)(N_ART + N_ENT) * K2P};
    float* h1p[3] = {H1, H1 + (size_t)N_ART * HIDD, H1 + (size_t)(N_ART + N_ENT) * HIDD};
    float* h2p[3] = {out + 100000,
                     out + 100000 + (size_t)N_ART * HIDD,
                     out + 100000 + (size_t)(N_ART + N_ENT) * HIDD};

    // --- split-convert features + weights ---
    for (int t = 0; t < 3; t++) {
        long long n = (long long)nn[t] * K1S;
        split3_A<false><<<(unsigned)((n + 255) / 256), 256>>>(x[t], X2 + X2OFF[t], nn[t], FEATD, K1S);
    }
    {
        long long n = 640LL * K1S;
        split3_W<<<(unsigned)((n + 255) / 256), 256>>>(c1llw, W1L, 640, FEATD, K1S);
        split3_W<<<(unsigned)((n + 255) / 256), 256>>>(c1lrw, W1R, 640, FEATD, K1S);
        long long n2 = 640LL * K2S;
        split3_W<<<(unsigned)((n2 + 255) / 256), 256>>>(c2llw, W2L, 640, HIDD, K2S);
        split3_W<<<(unsigned)((n2 + 255) / 256), 256>>>(c2lrw, W2R, 640, HIDD, K2S);
    }

    // --- in-degree counts per edge type (reused by both layers) ---
    cudaMemsetAsync(CNT, 0, 500000 * sizeof(float));
    for (int i = 0; i < 5; i++)
        count_k<<<(NEDGE + 255) / 256, 256>>>(ei[i] + NEDGE, CNT + i * 100000, NEDGE);

    // --- layer 1: FEAT -> HID via mma.sync ---
    cudaMemsetAsync(H1, 0, (size_t)25600000 * sizeof(float));
    for (int i = 0; i < 5; i++) {
        int s = SRC[i], d = DST[i];
        gemm_mma<<<(nn[d] + 127) / 128, 128>>>(
            X2 + X2OFF[d], W1L + (size_t)i * 128 * K1P, c1llb + i * HIDD, B, nn[d], K1P);
        gemm_mma<<<(nn[s] + 127) / 128, 128>>>(
            X2 + X2OFF[s], W1R + (size_t)i * 128 * K1P, nullptr, P, nn[s], K1P);
        cudaMemsetAsync(Acc, 0, (size_t)nn[d] * HIDD * sizeof(float));
        scatter_k<<<(NEDGE * 32 + 255) / 256, 256>>>(P, ei[i], ei[i] + NEDGE, Acc, NEDGE);
        combine_norm_add<<<(nn[d] + 7) / 8, 256>>>(B, Acc, CNT + i * 100000, h1p[d], nn[d]);
    }

    // --- split relu(h1) ---
    {
        long long n = 200000LL * K2S;
        split3_A<true><<<(unsigned)((n + 255) / 256), 256>>>(H1, H1s, 200000, HIDD, K2S);
    }

    // --- layer 2: HID -> HID via mma.sync ---
    cudaMemsetAsync(out + 100000, 0, (size_t)25600000 * sizeof(float));
    for (int i = 0; i < 5; i++) {
        int s = SRC[i], d = DST[i];
        gemm_mma<<<(nn[d] + 127) / 128, 128>>>(
            H1s + H1SOFF[d], W2L + (size_t)i * 128 * K2P, c2llb + i * HIDD, B, nn[d], K2P);
        gemm_mma<<<(nn[s] + 127) / 128, 128>>>(
            H1s + H1SOFF[s], W2R + (size_t)i * 128 * K2P, nullptr, P, nn[s], K2P);
        cudaMemsetAsync(Acc, 0, (size_t)nn[d] * HIDD * sizeof(float));
        scatter_k<<<(NEDGE * 32 + 255) / 256, 256>>>(P, ei[i], ei[i] + NEDGE, Acc, NEDGE);
        combine_norm_add<<<(nn[d] + 7) / 8, 256>>>(B, Acc, CNT + i * 100000, h2p[d], nn[d]);
    }

    // --- final relu on all h2 outputs (in-place in d_out) ---
    relu_k<<<(25600000 + 255) / 256, 256>>>(out + 100000, (size_t)25600000);

    // --- head MLP on h_art ---
    gemm_tn<true><<<dim3(1, (N_ART + 127) / 128), 256>>>(
        out + 100000, hw1, hb1, Z, N_ART, 64, HIDD);
    head2_k<<<(N_ART + 255) / 256, 256>>>(Z, hw2, hb2, out, N_ART);
}

// round 6
// speedup vs baseline: 2.3305x; 1.0498x over previous
#include <cuda_runtime.h>
#include <cuda_bf16.h>
#include <math.h>
#include <stdint.h>

#define N_ART 50000
#define N_ENT 100000
#define N_FACT 50000
#define NEDGE 200000
#define FEATD 769
#define HIDD 128

#define K1S 800    // layer-1 K padded (multiple of 32)
#define K2S 128    // layer-2 K

// ---------------------------------------------------------------------------
// Scratch (static device arrays; no allocation allowed)
// ---------------------------------------------------------------------------
__device__ float g_B[12800000];                 // lin_l output, up to 100k x 128
__device__ float g_P[12800000];                 // lin_r projected src
__device__ float g_A[12800000];                 // aggregation accumulator
__device__ float g_h1[25600000];                // layer-1 hidden: art|ent|fact
__device__ float g_cnt[500000];                 // per-edge-type in-degree counts
__device__ float g_z[3200000];                  // head hidden 50000 x 64
__device__ __nv_bfloat16 g_Xs[320000000];       // feature planes: per type [hi(M*800)|lo(M*800)]
__device__ __nv_bfloat16 g_H1s[51200000];       // relu(h1) planes: [hi(200000*128)|lo(...)]
__device__ __nv_bfloat16 g_W1L[1024000];        // c1 lin_l rows [hi(800)|lo(800)]: 640 x 1600
__device__ __nv_bfloat16 g_W1R[1024000];        // c1 lin_r
__device__ __nv_bfloat16 g_W2L[163840];         // c2 lin_l rows [hi|lo]: 640 x 256
__device__ __nv_bfloat16 g_W2R[163840];         // c2 lin_r

// ---------------------------------------------------------------------------
__device__ __forceinline__ uint32_t smem_u32(const void* p) {
    uint32_t a;
    asm("{ .reg .u64 t; cvta.to.shared.u64 t, %1; cvt.u32.u64 %0, t; }"
        : "=r"(a) : "l"(p));
    return a;
}

#define CP_ASYNC16(dst, src) \
    asm volatile("cp.async.cg.shared.global [%0], [%1], 16;" :: "r"(dst), "l"(src))
#define CP_COMMIT() asm volatile("cp.async.commit_group;" ::: "memory")
#define CP_WAIT1()  asm volatile("cp.async.wait_group 1;" ::: "memory")

// SMEM: 4 planes x 2 buffers x 10240B (128 rows x 80B, 40 bf16/row)
#define SSTRB 80
#define OFF_AHI 0
#define OFF_ALO 20480
#define OFF_WHI 40960
#define OFF_WLO 61440
#define SMEM_TOT 81920

// ---------------------------------------------------------------------------
// Tensor-core GEMM, pre-split hi/lo bf16 planes (all cp.async 16B-aligned):
//   C[M,128] = A[M,S] @ W[128,S]^T (+bias), fp32-accurate via 3 passes:
//   a_hi*w_hi + a_lo*w_hi + a_hi*w_lo
// Ahi/Alo: row stride S. W: row stride 2S, [hi | lo] sections.
// CTA: 256 threads (8 warps, 4x2 over 128x128), K-chunk 32, double-buffered.
// ---------------------------------------------------------------------------
__global__ __launch_bounds__(256) void gemm_mma(
    const __nv_bfloat16* __restrict__ Ahi, const __nv_bfloat16* __restrict__ Alo,
    const __nv_bfloat16* __restrict__ W,
    const float* __restrict__ bias, float* __restrict__ C, int M, int S)
{
    extern __shared__ char sm[];
    const uint32_t sb = smem_u32(sm);
    const int tid = threadIdx.x, lane = tid & 31, warp = tid >> 5;
    const int mQ = warp >> 1, nH = warp & 1;   // 4x2 warp grid
    const int rowBase = blockIdx.x * 128;
    const int NC = S >> 5;
    const int W2S = 2 * S;

    float acc[2][8][4];
#pragma unroll
    for (int i = 0; i < 2; i++)
#pragma unroll
        for (int j = 0; j < 8; j++)
#pragma unroll
            for (int q = 0; q < 4; q++) acc[i][j][q] = 0.f;

    const int lr4 = tid >> 2, lq4 = tid & 3;   // 64 rows x 4 quads (16B each)

#define LOAD_CHUNK(c, buf) do { \
    int k0 = (c) * 32; \
    _Pragma("unroll") \
    for (int i = 0; i < 2; i++) { \
        int r = lr4 + i * 64; \
        int ga = rowBase + r; if (ga >= M) ga = M - 1; \
        uint32_t so = (buf) * 10240 + r * SSTRB + lq4 * 16; \
        CP_ASYNC16(sb + OFF_AHI + so, Ahi + (size_t)ga * S + k0 + lq4 * 8); \
        CP_ASYNC16(sb + OFF_ALO + so, Alo + (size_t)ga * S + k0 + lq4 * 8); \
        CP_ASYNC16(sb + OFF_WHI + so, W + (size_t)r * W2S + k0 + lq4 * 8); \
        CP_ASYNC16(sb + OFF_WLO + so, W + (size_t)r * W2S + S + k0 + lq4 * 8); \
    } } while (0)

    LOAD_CHUNK(0, 0); CP_COMMIT();
    if (NC > 1) { LOAD_CHUNK(1, 1); }
    CP_COMMIT();

    const int a_row = lane & 15;
    const int a_sel = (lane >> 4) & 1;
    const int b_row = (lane & 7) + ((lane & 16) >> 1);
    const int b_sel = (lane >> 3) & 1;

    auto do_pass = [&](uint32_t abase, uint32_t wbase) {
#pragma unroll
        for (int kh = 0; kh < 2; kh++) {
            uint32_t ar[2][4], br[8][2];
#pragma unroll
            for (int mi = 0; mi < 2; mi++) {
                uint32_t addr = abase + (mQ * 32 + mi * 16 + a_row) * SSTRB
                                + kh * 32 + a_sel * 16;
                asm volatile(
                    "ldmatrix.sync.aligned.m8n8.x4.shared.b16 {%0,%1,%2,%3}, [%4];"
                    : "=r"(ar[mi][0]), "=r"(ar[mi][1]), "=r"(ar[mi][2]), "=r"(ar[mi][3])
                    : "r"(addr));
            }
#pragma unroll
            for (int pi = 0; pi < 4; pi++) {
                uint32_t addr = wbase + (nH * 64 + pi * 16 + b_row) * SSTRB
                                + kh * 32 + b_sel * 16;
                asm volatile(
                    "ldmatrix.sync.aligned.m8n8.x4.shared.b16 {%0,%1,%2,%3}, [%4];"
                    : "=r"(br[2 * pi][0]), "=r"(br[2 * pi][1]),
                      "=r"(br[2 * pi + 1][0]), "=r"(br[2 * pi + 1][1])
                    : "r"(addr));
            }
#pragma unroll
            for (int mi = 0; mi < 2; mi++)
#pragma unroll
                for (int ni = 0; ni < 8; ni++) {
                    asm volatile(
                        "mma.sync.aligned.m16n8k16.row.col.f32.bf16.bf16.f32 "
                        "{%0,%1,%2,%3}, {%4,%5,%6,%7}, {%8,%9}, {%0,%1,%2,%3};"
                        : "+f"(acc[mi][ni][0]), "+f"(acc[mi][ni][1]),
                          "+f"(acc[mi][ni][2]), "+f"(acc[mi][ni][3])
                        : "r"(ar[mi][0]), "r"(ar[mi][1]), "r"(ar[mi][2]), "r"(ar[mi][3]),
                          "r"(br[ni][0]), "r"(br[ni][1]));
                }
        }
    };

    for (int c = 0; c < NC; c++) {
        CP_WAIT1();
        __syncthreads();
        uint32_t bo = (uint32_t)(c & 1) * 10240;
        do_pass(sb + OFF_AHI + bo, sb + OFF_WHI + bo);
        do_pass(sb + OFF_ALO + bo, sb + OFF_WHI + bo);
        do_pass(sb + OFF_AHI + bo, sb + OFF_WLO + bo);
        __syncthreads();
        if (c + 2 < NC) LOAD_CHUNK(c + 2, c & 1);
        CP_COMMIT();
    }
#undef LOAD_CHUNK

    // epilogue
    const int g = lane >> 2, t = lane & 3;
#pragma unroll
    for (int mi = 0; mi < 2; mi++) {
        int r0 = rowBase + mQ * 32 + mi * 16 + g;
#pragma unroll
        for (int ni = 0; ni < 8; ni++) {
            int col = nH * 64 + ni * 8 + t * 2;
            float bx = 0.f, by = 0.f;
            if (bias) { bx = bias[col]; by = bias[col + 1]; }
            if (r0 < M) {
                float2 v = make_float2(acc[mi][ni][0] + bx, acc[mi][ni][1] + by);
                *(float2*)(C + (size_t)r0 * 128 + col) = v;
            }
            if (r0 + 8 < M) {
                float2 v = make_float2(acc[mi][ni][2] + bx, acc[mi][ni][3] + by);
                *(float2*)(C + (size_t)(r0 + 8) * 128 + col) = v;
            }
        }
    }
}

// ---------------------------------------------------------------------------
// A split: fp32 [M,K] -> hi plane [M,S], lo plane [M,S] (pads zeroed)
// ---------------------------------------------------------------------------
template<bool RELU>
__global__ void split2_A(const float* __restrict__ in,
                         __nv_bfloat16* __restrict__ outHi,
                         __nv_bfloat16* __restrict__ outLo,
                         int M, int K, int S)
{
    long long idx = (long long)blockIdx.x * blockDim.x + threadIdx.x;
    if (idx >= (long long)M * S) return;
    int row = (int)(idx / S);
    int k = (int)(idx - (long long)row * S);
    __nv_bfloat16 hi = __float2bfloat16(0.f), lo = hi;
    if (k < K) {
        float v = in[(size_t)row * K + k];
        if (RELU) v = fmaxf(v, 0.f);
        hi = __float2bfloat16(v);
        lo = __float2bfloat16(v - __bfloat162float(hi));
    }
    size_t o = (size_t)row * S + k;
    outHi[o] = hi;
    outLo[o] = lo;
}

// Weight split: rows [hi(S) | lo(S)], stride 2S
__global__ void split2_W(const float* __restrict__ in, __nv_bfloat16* __restrict__ out,
                         int M, int K, int S)
{
    long long idx = (long long)blockIdx.x * blockDim.x + threadIdx.x;
    if (idx >= (long long)M * S) return;
    int row = (int)(idx / S);
    int k = (int)(idx - (long long)row * S);
    __nv_bfloat16 hi = __float2bfloat16(0.f), lo = hi;
    if (k < K) {
        float v = in[(size_t)row * K + k];
        hi = __float2bfloat16(v);
        lo = __float2bfloat16(v - __bfloat162float(hi));
    }
    size_t o = (size_t)row * (2 * S) + k;
    out[o] = hi;
    out[o + S] = lo;
}

// ---------------------------------------------------------------------------
// SIMT GEMM for the 64-wide head: C = A @ W^T (+bias, relu-out)
// ---------------------------------------------------------------------------
template<bool RELU_OUT>
__global__ __launch_bounds__(256) void gemm_tn(
    const float* __restrict__ A, const float* __restrict__ W,
    const float* __restrict__ bias, float* __restrict__ C,
    int M, int N, int K)
{
    __shared__ float As[8][128];
    __shared__ float Ws[8][128];
    const int tid = threadIdx.x;
    const int tx = tid & 15, ty = tid >> 4;
    const int rowBase = blockIdx.y * 128;

    float acc[8][8];
#pragma unroll
    for (int i = 0; i < 8; i++)
#pragma unroll
        for (int j = 0; j < 8; j++) acc[i][j] = 0.f;

    for (int k0 = 0; k0 < K; k0 += 8) {
#pragma unroll
        for (int t = 0; t < 4; t++) {
            int idx = tid + t * 256;
            int k = idx & 7, r = idx >> 3;
            int row = rowBase + r, kk = k0 + k;
            float v = 0.f;
            if (row < M && kk < K) v = A[(size_t)row * K + kk];
            As[k][r] = v;
        }
#pragma unroll
        for (int t = 0; t < 4; t++) {
            int idx = tid + t * 256;
            int k = idx & 7, c = idx >> 3;
            int kk = k0 + k;
            float v = 0.f;
            if (c < N && kk < K) v = W[(size_t)c * K + kk];
            Ws[k][c] = v;
        }
        __syncthreads();
#pragma unroll
        for (int k = 0; k < 8; k++) {
            float4 a0 = *(const float4*)&As[k][ty * 8];
            float4 a1 = *(const float4*)&As[k][ty * 8 + 4];
            float4 b0 = *(const float4*)&Ws[k][tx * 8];
            float4 b1 = *(const float4*)&Ws[k][tx * 8 + 4];
            float av[8] = {a0.x, a0.y, a0.z, a0.w, a1.x, a1.y, a1.z, a1.w};
            float bv[8] = {b0.x, b0.y, b0.z, b0.w, b1.x, b1.y, b1.z, b1.w};
#pragma unroll
            for (int i = 0; i < 8; i++)
#pragma unroll
                for (int j = 0; j < 8; j++) acc[i][j] += av[i] * bv[j];
        }
        __syncthreads();
    }

#pragma unroll
    for (int i = 0; i < 8; i++) {
        int row = rowBase + ty * 8 + i;
        if (row < M) {
#pragma unroll
            for (int j = 0; j < 8; j++) {
                int col = tx * 8 + j;
                if (col < N) {
                    float v = acc[i][j] + bias[col];
                    if (RELU_OUT) v = fmaxf(v, 0.f);
                    C[(size_t)row * N + col] = v;
                }
            }
        }
    }
}

// ---------------------------------------------------------------------------
__global__ void count_k(const int* __restrict__ di, float* __restrict__ cnt, int E)
{
    int e = blockIdx.x * blockDim.x + threadIdx.x;
    if (e < E) atomicAdd(&cnt[di[e]], 1.0f);
}

// one warp per edge; scalar atomics (proven path)
__global__ void scatter_k(const float* __restrict__ P, const int* __restrict__ si,
                          const int* __restrict__ di, float* __restrict__ Acc, int E)
{
    int w = (blockIdx.x * blockDim.x + threadIdx.x) >> 5;
    int lane = threadIdx.x & 31;
    if (w >= E) return;
    int s = __ldg(si + w), d = __ldg(di + w);
    float4 v = *(const float4*)(P + (size_t)s * HIDD + lane * 4);
    float* dst = Acc + (size_t)d * HIDD + lane * 4;
    atomicAdd(dst + 0, v.x);
    atomicAdd(dst + 1, v.y);
    atomicAdd(dst + 2, v.z);
    atomicAdd(dst + 3, v.w);
}

__global__ void combine_norm_add(const float* __restrict__ B, const float* __restrict__ Acc,
                                 const float* __restrict__ cnt, float* __restrict__ H, int n)
{
    int w = (blockIdx.x * blockDim.x + threadIdx.x) >> 5;
    int lane = threadIdx.x & 31;
    if (w >= n) return;
    float inv = 1.0f / fmaxf(cnt[w], 1.0f);
    size_t off = (size_t)w * HIDD + lane * 4;
    float4 b = *(const float4*)(B + off);
    float4 a = *(const float4*)(Acc + off);
    float4 o;
    o.x = b.x + a.x * inv;
    o.y = b.y + a.y * inv;
    o.z = b.z + a.z * inv;
    o.w = b.w + a.w * inv;
    float ss = o.x * o.x + o.y * o.y + o.z * o.z + o.w * o.w;
#pragma unroll
    for (int sh = 16; sh; sh >>= 1) ss += __shfl_xor_sync(0xffffffffu, ss, sh);
    float scale = 1.0f / fmaxf(sqrtf(ss), 1e-12f);
    float4 h = *(float4*)(H + off);
    h.x += o.x * scale;
    h.y += o.y * scale;
    h.z += o.z * scale;
    h.w += o.w * scale;
    *(float4*)(H + off) = h;
}

__global__ void relu_k(float* __restrict__ p, size_t n)
{
    size_t i = (size_t)blockIdx.x * blockDim.x + threadIdx.x;
    if (i < n) p[i] = fmaxf(p[i], 0.f);
}

__global__ void head2_k(const float* __restrict__ Z, const float* __restrict__ W2,
                        const float* __restrict__ b2, float* __restrict__ out, int n)
{
    int row = blockIdx.x * blockDim.x + threadIdx.x;
    if (row >= n) return;
    float acc0 = b2[0], acc1 = b2[1];
    const float* z = Z + (size_t)row * 64;
#pragma unroll
    for (int k = 0; k < 64; k++) {
        float zv = z[k];
        acc0 += zv * __ldg(W2 + k);
        acc1 += zv * __ldg(W2 + 64 + k);
    }
    out[row * 2 + 0] = acc0;
    out[row * 2 + 1] = acc1;
}

// ---------------------------------------------------------------------------
extern "C" void kernel_launch(void* const* d_in, const int* in_sizes, int n_in,
                              void* d_out_, int out_size)
{
    const float* x[3] = {(const float*)d_in[0], (const float*)d_in[1], (const float*)d_in[2]};
    const int nn[3] = {N_ART, N_ENT, N_FACT};
    const int* ei[5];
    for (int i = 0; i < 5; i++) ei[i] = (const int*)d_in[3 + i];
    const float* c1llw = (const float*)d_in[8];
    const float* c1llb = (const float*)d_in[9];
    const float* c1lrw = (const float*)d_in[10];
    const float* c2llw = (const float*)d_in[11];
    const float* c2llb = (const float*)d_in[12];
    const float* c2lrw = (const float*)d_in[13];
    const float* hw1 = (const float*)d_in[14];
    const float* hb1 = (const float*)d_in[15];
    const float* hw2 = (const float*)d_in[16];
    const float* hb2 = (const float*)d_in[17];
    float* out = (float*)d_out_;

    static const int SRC[5] = {0, 0, 1, 1, 2};
    static const int DST[5] = {1, 2, 0, 2, 1};

    float *B, *P, *Acc, *H1, *CNT, *Z;
    __nv_bfloat16 *Xs, *H1s, *W1L, *W1R, *W2L, *W2R;
    cudaGetSymbolAddress((void**)&B, g_B);
    cudaGetSymbolAddress((void**)&P, g_P);
    cudaGetSymbolAddress((void**)&Acc, g_A);
    cudaGetSymbolAddress((void**)&H1, g_h1);
    cudaGetSymbolAddress((void**)&CNT, g_cnt);
    cudaGetSymbolAddress((void**)&Z, g_z);
    cudaGetSymbolAddress((void**)&Xs, g_Xs);
    cudaGetSymbolAddress((void**)&H1s, g_H1s);
    cudaGetSymbolAddress((void**)&W1L, g_W1L);
    cudaGetSymbolAddress((void**)&W1R, g_W1R);
    cudaGetSymbolAddress((void**)&W2L, g_W2L);
    cudaGetSymbolAddress((void**)&W2R, g_W2R);

    cudaFuncSetAttribute(gemm_mma, cudaFuncAttributeMaxDynamicSharedMemorySize, SMEM_TOT);

    // feature plane blocks: per type [hi(M*K1S) | lo(M*K1S)]
    const size_t XB[3] = {0,
                          (size_t)N_ART * 2 * K1S,
                          (size_t)(N_ART + N_ENT) * 2 * K1S};
    // h1s plane blocks (one 200000-row matrix): hi at 0, lo at 200000*K2S
    const size_t H1SLO = (size_t)200000 * K2S;
    const size_t R0[3] = {0, (size_t)N_ART, (size_t)(N_ART + N_ENT)};

    float* h1p[3] = {H1, H1 + (size_t)N_ART * HIDD, H1 + (size_t)(N_ART + N_ENT) * HIDD};
    float* h2p[3] = {out + 100000,
                     out + 100000 + (size_t)N_ART * HIDD,
                     out + 100000 + (size_t)(N_ART + N_ENT) * HIDD};

    // --- splits: features + weights ---
    for (int t = 0; t < 3; t++) {
        long long n = (long long)nn[t] * K1S;
        split2_A<false><<<(unsigned)((n + 255) / 256), 256>>>(
            x[t], Xs + XB[t], Xs + XB[t] + (size_t)nn[t] * K1S, nn[t], FEATD, K1S);
    }
    {
        long long n = 640LL * K1S;
        split2_W<<<(unsigned)((n + 255) / 256), 256>>>(c1llw, W1L, 640, FEATD, K1S);
        split2_W<<<(unsigned)((n + 255) / 256), 256>>>(c1lrw, W1R, 640, FEATD, K1S);
        long long n2 = 640LL * K2S;
        split2_W<<<(unsigned)((n2 + 255) / 256), 256>>>(c2llw, W2L, 640, HIDD, K2S);
        split2_W<<<(unsigned)((n2 + 255) / 256), 256>>>(c2lrw, W2R, 640, HIDD, K2S);
    }

    // --- in-degree counts per edge type (reused by both layers) ---
    cudaMemsetAsync(CNT, 0, 500000 * sizeof(float));
    for (int i = 0; i < 5; i++)
        count_k<<<(NEDGE + 255) / 256, 256>>>(ei[i] + NEDGE, CNT + i * 100000, NEDGE);

    // --- layer 1: FEAT(769) -> HID ---
    cudaMemsetAsync(H1, 0, (size_t)25600000 * sizeof(float));
    for (int i = 0; i < 5; i++) {
        int s = SRC[i], d = DST[i];
        gemm_mma<<<(nn[d] + 127) / 128, 256, SMEM_TOT>>>(
            Xs + XB[d], Xs + XB[d] + (size_t)nn[d] * K1S,
            W1L + (size_t)i * 128 * (2 * K1S), c1llb + i * HIDD, B, nn[d], K1S);
        gemm_mma<<<(nn[s] + 127) / 128, 256, SMEM_TOT>>>(
            Xs + XB[s], Xs + XB[s] + (size_t)nn[s] * K1S,
            W1R + (size_t)i * 128 * (2 * K1S), nullptr, P, nn[s], K1S);
        cudaMemsetAsync(Acc, 0, (size_t)nn[d] * HIDD * sizeof(float));
        scatter_k<<<(NEDGE * 32 + 255) / 256, 256>>>(P, ei[i], ei[i] + NEDGE, Acc, NEDGE);
        combine_norm_add<<<(nn[d] + 7) / 8, 256>>>(B, Acc, CNT + i * 100000, h1p[d], nn[d]);
    }

    // --- relu + split h1 into hi/lo planes ---
    {
        long long n = 200000LL * K2S;
        split2_A<true><<<(unsigned)((n + 255) / 256), 256>>>(
            H1, H1s, H1s + H1SLO, 200000, HIDD, K2S);
    }

    // --- layer 2: HID -> HID ---
    cudaMemsetAsync(out + 100000, 0, (size_t)25600000 * sizeof(float));
    for (int i = 0; i < 5; i++) {
        int s = SRC[i], d = DST[i];
        gemm_mma<<<(nn[d] + 127) / 128, 256, SMEM_TOT>>>(
            H1s + R0[d] * K2S, H1s + H1SLO + R0[d] * K2S,
            W2L + (size_t)i * 128 * (2 * K2S), c2llb + i * HIDD, B, nn[d], K2S);
        gemm_mma<<<(nn[s] + 127) / 128, 256, SMEM_TOT>>>(
            H1s + R0[s] * K2S, H1s + H1SLO + R0[s] * K2S,
            W2R + (size_t)i * 128 * (2 * K2S), nullptr, P, nn[s], K2S);
        cudaMemsetAsync(Acc, 0, (size_t)nn[d] * HIDD * sizeof(float));
        scatter_k<<<(NEDGE * 32 + 255) / 256, 256>>>(P, ei[i], ei[i] + NEDGE, Acc, NEDGE);
        combine_norm_add<<<(nn[d] + 7) / 8, 256>>>(B, Acc, CNT + i * 100000, h2p[d], nn[d]);
    }

    // --- final relu on all h2 outputs (in-place in d_out) ---
    relu_k<<<(25600000 + 255) / 256, 256>>>(out + 100000, (size_t)25600000);

    // --- head MLP on h_art ---
    gemm_tn<true><<<dim3(1, (N_ART + 127) / 128), 256>>>(
        out + 100000, hw1, hb1, Z, N_ART, 64, HIDD);
    head2_k<<<(N_ART + 255) / 256, 256>>>(Z, hw2, hb2, out, N_ART);
}

// round 7
// speedup vs baseline: 2.7990x; 1.2010x over previous
#include <cuda_runtime.h>
#include <cuda_bf16.h>
#include <math.h>
#include <stdint.h>

#define N_ART 50000
#define N_ENT 100000
#define N_FACT 50000
#define NEDGE 200000
#define FEATD 769
#define HIDD 128

#define K1S 800    // layer-1 K padded
#define K2S 128    // layer-2 K

// ---------------------------------------------------------------------------
// Scratch (static device arrays; no allocation allowed)
// ---------------------------------------------------------------------------
__device__ float g_B5[44800000];                // 5 lin_l outputs (by dst rows)
__device__ float g_P5[44800000];                // 5 lin_r outputs (by src rows)
__device__ float g_h1[25600000];                // layer-1 hidden: art|ent|fact
__device__ float g_z[3200000];                  // head hidden 50000 x 64
__device__ __nv_bfloat16 g_Xs[320000000];       // feature planes per type [hi|lo]
__device__ __nv_bfloat16 g_H1s[51200000];       // relu(h1) planes [hi|lo]
__device__ __nv_bfloat16 g_W1L[1024000];        // c1 lin_l rows [hi(800)|lo(800)]
__device__ __nv_bfloat16 g_W1R[1024000];
__device__ __nv_bfloat16 g_W2L[163840];         // c2 rows [hi(128)|lo(128)]
__device__ __nv_bfloat16 g_W2R[163840];
__device__ int g_cursor[500000];                // per-type counts / fill cursors
__device__ int g_off[500160];                   // per-type CSR offsets (stride 100032)
__device__ int g_srcA[1000000];                 // per-type CSR src lists (stride 200000)

// ---------------------------------------------------------------------------
__device__ __forceinline__ uint32_t smem_u32(const void* p) {
    uint32_t a;
    asm("{ .reg .u64 t; cvta.to.shared.u64 t, %1; cvt.u32.u64 %0, t; }"
        : "=r"(a) : "l"(p));
    return a;
}

#define CP_ASYNC16(dst, src) \
    asm volatile("cp.async.cg.shared.global [%0], [%1], 16;" :: "r"(dst), "l"(src))
#define CP_COMMIT() asm volatile("cp.async.commit_group;" ::: "memory")
#define CP_WAIT1()  asm volatile("cp.async.wait_group 1;" ::: "memory")

// SMEM: 4 planes x 2 buffers x 10240B (128 rows x 80B, 40 bf16/row)
#define SSTRB 80
#define OFF_AHI 0
#define OFF_ALO 20480
#define OFF_WHI 40960
#define OFF_WLO 61440
#define SMEM_TOT 81920

// ---------------------------------------------------------------------------
// Tensor-core GEMM (proven R6 core): C[M,128] = A[M,S] @ W[128,S]^T (+bias)
// 3 passes: a_hi*w_hi + a_lo*w_hi + a_hi*w_lo
// ---------------------------------------------------------------------------
__global__ __launch_bounds__(256) void gemm_mma(
    const __nv_bfloat16* __restrict__ Ahi, const __nv_bfloat16* __restrict__ Alo,
    const __nv_bfloat16* __restrict__ W,
    const float* __restrict__ bias, float* __restrict__ C, int M, int S)
{
    extern __shared__ char sm[];
    const uint32_t sb = smem_u32(sm);
    const int tid = threadIdx.x, lane = tid & 31, warp = tid >> 5;
    const int mQ = warp >> 1, nH = warp & 1;
    const int rowBase = blockIdx.x * 128;
    const int NC = S >> 5;
    const int W2S = 2 * S;

    float acc[2][8][4];
#pragma unroll
    for (int i = 0; i < 2; i++)
#pragma unroll
        for (int j = 0; j < 8; j++)
#pragma unroll
            for (int q = 0; q < 4; q++) acc[i][j][q] = 0.f;

    const int lr4 = tid >> 2, lq4 = tid & 3;

#define LOAD_CHUNK(c, buf) do { \
    int k0 = (c) * 32; \
    _Pragma("unroll") \
    for (int i = 0; i < 2; i++) { \
        int r = lr4 + i * 64; \
        int ga = rowBase + r; if (ga >= M) ga = M - 1; \
        uint32_t so = (buf) * 10240 + r * SSTRB + lq4 * 16; \
        CP_ASYNC16(sb + OFF_AHI + so, Ahi + (size_t)ga * S + k0 + lq4 * 8); \
        CP_ASYNC16(sb + OFF_ALO + so, Alo + (size_t)ga * S + k0 + lq4 * 8); \
        CP_ASYNC16(sb + OFF_WHI + so, W + (size_t)r * W2S + k0 + lq4 * 8); \
        CP_ASYNC16(sb + OFF_WLO + so, W + (size_t)r * W2S + S + k0 + lq4 * 8); \
    } } while (0)

    LOAD_CHUNK(0, 0); CP_COMMIT();
    if (NC > 1) { LOAD_CHUNK(1, 1); }
    CP_COMMIT();

    const int a_row = lane & 15;
    const int a_sel = (lane >> 4) & 1;
    const int b_row = (lane & 7) + ((lane & 16) >> 1);
    const int b_sel = (lane >> 3) & 1;

    auto do_pass = [&](uint32_t abase, uint32_t wbase) {
#pragma unroll
        for (int kh = 0; kh < 2; kh++) {
            uint32_t ar[2][4], br[8][2];
#pragma unroll
            for (int mi = 0; mi < 2; mi++) {
                uint32_t addr = abase + (mQ * 32 + mi * 16 + a_row) * SSTRB
                                + kh * 32 + a_sel * 16;
                asm volatile(
                    "ldmatrix.sync.aligned.m8n8.x4.shared.b16 {%0,%1,%2,%3}, [%4];"
                    : "=r"(ar[mi][0]), "=r"(ar[mi][1]), "=r"(ar[mi][2]), "=r"(ar[mi][3])
                    : "r"(addr));
            }
#pragma unroll
            for (int pi = 0; pi < 4; pi++) {
                uint32_t addr = wbase + (nH * 64 + pi * 16 + b_row) * SSTRB
                                + kh * 32 + b_sel * 16;
                asm volatile(
                    "ldmatrix.sync.aligned.m8n8.x4.shared.b16 {%0,%1,%2,%3}, [%4];"
                    : "=r"(br[2 * pi][0]), "=r"(br[2 * pi][1]),
                      "=r"(br[2 * pi + 1][0]), "=r"(br[2 * pi + 1][1])
                    : "r"(addr));
            }
#pragma unroll
            for (int mi = 0; mi < 2; mi++)
#pragma unroll
                for (int ni = 0; ni < 8; ni++) {
                    asm volatile(
                        "mma.sync.aligned.m16n8k16.row.col.f32.bf16.bf16.f32 "
                        "{%0,%1,%2,%3}, {%4,%5,%6,%7}, {%8,%9}, {%0,%1,%2,%3};"
                        : "+f"(acc[mi][ni][0]), "+f"(acc[mi][ni][1]),
                          "+f"(acc[mi][ni][2]), "+f"(acc[mi][ni][3])
                        : "r"(ar[mi][0]), "r"(ar[mi][1]), "r"(ar[mi][2]), "r"(ar[mi][3]),
                          "r"(br[ni][0]), "r"(br[ni][1]));
                }
        }
    };

    for (int c = 0; c < NC; c++) {
        CP_WAIT1();
        __syncthreads();
        uint32_t bo = (uint32_t)(c & 1) * 10240;
        do_pass(sb + OFF_AHI + bo, sb + OFF_WHI + bo);
        do_pass(sb + OFF_ALO + bo, sb + OFF_WHI + bo);
        do_pass(sb + OFF_AHI + bo, sb + OFF_WLO + bo);
        __syncthreads();
        if (c + 2 < NC) LOAD_CHUNK(c + 2, c & 1);
        CP_COMMIT();
    }
#undef LOAD_CHUNK

    const int g = lane >> 2, t = lane & 3;
#pragma unroll
    for (int mi = 0; mi < 2; mi++) {
        int r0 = rowBase + mQ * 32 + mi * 16 + g;
#pragma unroll
        for (int ni = 0; ni < 8; ni++) {
            int col = nH * 64 + ni * 8 + t * 2;
            float bx = 0.f, by = 0.f;
            if (bias) { bx = bias[col]; by = bias[col + 1]; }
            if (r0 < M) {
                float2 v = make_float2(acc[mi][ni][0] + bx, acc[mi][ni][1] + by);
                *(float2*)(C + (size_t)r0 * 128 + col) = v;
            }
            if (r0 + 8 < M) {
                float2 v = make_float2(acc[mi][ni][2] + bx, acc[mi][ni][3] + by);
                *(float2*)(C + (size_t)(r0 + 8) * 128 + col) = v;
            }
        }
    }
}

// ---------------------------------------------------------------------------
// Splits: one block per row, threads stride columns (no 64-bit division)
// ---------------------------------------------------------------------------
template<bool RELU>
__global__ void split2_A(const float* __restrict__ in,
                         __nv_bfloat16* __restrict__ outHi,
                         __nv_bfloat16* __restrict__ outLo,
                         int K, int S)
{
    int row = blockIdx.x;
    const float* src = in + (size_t)row * K;
    __nv_bfloat16* dh = outHi + (size_t)row * S;
    __nv_bfloat16* dl = outLo + (size_t)row * S;
    for (int k = threadIdx.x; k < S; k += blockDim.x) {
        __nv_bfloat16 hi = __float2bfloat16(0.f), lo = hi;
        if (k < K) {
            float v = src[k];
            if (RELU) v = fmaxf(v, 0.f);
            hi = __float2bfloat16(v);
            lo = __float2bfloat16(v - __bfloat162float(hi));
        }
        dh[k] = hi;
        dl[k] = lo;
    }
}

__global__ void split2_W(const float* __restrict__ in, __nv_bfloat16* __restrict__ out,
                         int K, int S)
{
    int row = blockIdx.x;
    const float* src = in + (size_t)row * K;
    __nv_bfloat16* d = out + (size_t)row * (2 * S);
    for (int k = threadIdx.x; k < S; k += blockDim.x) {
        __nv_bfloat16 hi = __float2bfloat16(0.f), lo = hi;
        if (k < K) {
            float v = src[k];
            hi = __float2bfloat16(v);
            lo = __float2bfloat16(v - __bfloat162float(hi));
        }
        d[k] = hi;
        d[S + k] = lo;
    }
}

// ---------------------------------------------------------------------------
// CSR build: count -> scan -> fill
// ---------------------------------------------------------------------------
__global__ void count_int_k(const int* __restrict__ di, int* __restrict__ cnt, int E)
{
    int e = blockIdx.x * blockDim.x + threadIdx.x;
    if (e < E) atomicAdd(&cnt[di[e]], 1);
}

// single-block chunked exclusive scan, n <= ~1e6
__global__ void scan_k(const int* __restrict__ cnt, int* __restrict__ off, int n)
{
    __shared__ int sh[32];
    __shared__ int carry;
    int tid = threadIdx.x, lane = tid & 31, w = tid >> 5;
    if (tid == 0) carry = 0;
    __syncthreads();
    for (int base = 0; base < n; base += 1024) {
        int i = base + tid;
        int v = (i < n) ? cnt[i] : 0;
        int x = v;
#pragma unroll
        for (int d = 1; d < 32; d <<= 1) {
            int y = __shfl_up_sync(0xffffffffu, x, d);
            if (lane >= d) x += y;
        }
        if (lane == 31) sh[w] = x;
        __syncthreads();
        if (w == 0) {
            int s = sh[lane];
#pragma unroll
            for (int d = 1; d < 32; d <<= 1) {
                int y = __shfl_up_sync(0xffffffffu, s, d);
                if (lane >= d) s += y;
            }
            sh[lane] = s;
        }
        __syncthreads();
        int excl = x - v + (w > 0 ? sh[w - 1] : 0) + carry;
        if (i < n) off[i] = excl;
        __syncthreads();
        if (tid == 1023) carry = excl + v;
        __syncthreads();
    }
    if (tid == 0) off[n] = carry;
}

__global__ void fill_k(const int* __restrict__ si, const int* __restrict__ di,
                       const int* __restrict__ off, int* __restrict__ cursor,
                       int* __restrict__ srcA, int E)
{
    int e = blockIdx.x * blockDim.x + threadIdx.x;
    if (e >= E) return;
    int d = di[e];
    int pos = atomicAdd(&cursor[d], 1);
    srcA[off[d] + pos] = si[e];
}

// ---------------------------------------------------------------------------
// Fused gather + mean + lin_l add + L2-normalize + sum over <=2 edge types
// one warp per dst row; writes output once (no memsets/atomics)
// ---------------------------------------------------------------------------
template<bool RELU, bool TWO>
__global__ void combine2(
    const float* __restrict__ B0, const float* __restrict__ P0,
    const int* __restrict__ off0, const int* __restrict__ src0,
    const float* __restrict__ B1, const float* __restrict__ P1,
    const int* __restrict__ off1, const int* __restrict__ src1,
    float* __restrict__ out, int n)
{
    int w = (blockIdx.x * blockDim.x + threadIdx.x) >> 5;
    int lane = threadIdx.x & 31;
    if (w >= n) return;
    size_t o = (size_t)w * HIDD + lane * 4;
    float4 r = make_float4(0.f, 0.f, 0.f, 0.f);

    {
        float4 b = *(const float4*)(B0 + o);
        int beg = __ldg(off0 + w), end = __ldg(off0 + w + 1);
        float4 a = make_float4(0.f, 0.f, 0.f, 0.f);
        for (int e = beg; e < end; e++) {
            int s = __ldg(src0 + e);
            float4 p = *(const float4*)(P0 + (size_t)s * HIDD + lane * 4);
            a.x += p.x; a.y += p.y; a.z += p.z; a.w += p.w;
        }
        float inv = 1.0f / fmaxf((float)(end - beg), 1.0f);
        float4 t;
        t.x = b.x + a.x * inv; t.y = b.y + a.y * inv;
        t.z = b.z + a.z * inv; t.w = b.w + a.w * inv;
        float ss = t.x * t.x + t.y * t.y + t.z * t.z + t.w * t.w;
#pragma unroll
        for (int sh = 16; sh; sh >>= 1) ss += __shfl_xor_sync(0xffffffffu, ss, sh);
        float sc = 1.0f / fmaxf(sqrtf(ss), 1e-12f);
        r.x += t.x * sc; r.y += t.y * sc; r.z += t.z * sc; r.w += t.w * sc;
    }
    if (TWO) {
        float4 b = *(const float4*)(B1 + o);
        int beg = __ldg(off1 + w), end = __ldg(off1 + w + 1);
        float4 a = make_float4(0.f, 0.f, 0.f, 0.f);
        for (int e = beg; e < end; e++) {
            int s = __ldg(src1 + e);
            float4 p = *(const float4*)(P1 + (size_t)s * HIDD + lane * 4);
            a.x += p.x; a.y += p.y; a.z += p.z; a.w += p.w;
        }
        float inv = 1.0f / fmaxf((float)(end - beg), 1.0f);
        float4 t;
        t.x = b.x + a.x * inv; t.y = b.y + a.y * inv;
        t.z = b.z + a.z * inv; t.w = b.w + a.w * inv;
        float ss = t.x * t.x + t.y * t.y + t.z * t.z + t.w * t.w;
#pragma unroll
        for (int sh = 16; sh; sh >>= 1) ss += __shfl_xor_sync(0xffffffffu, ss, sh);
        float sc = 1.0f / fmaxf(sqrtf(ss), 1e-12f);
        r.x += t.x * sc; r.y += t.y * sc; r.z += t.z * sc; r.w += t.w * sc;
    }
    if (RELU) {
        r.x = fmaxf(r.x, 0.f); r.y = fmaxf(r.y, 0.f);
        r.z = fmaxf(r.z, 0.f); r.w = fmaxf(r.w, 0.f);
    }
    *(float4*)(out + o) = r;
}

// ---------------------------------------------------------------------------
// SIMT GEMM for the 64-wide head
// ---------------------------------------------------------------------------
template<bool RELU_OUT>
__global__ __launch_bounds__(256) void gemm_tn(
    const float* __restrict__ A, const float* __restrict__ W,
    const float* __restrict__ bias, float* __restrict__ C,
    int M, int N, int K)
{
    __shared__ float As[8][128];
    __shared__ float Ws[8][128];
    const int tid = threadIdx.x;
    const int tx = tid & 15, ty = tid >> 4;
    const int rowBase = blockIdx.y * 128;

    float acc[8][8];
#pragma unroll
    for (int i = 0; i < 8; i++)
#pragma unroll
        for (int j = 0; j < 8; j++) acc[i][j] = 0.f;

    for (int k0 = 0; k0 < K; k0 += 8) {
#pragma unroll
        for (int t = 0; t < 4; t++) {
            int idx = tid + t * 256;
            int k = idx & 7, r = idx >> 3;
            int row = rowBase + r, kk = k0 + k;
            float v = 0.f;
            if (row < M && kk < K) v = A[(size_t)row * K + kk];
            As[k][r] = v;
        }
#pragma unroll
        for (int t = 0; t < 4; t++) {
            int idx = tid + t * 256;
            int k = idx & 7, c = idx >> 3;
            int kk = k0 + k;
            float v = 0.f;
            if (c < N && kk < K) v = W[(size_t)c * K + kk];
            Ws[k][c] = v;
        }
        __syncthreads();
#pragma unroll
        for (int k = 0; k < 8; k++) {
            float4 a0 = *(const float4*)&As[k][ty * 8];
            float4 a1 = *(const float4*)&As[k][ty * 8 + 4];
            float4 b0 = *(const float4*)&Ws[k][tx * 8];
            float4 b1 = *(const float4*)&Ws[k][tx * 8 + 4];
            float av[8] = {a0.x, a0.y, a0.z, a0.w, a1.x, a1.y, a1.z, a1.w};
            float bv[8] = {b0.x, b0.y, b0.z, b0.w, b1.x, b1.y, b1.z, b1.w};
#pragma unroll
            for (int i = 0; i < 8; i++)
#pragma unroll
                for (int j = 0; j < 8; j++) acc[i][j] += av[i] * bv[j];
        }
        __syncthreads();
    }

#pragma unroll
    for (int i = 0; i < 8; i++) {
        int row = rowBase + ty * 8 + i;
        if (row < M) {
#pragma unroll
            for (int j = 0; j < 8; j++) {
                int col = tx * 8 + j;
                if (col < N) {
                    float v = acc[i][j] + bias[col];
                    if (RELU_OUT) v = fmaxf(v, 0.f);
                    C[(size_t)row * N + col] = v;
                }
            }
        }
    }
}

__global__ void head2_k(const float* __restrict__ Z, const float* __restrict__ W2,
                        const float* __restrict__ b2, float* __restrict__ out, int n)
{
    int row = blockIdx.x * blockDim.x + threadIdx.x;
    if (row >= n) return;
    float acc0 = b2[0], acc1 = b2[1];
    const float* z = Z + (size_t)row * 64;
#pragma unroll
    for (int k = 0; k < 64; k++) {
        float zv = z[k];
        acc0 += zv * __ldg(W2 + k);
        acc1 += zv * __ldg(W2 + 64 + k);
    }
    out[row * 2 + 0] = acc0;
    out[row * 2 + 1] = acc1;
}

// ---------------------------------------------------------------------------
extern "C" void kernel_launch(void* const* d_in, const int* in_sizes, int n_in,
                              void* d_out_, int out_size)
{
    const float* x[3] = {(const float*)d_in[0], (const float*)d_in[1], (const float*)d_in[2]};
    const int nn[3] = {N_ART, N_ENT, N_FACT};
    const int* ei[5];
    for (int i = 0; i < 5; i++) ei[i] = (const int*)d_in[3 + i];
    const float* c1llw = (const float*)d_in[8];
    const float* c1llb = (const float*)d_in[9];
    const float* c1lrw = (const float*)d_in[10];
    const float* c2llw = (const float*)d_in[11];
    const float* c2llb = (const float*)d_in[12];
    const float* c2lrw = (const float*)d_in[13];
    const float* hw1 = (const float*)d_in[14];
    const float* hb1 = (const float*)d_in[15];
    const float* hw2 = (const float*)d_in[16];
    const float* hb2 = (const float*)d_in[17];
    float* out = (float*)d_out_;

    static const int SRC[5] = {0, 0, 1, 1, 2};
    static const int DST[5] = {1, 2, 0, 2, 1};
    // per-edge-type GEMM output row offsets
    static const size_t BOFF[5] = {0, 100000, 150000, 200000, 250000};
    static const size_t POFF[5] = {0, 50000, 100000, 200000, 300000};

    float *B5, *P5, *H1, *Z;
    __nv_bfloat16 *Xs, *H1s, *W1L, *W1R, *W2L, *W2R;
    int *CUR, *OFFS, *SRCA;
    cudaGetSymbolAddress((void**)&B5, g_B5);
    cudaGetSymbolAddress((void**)&P5, g_P5);
    cudaGetSymbolAddress((void**)&H1, g_h1);
    cudaGetSymbolAddress((void**)&Z, g_z);
    cudaGetSymbolAddress((void**)&Xs, g_Xs);
    cudaGetSymbolAddress((void**)&H1s, g_H1s);
    cudaGetSymbolAddress((void**)&W1L, g_W1L);
    cudaGetSymbolAddress((void**)&W1R, g_W1R);
    cudaGetSymbolAddress((void**)&W2L, g_W2L);
    cudaGetSymbolAddress((void**)&W2R, g_W2R);
    cudaGetSymbolAddress((void**)&CUR, g_cursor);
    cudaGetSymbolAddress((void**)&OFFS, g_off);
    cudaGetSymbolAddress((void**)&SRCA, g_srcA);

    cudaFuncSetAttribute(gemm_mma, cudaFuncAttributeMaxDynamicSharedMemorySize, SMEM_TOT);

    const size_t XB[3] = {0,
                          (size_t)N_ART * 2 * K1S,
                          (size_t)(N_ART + N_ENT) * 2 * K1S};
    const size_t H1SLO = (size_t)200000 * K2S;
    const size_t R0[3] = {0, (size_t)N_ART, (size_t)(N_ART + N_ENT)};

    float* h1p[3] = {H1, H1 + (size_t)N_ART * HIDD, H1 + (size_t)(N_ART + N_ENT) * HIDD};
    float* h2p[3] = {out + 100000,
                     out + 100000 + (size_t)N_ART * HIDD,
                     out + 100000 + (size_t)(N_ART + N_ENT) * HIDD};

    // --- splits: features + weights ---
    for (int t = 0; t < 3; t++)
        split2_A<false><<<nn[t], 256>>>(
            x[t], Xs + XB[t], Xs + XB[t] + (size_t)nn[t] * K1S, FEATD, K1S);
    split2_W<<<640, 256>>>(c1llw, W1L, FEATD, K1S);
    split2_W<<<640, 256>>>(c1lrw, W1R, FEATD, K1S);
    split2_W<<<640, 128>>>(c2llw, W2L, HIDD, K2S);
    split2_W<<<640, 128>>>(c2lrw, W2R, HIDD, K2S);

    // --- CSR build (once; reused by both layers) ---
    cudaMemsetAsync(CUR, 0, 500000 * sizeof(int));
    for (int i = 0; i < 5; i++)
        count_int_k<<<(NEDGE + 255) / 256, 256>>>(ei[i] + NEDGE, CUR + i * 100000, NEDGE);
    for (int i = 0; i < 5; i++)
        scan_k<<<1, 1024>>>(CUR + i * 100000, OFFS + i * 100032, nn[DST[i]]);
    cudaMemsetAsync(CUR, 0, 500000 * sizeof(int));
    for (int i = 0; i < 5; i++)
        fill_k<<<(NEDGE + 255) / 256, 256>>>(ei[i], ei[i] + NEDGE,
                                             OFFS + i * 100032, CUR + i * 100000,
                                             SRCA + i * 200000, NEDGE);

    // --- layer 1 GEMMs ---
    for (int i = 0; i < 5; i++) {
        int s = SRC[i], d = DST[i];
        gemm_mma<<<(nn[d] + 127) / 128, 256, SMEM_TOT>>>(
            Xs + XB[d], Xs + XB[d] + (size_t)nn[d] * K1S,
            W1L + (size_t)i * 128 * (2 * K1S), c1llb + i * HIDD,
            B5 + BOFF[i] * HIDD, nn[d], K1S);
        gemm_mma<<<(nn[s] + 127) / 128, 256, SMEM_TOT>>>(
            Xs + XB[s], Xs + XB[s] + (size_t)nn[s] * K1S,
            W1R + (size_t)i * 128 * (2 * K1S), nullptr,
            P5 + POFF[i] * HIDD, nn[s], K1S);
    }
    // --- layer 1 fused combines: art<-e2, ent<-e0+e4, fact<-e1+e3 ---
    combine2<false, false><<<(N_ART + 7) / 8, 256>>>(
        B5 + BOFF[2] * HIDD, P5 + POFF[2] * HIDD, OFFS + 2 * 100032, SRCA + 2 * 200000,
        nullptr, nullptr, nullptr, nullptr, h1p[0], N_ART);
    combine2<false, true><<<(N_ENT + 7) / 8, 256>>>(
        B5 + BOFF[0] * HIDD, P5 + POFF[0] * HIDD, OFFS + 0 * 100032, SRCA + 0 * 200000,
        B5 + BOFF[4] * HIDD, P5 + POFF[4] * HIDD, OFFS + 4 * 100032, SRCA + 4 * 200000,
        h1p[1], N_ENT);
    combine2<false, true><<<(N_FACT + 7) / 8, 256>>>(
        B5 + BOFF[1] * HIDD, P5 + POFF[1] * HIDD, OFFS + 1 * 100032, SRCA + 1 * 200000,
        B5 + BOFF[3] * HIDD, P5 + POFF[3] * HIDD, OFFS + 3 * 100032, SRCA + 3 * 200000,
        h1p[2], N_FACT);

    // --- relu + split h1 into hi/lo planes ---
    split2_A<true><<<200000, 128>>>(H1, H1s, H1s + H1SLO, HIDD, K2S);

    // --- layer 2 GEMMs ---
    for (int i = 0; i < 5; i++) {
        int s = SRC[i], d = DST[i];
        gemm_mma<<<(nn[d] + 127) / 128, 256, SMEM_TOT>>>(
            H1s + R0[d] * K2S, H1s + H1SLO + R0[d] * K2S,
            W2L + (size_t)i * 128 * (2 * K2S), c2llb + i * HIDD,
            B5 + BOFF[i] * HIDD, nn[d], K2S);
        gemm_mma<<<(nn[s] + 127) / 128, 256, SMEM_TOT>>>(
            H1s + R0[s] * K2S, H1s + H1SLO + R0[s] * K2S,
            W2R + (size_t)i * 128 * (2 * K2S), nullptr,
            P5 + POFF[i] * HIDD, nn[s], K2S);
    }
    // --- layer 2 fused combines with final relu ---
    combine2<true, false><<<(N_ART + 7) / 8, 256>>>(
        B5 + BOFF[2] * HIDD, P5 + POFF[2] * HIDD, OFFS + 2 * 100032, SRCA + 2 * 200000,
        nullptr, nullptr, nullptr, nullptr, h2p[0], N_ART);
    combine2<true, true><<<(N_ENT + 7) / 8, 256>>>(
        B5 + BOFF[0] * HIDD, P5 + POFF[0] * HIDD, OFFS + 0 * 100032, SRCA + 0 * 200000,
        B5 + BOFF[4] * HIDD, P5 + POFF[4] * HIDD, OFFS + 4 * 100032, SRCA + 4 * 200000,
        h2p[1], N_ENT);
    combine2<true, true><<<(N_FACT + 7) / 8, 256>>>(
        B5 + BOFF[1] * HIDD, P5 + POFF[1] * HIDD, OFFS + 1 * 100032, SRCA + 1 * 200000,
        B5 + BOFF[3] * HIDD, P5 + POFF[3] * HIDD, OFFS + 3 * 100032, SRCA + 3 * 200000,
        h2p[2], N_FACT);

    // --- head MLP on h_art (already relu'd) ---
    gemm_tn<true><<<dim3(1, (N_ART + 127) / 128), 256>>>(
        out + 100000, hw1, hb1, Z, N_ART, 64, HIDD);
    head2_k<<<(N_ART + 255) / 256, 256>>>(Z, hw2, hb2, out, N_ART);
}

// round 8
// speedup vs baseline: 3.3919x; 1.2118x over previous
#include <cuda_runtime.h>
#include <cuda_bf16.h>
#include <math.h>
#include <stdint.h>

#define N_ART 50000
#define N_ENT 100000
#define N_FACT 50000
#define NEDGE 200000
#define FEATD 769
#define HIDD 128

#define K1S 800
#define K2S 128

// ---------------------------------------------------------------------------
// Scratch
// ---------------------------------------------------------------------------
__device__ float g_B5[44800000];                // 5 lin_l outputs (dst rows)
__device__ float g_P5[44800000];                // 5 lin_r outputs (src rows)
__device__ float g_h1[25600000];
__device__ float g_z[3200000];
__device__ __nv_bfloat16 g_Xs[320000000];       // feature planes per type [hi|lo]
__device__ __nv_bfloat16 g_H1s[51200000];       // relu(h1) planes [hi|lo]
__device__ __nv_bfloat16 g_W1L[1024000];
__device__ __nv_bfloat16 g_W1R[1024000];
__device__ __nv_bfloat16 g_W2L[163840];
__device__ __nv_bfloat16 g_W2R[163840];
__device__ int g_cursor[500000];
__device__ int g_off[500160];                   // per-type CSR offsets (stride 100032)
__device__ int g_srcA[1000000];                 // per-type CSR src lists (stride 200000)

// ---------------------------------------------------------------------------
__device__ __forceinline__ uint32_t smem_u32(const void* p) {
    uint32_t a;
    asm("{ .reg .u64 t; cvta.to.shared.u64 t, %1; cvt.u32.u64 %0, t; }"
        : "=r"(a) : "l"(p));
    return a;
}

#define CP_ASYNC16(dst, src) \
    asm volatile("cp.async.cg.shared.global [%0], [%1], 16;" :: "r"(dst), "l"(src))
#define CP_COMMIT() asm volatile("cp.async.commit_group;" ::: "memory")
#define CP_WAIT1()  asm volatile("cp.async.wait_group 1;" ::: "memory")

#define SSTRB 80
#define OFF_AHI 0
#define OFF_ALO 20480
#define OFF_WHI 40960
#define OFF_WLO 61440
#define SMEM_TOT 81920

struct MultiOut {
    const __nv_bfloat16* W[4];
    const float* bias[4];
    float* C[4];
};

// ---------------------------------------------------------------------------
// Fused multi-output tensor-core GEMM: for y-block b:
//   C_b[M,128] = A[M,S] @ W_b[128,S]^T (+bias_b), 3-pass hi/lo split math.
// grid = (ceil(M/128), nblocks). All y-blocks share A reads via L2.
// ---------------------------------------------------------------------------
__global__ __launch_bounds__(256) void gemm_mma_multi(
    const __nv_bfloat16* __restrict__ Ahi, const __nv_bfloat16* __restrict__ Alo,
    MultiOut p, int M, int S)
{
    extern __shared__ char sm[];
    const uint32_t sb = smem_u32(sm);
    const int tid = threadIdx.x, lane = tid & 31, warp = tid >> 5;
    const int mQ = warp >> 1, nH = warp & 1;
    const int rowBase = blockIdx.x * 128;
    const int by = blockIdx.y;
    const __nv_bfloat16* __restrict__ W = p.W[by];
    const float* __restrict__ bias = p.bias[by];
    float* __restrict__ C = p.C[by];
    const int NC = S >> 5;
    const int W2S = 2 * S;

    float acc[2][8][4];
#pragma unroll
    for (int i = 0; i < 2; i++)
#pragma unroll
        for (int j = 0; j < 8; j++)
#pragma unroll
            for (int q = 0; q < 4; q++) acc[i][j][q] = 0.f;

    const int lr4 = tid >> 2, lq4 = tid & 3;

#define LOAD_CHUNK(c, buf) do { \
    int k0 = (c) * 32; \
    _Pragma("unroll") \
    for (int i = 0; i < 2; i++) { \
        int r = lr4 + i * 64; \
        int ga = rowBase + r; if (ga >= M) ga = M - 1; \
        uint32_t so = (buf) * 10240 + r * SSTRB + lq4 * 16; \
        CP_ASYNC16(sb + OFF_AHI + so, Ahi + (size_t)ga * S + k0 + lq4 * 8); \
        CP_ASYNC16(sb + OFF_ALO + so, Alo + (size_t)ga * S + k0 + lq4 * 8); \
        CP_ASYNC16(sb + OFF_WHI + so, W + (size_t)r * W2S + k0 + lq4 * 8); \
        CP_ASYNC16(sb + OFF_WLO + so, W + (size_t)r * W2S + S + k0 + lq4 * 8); \
    } } while (0)

    LOAD_CHUNK(0, 0); CP_COMMIT();
    if (NC > 1) { LOAD_CHUNK(1, 1); }
    CP_COMMIT();

    const int a_row = lane & 15;
    const int a_sel = (lane >> 4) & 1;
    const int b_row = (lane & 7) + ((lane & 16) >> 1);
    const int b_sel = (lane >> 3) & 1;

    auto do_pass = [&](uint32_t abase, uint32_t wbase) {
#pragma unroll
        for (int kh = 0; kh < 2; kh++) {
            uint32_t ar[2][4], br[8][2];
#pragma unroll
            for (int mi = 0; mi < 2; mi++) {
                uint32_t addr = abase + (mQ * 32 + mi * 16 + a_row) * SSTRB
                                + kh * 32 + a_sel * 16;
                asm volatile(
                    "ldmatrix.sync.aligned.m8n8.x4.shared.b16 {%0,%1,%2,%3}, [%4];"
                    : "=r"(ar[mi][0]), "=r"(ar[mi][1]), "=r"(ar[mi][2]), "=r"(ar[mi][3])
                    : "r"(addr));
            }
#pragma unroll
            for (int pi = 0; pi < 4; pi++) {
                uint32_t addr = wbase + (nH * 64 + pi * 16 + b_row) * SSTRB
                                + kh * 32 + b_sel * 16;
                asm volatile(
                    "ldmatrix.sync.aligned.m8n8.x4.shared.b16 {%0,%1,%2,%3}, [%4];"
                    : "=r"(br[2 * pi][0]), "=r"(br[2 * pi][1]),
                      "=r"(br[2 * pi + 1][0]), "=r"(br[2 * pi + 1][1])
                    : "r"(addr));
            }
#pragma unroll
            for (int mi = 0; mi < 2; mi++)
#pragma unroll
                for (int ni = 0; ni < 8; ni++) {
                    asm volatile(
                        "mma.sync.aligned.m16n8k16.row.col.f32.bf16.bf16.f32 "
                        "{%0,%1,%2,%3}, {%4,%5,%6,%7}, {%8,%9}, {%0,%1,%2,%3};"
                        : "+f"(acc[mi][ni][0]), "+f"(acc[mi][ni][1]),
                          "+f"(acc[mi][ni][2]), "+f"(acc[mi][ni][3])
                        : "r"(ar[mi][0]), "r"(ar[mi][1]), "r"(ar[mi][2]), "r"(ar[mi][3]),
                          "r"(br[ni][0]), "r"(br[ni][1]));
                }
        }
    };

    for (int c = 0; c < NC; c++) {
        CP_WAIT1();
        __syncthreads();
        uint32_t bo = (uint32_t)(c & 1) * 10240;
        do_pass(sb + OFF_AHI + bo, sb + OFF_WHI + bo);
        do_pass(sb + OFF_ALO + bo, sb + OFF_WHI + bo);
        do_pass(sb + OFF_AHI + bo, sb + OFF_WLO + bo);
        __syncthreads();
        if (c + 2 < NC) LOAD_CHUNK(c + 2, c & 1);
        CP_COMMIT();
    }
#undef LOAD_CHUNK

    const int g = lane >> 2, t = lane & 3;
#pragma unroll
    for (int mi = 0; mi < 2; mi++) {
        int r0 = rowBase + mQ * 32 + mi * 16 + g;
#pragma unroll
        for (int ni = 0; ni < 8; ni++) {
            int col = nH * 64 + ni * 8 + t * 2;
            float bx = 0.f, by2 = 0.f;
            if (bias) { bx = bias[col]; by2 = bias[col + 1]; }
            if (r0 < M) {
                float2 v = make_float2(acc[mi][ni][0] + bx, acc[mi][ni][1] + by2);
                *(float2*)(C + (size_t)r0 * 128 + col) = v;
            }
            if (r0 + 8 < M) {
                float2 v = make_float2(acc[mi][ni][2] + bx, acc[mi][ni][3] + by2);
                *(float2*)(C + (size_t)(r0 + 8) * 128 + col) = v;
            }
        }
    }
}

// ---------------------------------------------------------------------------
// Splits
// ---------------------------------------------------------------------------
// block per row, 4 cols/thread (S <= 1024)
__global__ void splitA_feat(const float* __restrict__ in,
                            __nv_bfloat16* __restrict__ outHi,
                            __nv_bfloat16* __restrict__ outLo, int K, int S)
{
    int row = blockIdx.x;
    int k = threadIdx.x * 4;
    if (k >= S) return;
    const float* src = in + (size_t)row * K;
    float v[4];
#pragma unroll
    for (int j = 0; j < 4; j++) {
        int kk = k + j;
        v[j] = (kk < K) ? src[kk] : 0.f;
    }
    __nv_bfloat16 h[4], l[4];
#pragma unroll
    for (int j = 0; j < 4; j++) {
        h[j] = __float2bfloat16(v[j]);
        l[j] = __float2bfloat16(v[j] - __bfloat162float(h[j]));
    }
    *(uint2*)(outHi + (size_t)row * S + k) = *(uint2*)h;
    *(uint2*)(outLo + (size_t)row * S + k) = *(uint2*)l;
}

// warp per row, K=S=128: one float4 per lane; relu fused
__global__ void splitA_h1(const float* __restrict__ in,
                          __nv_bfloat16* __restrict__ outHi,
                          __nv_bfloat16* __restrict__ outLo, int M)
{
    int w = (blockIdx.x * blockDim.x + threadIdx.x) >> 5;
    int lane = threadIdx.x & 31;
    if (w >= M) return;
    size_t o = (size_t)w * 128 + lane * 4;
    float4 v = *(const float4*)(in + o);
    float vv[4] = {fmaxf(v.x, 0.f), fmaxf(v.y, 0.f), fmaxf(v.z, 0.f), fmaxf(v.w, 0.f)};
    __nv_bfloat16 h[4], l[4];
#pragma unroll
    for (int j = 0; j < 4; j++) {
        h[j] = __float2bfloat16(vv[j]);
        l[j] = __float2bfloat16(vv[j] - __bfloat162float(h[j]));
    }
    *(uint2*)(outHi + o) = *(uint2*)h;
    *(uint2*)(outLo + o) = *(uint2*)l;
}

__global__ void split2_W(const float* __restrict__ in, __nv_bfloat16* __restrict__ out,
                         int K, int S)
{
    int row = blockIdx.x;
    const float* src = in + (size_t)row * K;
    __nv_bfloat16* d = out + (size_t)row * (2 * S);
    for (int k = threadIdx.x; k < S; k += blockDim.x) {
        __nv_bfloat16 hi = __float2bfloat16(0.f), lo = hi;
        if (k < K) {
            float v = src[k];
            hi = __float2bfloat16(v);
            lo = __float2bfloat16(v - __bfloat162float(hi));
        }
        d[k] = hi;
        d[S + k] = lo;
    }
}

// ---------------------------------------------------------------------------
// CSR build (merged launches)
// ---------------------------------------------------------------------------
struct EdgePtrs { const int* e[5]; };

__global__ void count5_k(EdgePtrs ep, int* __restrict__ cnt, int E)
{
    int i = blockIdx.y;
    int e = blockIdx.x * blockDim.x + threadIdx.x;
    if (e < E) atomicAdd(&cnt[i * 100000 + ep.e[i][E + e]], 1);
}

__constant__ int c_dstN[5] = {100000, 50000, 50000, 50000, 100000};

__global__ void scan5_k(const int* __restrict__ cnt, int* __restrict__ off)
{
    __shared__ int sh[32];
    __shared__ int carry;
    int type = blockIdx.x;
    const int n = c_dstN[type];
    const int* c = cnt + type * 100000;
    int* o = off + type * 100032;
    int tid = threadIdx.x, lane = tid & 31, w = tid >> 5;
    if (tid == 0) carry = 0;
    __syncthreads();
    for (int base = 0; base < n; base += 1024) {
        int i = base + tid;
        int v = (i < n) ? c[i] : 0;
        int x = v;
#pragma unroll
        for (int d = 1; d < 32; d <<= 1) {
            int y = __shfl_up_sync(0xffffffffu, x, d);
            if (lane >= d) x += y;
        }
        if (lane == 31) sh[w] = x;
        __syncthreads();
        if (w == 0) {
            int s = sh[lane];
#pragma unroll
            for (int d = 1; d < 32; d <<= 1) {
                int y = __shfl_up_sync(0xffffffffu, s, d);
                if (lane >= d) s += y;
            }
            sh[lane] = s;
        }
        __syncthreads();
        int excl = x - v + (w > 0 ? sh[w - 1] : 0) + carry;
        if (i < n) o[i] = excl;
        __syncthreads();
        if (tid == 1023) carry = excl + v;
        __syncthreads();
    }
    if (tid == 0) o[n] = carry;
}

__global__ void fill5_k(EdgePtrs ep, const int* __restrict__ off, int* __restrict__ cursor,
                        int* __restrict__ srcA, int E)
{
    int i = blockIdx.y;
    int e = blockIdx.x * blockDim.x + threadIdx.x;
    if (e >= E) return;
    int d = ep.e[i][E + e];
    int pos = atomicAdd(&cursor[i * 100000 + d], 1);
    srcA[i * 200000 + off[i * 100032 + d] + pos] = ep.e[i][e];
}

// ---------------------------------------------------------------------------
// Fused gather + mean + lin_l + L2-normalize + sum over <=2 edge types
// ---------------------------------------------------------------------------
template<bool RELU, bool TWO>
__global__ void combine2(
    const float* __restrict__ B0, const float* __restrict__ P0,
    const int* __restrict__ off0, const int* __restrict__ src0,
    const float* __restrict__ B1, const float* __restrict__ P1,
    const int* __restrict__ off1, const int* __restrict__ src1,
    float* __restrict__ out, int n)
{
    int w = (blockIdx.x * blockDim.x + threadIdx.x) >> 5;
    int lane = threadIdx.x & 31;
    if (w >= n) return;
    size_t o = (size_t)w * HIDD + lane * 4;
    float4 r = make_float4(0.f, 0.f, 0.f, 0.f);

    {
        float4 b = *(const float4*)(B0 + o);
        int beg = __ldg(off0 + w), end = __ldg(off0 + w + 1);
        float4 a = make_float4(0.f, 0.f, 0.f, 0.f);
        for (int e = beg; e < end; e++) {
            int s = __ldg(src0 + e);
            float4 p = *(const float4*)(P0 + (size_t)s * HIDD + lane * 4);
            a.x += p.x; a.y += p.y; a.z += p.z; a.w += p.w;
        }
        float inv = 1.0f / fmaxf((float)(end - beg), 1.0f);
        float4 t;
        t.x = b.x + a.x * inv; t.y = b.y + a.y * inv;
        t.z = b.z + a.z * inv; t.w = b.w + a.w * inv;
        float ss = t.x * t.x + t.y * t.y + t.z * t.z + t.w * t.w;
#pragma unroll
        for (int sh = 16; sh; sh >>= 1) ss += __shfl_xor_sync(0xffffffffu, ss, sh);
        float sc = 1.0f / fmaxf(sqrtf(ss), 1e-12f);
        r.x += t.x * sc; r.y += t.y * sc; r.z += t.z * sc; r.w += t.w * sc;
    }
    if (TWO) {
        float4 b = *(const float4*)(B1 + o);
        int beg = __ldg(off1 + w), end = __ldg(off1 + w + 1);
        float4 a = make_float4(0.f, 0.f, 0.f, 0.f);
        for (int e = beg; e < end; e++) {
            int s = __ldg(src1 + e);
            float4 p = *(const float4*)(P1 + (size_t)s * HIDD + lane * 4);
            a.x += p.x; a.y += p.y; a.z += p.z; a.w += p.w;
        }
        float inv = 1.0f / fmaxf((float)(end - beg), 1.0f);
        float4 t;
        t.x = b.x + a.x * inv; t.y = b.y + a.y * inv;
        t.z = b.z + a.z * inv; t.w = b.w + a.w * inv;
        float ss = t.x * t.x + t.y * t.y + t.z * t.z + t.w * t.w;
#pragma unroll
        for (int sh = 16; sh; sh >>= 1) ss += __shfl_xor_sync(0xffffffffu, ss, sh);
        float sc = 1.0f / fmaxf(sqrtf(ss), 1e-12f);
        r.x += t.x * sc; r.y += t.y * sc; r.z += t.z * sc; r.w += t.w * sc;
    }
    if (RELU) {
        r.x = fmaxf(r.x, 0.f); r.y = fmaxf(r.y, 0.f);
        r.z = fmaxf(r.z, 0.f); r.w = fmaxf(r.w, 0.f);
    }
    *(float4*)(out + o) = r;
}

// ---------------------------------------------------------------------------
// SIMT GEMM for the 64-wide head
// ---------------------------------------------------------------------------
template<bool RELU_OUT>
__global__ __launch_bounds__(256) void gemm_tn(
    const float* __restrict__ A, const float* __restrict__ W,
    const float* __restrict__ bias, float* __restrict__ C,
    int M, int N, int K)
{
    __shared__ float As[8][128];
    __shared__ float Ws[8][128];
    const int tid = threadIdx.x;
    const int tx = tid & 15, ty = tid >> 4;
    const int rowBase = blockIdx.y * 128;

    float acc[8][8];
#pragma unroll
    for (int i = 0; i < 8; i++)
#pragma unroll
        for (int j = 0; j < 8; j++) acc[i][j] = 0.f;

    for (int k0 = 0; k0 < K; k0 += 8) {
#pragma unroll
        for (int t = 0; t < 4; t++) {
            int idx = tid + t * 256;
            int k = idx & 7, r = idx >> 3;
            int row = rowBase + r, kk = k0 + k;
            float v = 0.f;
            if (row < M && kk < K) v = A[(size_t)row * K + kk];
            As[k][r] = v;
        }
#pragma unroll
        for (int t = 0; t < 4; t++) {
            int idx = tid + t * 256;
            int k = idx & 7, c = idx >> 3;
            int kk = k0 + k;
            float v = 0.f;
            if (c < N && kk < K) v = W[(size_t)c * K + kk];
            Ws[k][c] = v;
        }
        __syncthreads();
#pragma unroll
        for (int k = 0; k < 8; k++) {
            float4 a0 = *(const float4*)&As[k][ty * 8];
            float4 a1 = *(const float4*)&As[k][ty * 8 + 4];
            float4 b0 = *(const float4*)&Ws[k][tx * 8];
            float4 b1 = *(const float4*)&Ws[k][tx * 8 + 4];
            float av[8] = {a0.x, a0.y, a0.z, a0.w, a1.x, a1.y, a1.z, a1.w};
            float bv[8] = {b0.x, b0.y, b0.z, b0.w, b1.x, b1.y, b1.z, b1.w};
#pragma unroll
            for (int i = 0; i < 8; i++)
#pragma unroll
                for (int j = 0; j < 8; j++) acc[i][j] += av[i] * bv[j];
        }
        __syncthreads();
    }

#pragma unroll
    for (int i = 0; i < 8; i++) {
        int row = rowBase + ty * 8 + i;
        if (row < M) {
#pragma unroll
            for (int j = 0; j < 8; j++) {
                int col = tx * 8 + j;
                if (col < N) {
                    float v = acc[i][j] + bias[col];
                    if (RELU_OUT) v = fmaxf(v, 0.f);
                    C[(size_t)row * N + col] = v;
                }
            }
        }
    }
}

__global__ void head2_k(const float* __restrict__ Z, const float* __restrict__ W2,
                        const float* __restrict__ b2, float* __restrict__ out, int n)
{
    int row = blockIdx.x * blockDim.x + threadIdx.x;
    if (row >= n) return;
    float acc0 = b2[0], acc1 = b2[1];
    const float* z = Z + (size_t)row * 64;
#pragma unroll
    for (int k = 0; k < 64; k++) {
        float zv = z[k];
        acc0 += zv * __ldg(W2 + k);
        acc1 += zv * __ldg(W2 + 64 + k);
    }
    out[row * 2 + 0] = acc0;
    out[row * 2 + 1] = acc1;
}

// ---------------------------------------------------------------------------
extern "C" void kernel_launch(void* const* d_in, const int* in_sizes, int n_in,
                              void* d_out_, int out_size)
{
    const float* x[3] = {(const float*)d_in[0], (const float*)d_in[1], (const float*)d_in[2]};
    const int nn[3] = {N_ART, N_ENT, N_FACT};
    const int* ei[5];
    for (int i = 0; i < 5; i++) ei[i] = (const int*)d_in[3 + i];
    const float* c1llw = (const float*)d_in[8];
    const float* c1llb = (const float*)d_in[9];
    const float* c1lrw = (const float*)d_in[10];
    const float* c2llw = (const float*)d_in[11];
    const float* c2llb = (const float*)d_in[12];
    const float* c2lrw = (const float*)d_in[13];
    const float* hw1 = (const float*)d_in[14];
    const float* hb1 = (const float*)d_in[15];
    const float* hw2 = (const float*)d_in[16];
    const float* hb2 = (const float*)d_in[17];
    float* out = (float*)d_out_;

    // edge i: (src, dst). BOFF: dst-row offsets into B5; POFF: src-row offsets into P5
    static const size_t BOFF[5] = {0, 100000, 150000, 200000, 250000};
    static const size_t POFF[5] = {0, 50000, 100000, 200000, 300000};
    const size_t WB1 = (size_t)128 * 2 * K1S;
    const size_t WB2 = (size_t)128 * 2 * K2S;

    float *B5, *P5, *H1, *Z;
    __nv_bfloat16 *Xs, *H1s, *W1L, *W1R, *W2L, *W2R;
    int *CUR, *OFFS, *SRCA;
    cudaGetSymbolAddress((void**)&B5, g_B5);
    cudaGetSymbolAddress((void**)&P5, g_P5);
    cudaGetSymbolAddress((void**)&H1, g_h1);
    cudaGetSymbolAddress((void**)&Z, g_z);
    cudaGetSymbolAddress((void**)&Xs, g_Xs);
    cudaGetSymbolAddress((void**)&H1s, g_H1s);
    cudaGetSymbolAddress((void**)&W1L, g_W1L);
    cudaGetSymbolAddress((void**)&W1R, g_W1R);
    cudaGetSymbolAddress((void**)&W2L, g_W2L);
    cudaGetSymbolAddress((void**)&W2R, g_W2R);
    cudaGetSymbolAddress((void**)&CUR, g_cursor);
    cudaGetSymbolAddress((void**)&OFFS, g_off);
    cudaGetSymbolAddress((void**)&SRCA, g_srcA);

    cudaFuncSetAttribute(gemm_mma_multi, cudaFuncAttributeMaxDynamicSharedMemorySize, SMEM_TOT);

    const size_t XB[3] = {0,
                          (size_t)N_ART * 2 * K1S,
                          (size_t)(N_ART + N_ENT) * 2 * K1S};
    const size_t H1SLO = (size_t)200000 * K2S;
    const size_t R0[3] = {0, (size_t)N_ART, (size_t)(N_ART + N_ENT)};

    float* h1p[3] = {H1, H1 + (size_t)N_ART * HIDD, H1 + (size_t)(N_ART + N_ENT) * HIDD};
    float* h2p[3] = {out + 100000,
                     out + 100000 + (size_t)N_ART * HIDD,
                     out + 100000 + (size_t)(N_ART + N_ENT) * HIDD};

    // --- splits ---
    for (int t = 0; t < 3; t++)
        splitA_feat<<<nn[t], 256>>>(
            x[t], Xs + XB[t], Xs + XB[t] + (size_t)nn[t] * K1S, FEATD, K1S);
    split2_W<<<640, 256>>>(c1llw, W1L, FEATD, K1S);
    split2_W<<<640, 256>>>(c1lrw, W1R, FEATD, K1S);
    split2_W<<<640, 128>>>(c2llw, W2L, HIDD, K2S);
    split2_W<<<640, 128>>>(c2lrw, W2R, HIDD, K2S);

    // --- CSR build ---
    EdgePtrs ep;
    for (int i = 0; i < 5; i++) ep.e[i] = ei[i];
    cudaMemsetAsync(CUR, 0, 500000 * sizeof(int));
    count5_k<<<dim3((NEDGE + 255) / 256, 5), 256>>>(ep, CUR, NEDGE);
    scan5_k<<<5, 1024>>>(CUR, OFFS);
    cudaMemsetAsync(CUR, 0, 500000 * sizeof(int));
    fill5_k<<<dim3((NEDGE + 255) / 256, 5), 256>>>(ep, OFFS, CUR, SRCA, NEDGE);

    // --- per-node-type fused GEMM block tables ---
    // art (t=0): lin_l e2 -> B[2]; lin_r e0 -> P[0]; lin_r e1 -> P[1]
    // ent (t=1): lin_l e0 -> B[0]; lin_l e4 -> B[4]; lin_r e2 -> P[2]; lin_r e3 -> P[3]
    // fact(t=2): lin_l e1 -> B[1]; lin_l e3 -> B[3]; lin_r e4 -> P[4]
    const int NBLK[3] = {3, 4, 3};
    const int LLe[3][2] = {{2, -1}, {0, 4}, {1, 3}};   // lin_l edge ids per type
    const int LRe[3][2] = {{0, 1}, {2, 3}, {4, -1}};   // lin_r edge ids per type

    for (int layer = 0; layer < 2; layer++) {
        const __nv_bfloat16* WL = layer ? W2L : W1L;
        const __nv_bfloat16* WR = layer ? W2R : W1R;
        const float* bb = layer ? c2llb : c1llb;
        const size_t WB = layer ? WB2 : WB1;
        const int S = layer ? K2S : K1S;

        for (int t = 0; t < 3; t++) {
            MultiOut p;
            int nb = 0;
            for (int j = 0; j < 2; j++) {
                int e = LLe[t][j];
                if (e < 0) break;
                p.W[nb] = WL + (size_t)e * WB;
                p.bias[nb] = bb + e * HIDD;
                p.C[nb] = B5 + BOFF[e] * HIDD;
                nb++;
            }
            for (int j = 0; j < 2; j++) {
                int e = LRe[t][j];
                if (e < 0) break;
                p.W[nb] = WR + (size_t)e * WB;
                p.bias[nb] = nullptr;
                p.C[nb] = P5 + POFF[e] * HIDD;
                nb++;
            }
            const __nv_bfloat16* Ahi;
            const __nv_bfloat16* Alo;
            if (layer == 0) {
                Ahi = Xs + XB[t];
                Alo = Xs + XB[t] + (size_t)nn[t] * K1S;
            } else {
                Ahi = H1s + R0[t] * K2S;
                Alo = H1s + H1SLO + R0[t] * K2S;
            }
            gemm_mma_multi<<<dim3((nn[t] + 127) / 128, NBLK[t]), 256, SMEM_TOT>>>(
                Ahi, Alo, p, nn[t], S);
        }

        // fused combines: art<-e2, ent<-e0+e4, fact<-e1+e3
        float** hp = layer ? h2p : h1p;
        if (layer == 0) {
            combine2<false, false><<<(N_ART + 7) / 8, 256>>>(
                B5 + BOFF[2] * HIDD, P5 + POFF[2] * HIDD, OFFS + 2 * 100032, SRCA + 2 * 200000,
                nullptr, nullptr, nullptr, nullptr, hp[0], N_ART);
            combine2<false, true><<<(N_ENT + 7) / 8, 256>>>(
                B5 + BOFF[0] * HIDD, P5 + POFF[0] * HIDD, OFFS + 0 * 100032, SRCA + 0 * 200000,
                B5 + BOFF[4] * HIDD, P5 + POFF[4] * HIDD, OFFS + 4 * 100032, SRCA + 4 * 200000,
                hp[1], N_ENT);
            combine2<false, true><<<(N_FACT + 7) / 8, 256>>>(
                B5 + BOFF[1] * HIDD, P5 + POFF[1] * HIDD, OFFS + 1 * 100032, SRCA + 1 * 200000,
                B5 + BOFF[3] * HIDD, P5 + POFF[3] * HIDD, OFFS + 3 * 100032, SRCA + 3 * 200000,
                hp[2], N_FACT);
            // relu + split h1 into hi/lo planes
            splitA_h1<<<(200000 + 7) / 8, 256>>>(H1, H1s, H1s + H1SLO, 200000);
        } else {
            combine2<true, false><<<(N_ART + 7) / 8, 256>>>(
                B5 + BOFF[2] * HIDD, P5 + POFF[2] * HIDD, OFFS + 2 * 100032, SRCA + 2 * 200000,
                nullptr, nullptr, nullptr, nullptr, hp[0], N_ART);
            combine2<true, true><<<(N_ENT + 7) / 8, 256>>>(
                B5 + BOFF[0] * HIDD, P5 + POFF[0] * HIDD, OFFS + 0 * 100032, SRCA + 0 * 200000,
                B5 + BOFF[4] * HIDD, P5 + POFF[4] * HIDD, OFFS + 4 * 100032, SRCA + 4 * 200000,
                hp[1], N_ENT);
            combine2<true, true><<<(N_FACT + 7) / 8, 256>>>(
                B5 + BOFF[1] * HIDD, P5 + POFF[1] * HIDD, OFFS + 1 * 100032, SRCA + 1 * 200000,
                B5 + BOFF[3] * HIDD, P5 + POFF[3] * HIDD, OFFS + 3 * 100032, SRCA + 3 * 200000,
                hp[2], N_FACT);
        }
    }

    // --- head MLP on h_art (already relu'd) ---
    gemm_tn<true><<<dim3(1, (N_ART + 127) / 128), 256>>>(
        out + 100000, hw1, hb1, Z, N_ART, 64, HIDD);
    head2_k<<<(N_ART + 255) / 256, 256>>>(Z, hw2, hb2, out, N_ART);
}

// round 9
// speedup vs baseline: 3.4089x; 1.0050x over previous
#include <cuda_runtime.h>
#include <cuda_bf16.h>
#include <math.h>
#include <stdint.h>

#define N_ART 50000
#define N_ENT 100000
#define N_FACT 50000
#define NEDGE 200000
#define FEATD 769
#define HIDD 128

#define K1S 800
#define K2S 128

// ---------------------------------------------------------------------------
// Scratch
// ---------------------------------------------------------------------------
__device__ float g_B5[44800000];                // 5 lin_l outputs (dst rows)
__device__ float g_P5[44800000];                // 5 lin_r outputs (src rows)
__device__ float g_h1[25600000];
__device__ float g_z[3200000];
__device__ __nv_bfloat16 g_Xs[320000000];       // feature planes per type [hi|lo]
__device__ __nv_bfloat16 g_H1s[51200000];       // relu(h1) planes [hi|lo]
__device__ __nv_bfloat16 g_W1L[1024000];
__device__ __nv_bfloat16 g_W1R[1024000];
__device__ __nv_bfloat16 g_W2L[163840];
__device__ __nv_bfloat16 g_W2R[163840];
__device__ int g_cursor[500000];
__device__ int g_off[500160];                   // per-type CSR offsets (stride 100032)
__device__ int g_srcA[1000000];                 // per-type CSR src lists (stride 200000)

// ---------------------------------------------------------------------------
__device__ __forceinline__ uint32_t smem_u32(const void* p) {
    uint32_t a;
    asm("{ .reg .u64 t; cvta.to.shared.u64 t, %1; cvt.u32.u64 %0, t; }"
        : "=r"(a) : "l"(p));
    return a;
}

#define CP_ASYNC16(dst, src) \
    asm volatile("cp.async.cg.shared.global [%0], [%1], 16;" :: "r"(dst), "l"(src))
#define CP_COMMIT() asm volatile("cp.async.commit_group;" ::: "memory")
#define CP_WAIT1()  asm volatile("cp.async.wait_group 1;" ::: "memory")

#define SSTRB 80
#define OFF_AHI 0
#define OFF_ALO 20480
#define OFF_WHI 40960
#define OFF_WLO 61440
#define SMEM_TOT 81920

struct MultiOut {
    const __nv_bfloat16* W[4];
    const float* bias[4];
    float* C[4];
};

// ---------------------------------------------------------------------------
// Fused multi-output tensor-core GEMM.
// grid = (NBLK, ceil(M/128)): weight-block on x (fastest) so sibling CTAs
// sharing one A row-tile are scheduling-adjacent -> A served once from DRAM.
// ---------------------------------------------------------------------------
__global__ __launch_bounds__(256) void gemm_mma_multi(
    const __nv_bfloat16* __restrict__ Ahi, const __nv_bfloat16* __restrict__ Alo,
    MultiOut p, int M, int S)
{
    extern __shared__ char sm[];
    const uint32_t sb = smem_u32(sm);
    const int tid = threadIdx.x, lane = tid & 31, warp = tid >> 5;
    const int mQ = warp >> 1, nH = warp & 1;
    const int rowBase = blockIdx.y * 128;
    const int by = blockIdx.x;
    const __nv_bfloat16* __restrict__ W = p.W[by];
    const float* __restrict__ bias = p.bias[by];
    float* __restrict__ C = p.C[by];
    const int NC = S >> 5;
    const int W2S = 2 * S;

    float acc[2][8][4];
#pragma unroll
    for (int i = 0; i < 2; i++)
#pragma unroll
        for (int j = 0; j < 8; j++)
#pragma unroll
            for (int q = 0; q < 4; q++) acc[i][j][q] = 0.f;

    const int lr4 = tid >> 2, lq4 = tid & 3;

#define LOAD_CHUNK(c, buf) do { \
    int k0 = (c) * 32; \
    _Pragma("unroll") \
    for (int i = 0; i < 2; i++) { \
        int r = lr4 + i * 64; \
        int ga = rowBase + r; if (ga >= M) ga = M - 1; \
        uint32_t so = (buf) * 10240 + r * SSTRB + lq4 * 16; \
        CP_ASYNC16(sb + OFF_AHI + so, Ahi + (size_t)ga * S + k0 + lq4 * 8); \
        CP_ASYNC16(sb + OFF_ALO + so, Alo + (size_t)ga * S + k0 + lq4 * 8); \
        CP_ASYNC16(sb + OFF_WHI + so, W + (size_t)r * W2S + k0 + lq4 * 8); \
        CP_ASYNC16(sb + OFF_WLO + so, W + (size_t)r * W2S + S + k0 + lq4 * 8); \
    } } while (0)

    LOAD_CHUNK(0, 0); CP_COMMIT();
    if (NC > 1) { LOAD_CHUNK(1, 1); }
    CP_COMMIT();

    const int a_row = lane & 15;
    const int a_sel = (lane >> 4) & 1;
    const int b_row = (lane & 7) + ((lane & 16) >> 1);
    const int b_sel = (lane >> 3) & 1;

    auto do_pass = [&](uint32_t abase, uint32_t wbase) {
#pragma unroll
        for (int kh = 0; kh < 2; kh++) {
            uint32_t ar[2][4], br[8][2];
#pragma unroll
            for (int mi = 0; mi < 2; mi++) {
                uint32_t addr = abase + (mQ * 32 + mi * 16 + a_row) * SSTRB
                                + kh * 32 + a_sel * 16;
                asm volatile(
                    "ldmatrix.sync.aligned.m8n8.x4.shared.b16 {%0,%1,%2,%3}, [%4];"
                    : "=r"(ar[mi][0]), "=r"(ar[mi][1]), "=r"(ar[mi][2]), "=r"(ar[mi][3])
                    : "r"(addr));
            }
#pragma unroll
            for (int pi = 0; pi < 4; pi++) {
                uint32_t addr = wbase + (nH * 64 + pi * 16 + b_row) * SSTRB
                                + kh * 32 + b_sel * 16;
                asm volatile(
                    "ldmatrix.sync.aligned.m8n8.x4.shared.b16 {%0,%1,%2,%3}, [%4];"
                    : "=r"(br[2 * pi][0]), "=r"(br[2 * pi][1]),
                      "=r"(br[2 * pi + 1][0]), "=r"(br[2 * pi + 1][1])
                    : "r"(addr));
            }
#pragma unroll
            for (int mi = 0; mi < 2; mi++)
#pragma unroll
                for (int ni = 0; ni < 8; ni++) {
                    asm volatile(
                        "mma.sync.aligned.m16n8k16.row.col.f32.bf16.bf16.f32 "
                        "{%0,%1,%2,%3}, {%4,%5,%6,%7}, {%8,%9}, {%0,%1,%2,%3};"
                        : "+f"(acc[mi][ni][0]), "+f"(acc[mi][ni][1]),
                          "+f"(acc[mi][ni][2]), "+f"(acc[mi][ni][3])
                        : "r"(ar[mi][0]), "r"(ar[mi][1]), "r"(ar[mi][2]), "r"(ar[mi][3]),
                          "r"(br[ni][0]), "r"(br[ni][1]));
                }
        }
    };

    for (int c = 0; c < NC; c++) {
        CP_WAIT1();
        __syncthreads();
        uint32_t bo = (uint32_t)(c & 1) * 10240;
        do_pass(sb + OFF_AHI + bo, sb + OFF_WHI + bo);
        do_pass(sb + OFF_ALO + bo, sb + OFF_WHI + bo);
        do_pass(sb + OFF_AHI + bo, sb + OFF_WLO + bo);
        __syncthreads();
        if (c + 2 < NC) LOAD_CHUNK(c + 2, c & 1);
        CP_COMMIT();
    }
#undef LOAD_CHUNK

    const int g = lane >> 2, t = lane & 3;
#pragma unroll
    for (int mi = 0; mi < 2; mi++) {
        int r0 = rowBase + mQ * 32 + mi * 16 + g;
#pragma unroll
        for (int ni = 0; ni < 8; ni++) {
            int col = nH * 64 + ni * 8 + t * 2;
            float bx = 0.f, by2 = 0.f;
            if (bias) { bx = bias[col]; by2 = bias[col + 1]; }
            if (r0 < M) {
                float2 v = make_float2(acc[mi][ni][0] + bx, acc[mi][ni][1] + by2);
                *(float2*)(C + (size_t)r0 * 128 + col) = v;
            }
            if (r0 + 8 < M) {
                float2 v = make_float2(acc[mi][ni][2] + bx, acc[mi][ni][3] + by2);
                *(float2*)(C + (size_t)(r0 + 8) * 128 + col) = v;
            }
        }
    }
}

// ---------------------------------------------------------------------------
// Splits
// ---------------------------------------------------------------------------
__global__ void splitA_feat(const float* __restrict__ in,
                            __nv_bfloat16* __restrict__ outHi,
                            __nv_bfloat16* __restrict__ outLo, int K, int S)
{
    int row = blockIdx.x;
    int k = threadIdx.x * 4;
    if (k >= S) return;
    const float* src = in + (size_t)row * K;
    float v[4];
#pragma unroll
    for (int j = 0; j < 4; j++) {
        int kk = k + j;
        v[j] = (kk < K) ? src[kk] : 0.f;
    }
    __nv_bfloat16 h[4], l[4];
#pragma unroll
    for (int j = 0; j < 4; j++) {
        h[j] = __float2bfloat16(v[j]);
        l[j] = __float2bfloat16(v[j] - __bfloat162float(h[j]));
    }
    *(uint2*)(outHi + (size_t)row * S + k) = *(uint2*)h;
    *(uint2*)(outLo + (size_t)row * S + k) = *(uint2*)l;
}

__global__ void splitA_h1(const float* __restrict__ in,
                          __nv_bfloat16* __restrict__ outHi,
                          __nv_bfloat16* __restrict__ outLo, int M)
{
    int w = (blockIdx.x * blockDim.x + threadIdx.x) >> 5;
    int lane = threadIdx.x & 31;
    if (w >= M) return;
    size_t o = (size_t)w * 128 + lane * 4;
    float4 v = *(const float4*)(in + o);
    float vv[4] = {fmaxf(v.x, 0.f), fmaxf(v.y, 0.f), fmaxf(v.z, 0.f), fmaxf(v.w, 0.f)};
    __nv_bfloat16 h[4], l[4];
#pragma unroll
    for (int j = 0; j < 4; j++) {
        h[j] = __float2bfloat16(vv[j]);
        l[j] = __float2bfloat16(vv[j] - __bfloat162float(h[j]));
    }
    *(uint2*)(outHi + o) = *(uint2*)h;
    *(uint2*)(outLo + o) = *(uint2*)l;
}

__global__ void split2_W(const float* __restrict__ in, __nv_bfloat16* __restrict__ out,
                         int K, int S)
{
    int row = blockIdx.x;
    const float* src = in + (size_t)row * K;
    __nv_bfloat16* d = out + (size_t)row * (2 * S);
    for (int k = threadIdx.x; k < S; k += blockDim.x) {
        __nv_bfloat16 hi = __float2bfloat16(0.f), lo = hi;
        if (k < K) {
            float v = src[k];
            hi = __float2bfloat16(v);
            lo = __float2bfloat16(v - __bfloat162float(hi));
        }
        d[k] = hi;
        d[S + k] = lo;
    }
}

// ---------------------------------------------------------------------------
// CSR build
// ---------------------------------------------------------------------------
struct EdgePtrs { const int* e[5]; };

__global__ void count5_k(EdgePtrs ep, int* __restrict__ cnt, int E)
{
    int i = blockIdx.y;
    int e = blockIdx.x * blockDim.x + threadIdx.x;
    if (e < E) atomicAdd(&cnt[i * 100000 + ep.e[i][E + e]], 1);
}

__constant__ int c_dstN[5] = {100000, 50000, 50000, 50000, 100000};

__global__ void scan5_k(const int* __restrict__ cnt, int* __restrict__ off)
{
    __shared__ int sh[32];
    __shared__ int carry;
    int type = blockIdx.x;
    const int n = c_dstN[type];
    const int* c = cnt + type * 100000;
    int* o = off + type * 100032;
    int tid = threadIdx.x, lane = tid & 31, w = tid >> 5;
    if (tid == 0) carry = 0;
    __syncthreads();
    for (int base = 0; base < n; base += 1024) {
        int i = base + tid;
        int v = (i < n) ? c[i] : 0;
        int x = v;
#pragma unroll
        for (int d = 1; d < 32; d <<= 1) {
            int y = __shfl_up_sync(0xffffffffu, x, d);
            if (lane >= d) x += y;
        }
        if (lane == 31) sh[w] = x;
        __syncthreads();
        if (w == 0) {
            int s = sh[lane];
#pragma unroll
            for (int d = 1; d < 32; d <<= 1) {
                int y = __shfl_up_sync(0xffffffffu, s, d);
                if (lane >= d) s += y;
            }
            sh[lane] = s;
        }
        __syncthreads();
        int excl = x - v + (w > 0 ? sh[w - 1] : 0) + carry;
        if (i < n) o[i] = excl;
        __syncthreads();
        if (tid == 1023) carry = excl + v;
        __syncthreads();
    }
    if (tid == 0) o[n] = carry;
}

__global__ void fill5_k(EdgePtrs ep, const int* __restrict__ off, int* __restrict__ cursor,
                        int* __restrict__ srcA, int E)
{
    int i = blockIdx.y;
    int e = blockIdx.x * blockDim.x + threadIdx.x;
    if (e >= E) return;
    int d = ep.e[i][E + e];
    int pos = atomicAdd(&cursor[i * 100000 + d], 1);
    srcA[i * 200000 + off[i * 100032 + d] + pos] = ep.e[i][e];
}

// ---------------------------------------------------------------------------
// Fused gather + mean + lin_l + L2-normalize + sum over <=2 edge types
// ---------------------------------------------------------------------------
template<bool RELU, bool TWO>
__global__ void combine2(
    const float* __restrict__ B0, const float* __restrict__ P0,
    const int* __restrict__ off0, const int* __restrict__ src0,
    const float* __restrict__ B1, const float* __restrict__ P1,
    const int* __restrict__ off1, const int* __restrict__ src1,
    float* __restrict__ out, int n)
{
    int w = (blockIdx.x * blockDim.x + threadIdx.x) >> 5;
    int lane = threadIdx.x & 31;
    if (w >= n) return;
    size_t o = (size_t)w * HIDD + lane * 4;
    float4 r = make_float4(0.f, 0.f, 0.f, 0.f);

    {
        float4 b = *(const float4*)(B0 + o);
        int beg = __ldg(off0 + w), end = __ldg(off0 + w + 1);
        float4 a = make_float4(0.f, 0.f, 0.f, 0.f);
        for (int e = beg; e < end; e++) {
            int s = __ldg(src0 + e);
            float4 p = *(const float4*)(P0 + (size_t)s * HIDD + lane * 4);
            a.x += p.x; a.y += p.y; a.z += p.z; a.w += p.w;
        }
        float inv = 1.0f / fmaxf((float)(end - beg), 1.0f);
        float4 t;
        t.x = b.x + a.x * inv; t.y = b.y + a.y * inv;
        t.z = b.z + a.z * inv; t.w = b.w + a.w * inv;
        float ss = t.x * t.x + t.y * t.y + t.z * t.z + t.w * t.w;
#pragma unroll
        for (int sh = 16; sh; sh >>= 1) ss += __shfl_xor_sync(0xffffffffu, ss, sh);
        float sc = 1.0f / fmaxf(sqrtf(ss), 1e-12f);
        r.x += t.x * sc; r.y += t.y * sc; r.z += t.z * sc; r.w += t.w * sc;
    }
    if (TWO) {
        float4 b = *(const float4*)(B1 + o);
        int beg = __ldg(off1 + w), end = __ldg(off1 + w + 1);
        float4 a = make_float4(0.f, 0.f, 0.f, 0.f);
        for (int e = beg; e < end; e++) {
            int s = __ldg(src1 + e);
            float4 p = *(const float4*)(P1 + (size_t)s * HIDD + lane * 4);
            a.x += p.x; a.y += p.y; a.z += p.z; a.w += p.w;
        }
        float inv = 1.0f / fmaxf((float)(end - beg), 1.0f);
        float4 t;
        t.x = b.x + a.x * inv; t.y = b.y + a.y * inv;
        t.z = b.z + a.z * inv; t.w = b.w + a.w * inv;
        float ss = t.x * t.x + t.y * t.y + t.z * t.z + t.w * t.w;
#pragma unroll
        for (int sh = 16; sh; sh >>= 1) ss += __shfl_xor_sync(0xffffffffu, ss, sh);
        float sc = 1.0f / fmaxf(sqrtf(ss), 1e-12f);
        r.x += t.x * sc; r.y += t.y * sc; r.z += t.z * sc; r.w += t.w * sc;
    }
    if (RELU) {
        r.x = fmaxf(r.x, 0.f); r.y = fmaxf(r.y, 0.f);
        r.z = fmaxf(r.z, 0.f); r.w = fmaxf(r.w, 0.f);
    }
    *(float4*)(out + o) = r;
}

// ---------------------------------------------------------------------------
// SIMT GEMM for the 64-wide head
// ---------------------------------------------------------------------------
template<bool RELU_OUT>
__global__ __launch_bounds__(256) void gemm_tn(
    const float* __restrict__ A, const float* __restrict__ W,
    const float* __restrict__ bias, float* __restrict__ C,
    int M, int N, int K)
{
    __shared__ float As[8][128];
    __shared__ float Ws[8][128];
    const int tid = threadIdx.x;
    const int tx = tid & 15, ty = tid >> 4;
    const int rowBase = blockIdx.y * 128;

    float acc[8][8];
#pragma unroll
    for (int i = 0; i < 8; i++)
#pragma unroll
        for (int j = 0; j < 8; j++) acc[i][j] = 0.f;

    for (int k0 = 0; k0 < K; k0 += 8) {
#pragma unroll
        for (int t = 0; t < 4; t++) {
            int idx = tid + t * 256;
            int k = idx & 7, r = idx >> 3;
            int row = rowBase + r, kk = k0 + k;
            float v = 0.f;
            if (row < M && kk < K) v = A[(size_t)row * K + kk];
            As[k][r] = v;
        }
#pragma unroll
        for (int t = 0; t < 4; t++) {
            int idx = tid + t * 256;
            int k = idx & 7, c = idx >> 3;
            int kk = k0 + k;
            float v = 0.f;
            if (c < N && kk < K) v = W[(size_t)c * K + kk];
            Ws[k][c] = v;
        }
        __syncthreads();
#pragma unroll
        for (int k = 0; k < 8; k++) {
            float4 a0 = *(const float4*)&As[k][ty * 8];
            float4 a1 = *(const float4*)&As[k][ty * 8 + 4];
            float4 b0 = *(const float4*)&Ws[k][tx * 8];
            float4 b1 = *(const float4*)&Ws[k][tx * 8 + 4];
            float av[8] = {a0.x, a0.y, a0.z, a0.w, a1.x, a1.y, a1.z, a1.w};
            float bv[8] = {b0.x, b0.y, b0.z, b0.w, b1.x, b1.y, b1.z, b1.w};
#pragma unroll
            for (int i = 0; i < 8; i++)
#pragma unroll
                for (int j = 0; j < 8; j++) acc[i][j] += av[i] * bv[j];
        }
        __syncthreads();
    }

#pragma unroll
    for (int i = 0; i < 8; i++) {
        int row = rowBase + ty * 8 + i;
        if (row < M) {
#pragma unroll
            for (int j = 0; j < 8; j++) {
                int col = tx * 8 + j;
                if (col < N) {
                    float v = acc[i][j] + bias[col];
                    if (RELU_OUT) v = fmaxf(v, 0.f);
                    C[(size_t)row * N + col] = v;
                }
            }
        }
    }
}

__global__ void head2_k(const float* __restrict__ Z, const float* __restrict__ W2,
                        const float* __restrict__ b2, float* __restrict__ out, int n)
{
    int row = blockIdx.x * blockDim.x + threadIdx.x;
    if (row >= n) return;
    float acc0 = b2[0], acc1 = b2[1];
    const float* z = Z + (size_t)row * 64;
#pragma unroll
    for (int k = 0; k < 64; k++) {
        float zv = z[k];
        acc0 += zv * __ldg(W2 + k);
        acc1 += zv * __ldg(W2 + 64 + k);
    }
    out[row * 2 + 0] = acc0;
    out[row * 2 + 1] = acc1;
}

// ---------------------------------------------------------------------------
extern "C" void kernel_launch(void* const* d_in, const int* in_sizes, int n_in,
                              void* d_out_, int out_size)
{
    const float* x[3] = {(const float*)d_in[0], (const float*)d_in[1], (const float*)d_in[2]};
    const int nn[3] = {N_ART, N_ENT, N_FACT};
    const int* ei[5];
    for (int i = 0; i < 5; i++) ei[i] = (const int*)d_in[3 + i];
    const float* c1llw = (const float*)d_in[8];
    const float* c1llb = (const float*)d_in[9];
    const float* c1lrw = (const float*)d_in[10];
    const float* c2llw = (const float*)d_in[11];
    const float* c2llb = (const float*)d_in[12];
    const float* c2lrw = (const float*)d_in[13];
    const float* hw1 = (const float*)d_in[14];
    const float* hb1 = (const float*)d_in[15];
    const float* hw2 = (const float*)d_in[16];
    const float* hb2 = (const float*)d_in[17];
    float* out = (float*)d_out_;

    static const size_t BOFF[5] = {0, 100000, 150000, 200000, 250000};
    static const size_t POFF[5] = {0, 50000, 100000, 200000, 300000};
    const size_t WB1 = (size_t)128 * 2 * K1S;
    const size_t WB2 = (size_t)128 * 2 * K2S;

    float *B5, *P5, *H1, *Z;
    __nv_bfloat16 *Xs, *H1s, *W1L, *W1R, *W2L, *W2R;
    int *CUR, *OFFS, *SRCA;
    cudaGetSymbolAddress((void**)&B5, g_B5);
    cudaGetSymbolAddress((void**)&P5, g_P5);
    cudaGetSymbolAddress((void**)&H1, g_h1);
    cudaGetSymbolAddress((void**)&Z, g_z);
    cudaGetSymbolAddress((void**)&Xs, g_Xs);
    cudaGetSymbolAddress((void**)&H1s, g_H1s);
    cudaGetSymbolAddress((void**)&W1L, g_W1L);
    cudaGetSymbolAddress((void**)&W1R, g_W1R);
    cudaGetSymbolAddress((void**)&W2L, g_W2L);
    cudaGetSymbolAddress((void**)&W2R, g_W2R);
    cudaGetSymbolAddress((void**)&CUR, g_cursor);
    cudaGetSymbolAddress((void**)&OFFS, g_off);
    cudaGetSymbolAddress((void**)&SRCA, g_srcA);

    cudaFuncSetAttribute(gemm_mma_multi, cudaFuncAttributeMaxDynamicSharedMemorySize, SMEM_TOT);

    const size_t XB[3] = {0,
                          (size_t)N_ART * 2 * K1S,
                          (size_t)(N_ART + N_ENT) * 2 * K1S};
    const size_t H1SLO = (size_t)200000 * K2S;
    const size_t R0[3] = {0, (size_t)N_ART, (size_t)(N_ART + N_ENT)};

    float* h1p[3] = {H1, H1 + (size_t)N_ART * HIDD, H1 + (size_t)(N_ART + N_ENT) * HIDD};
    float* h2p[3] = {out + 100000,
                     out + 100000 + (size_t)N_ART * HIDD,
                     out + 100000 + (size_t)(N_ART + N_ENT) * HIDD};

    // GEMM block tables per node type
    const int NBLK[3] = {3, 4, 3};
    const int LLe[3][2] = {{2, -1}, {0, 4}, {1, 3}};
    const int LRe[3][2] = {{0, 1}, {2, 3}, {4, -1}};

    auto launch_gemm = [&](int layer, int t) {
        const __nv_bfloat16* WL = layer ? W2L : W1L;
        const __nv_bfloat16* WR = layer ? W2R : W1R;
        const float* bb = layer ? c2llb : c1llb;
        const size_t WB = layer ? WB2 : WB1;
        const int S = layer ? K2S : K1S;
        MultiOut p;
        int nb = 0;
        for (int j = 0; j < 2; j++) {
            int e = LLe[t][j];
            if (e < 0) break;
            p.W[nb] = WL + (size_t)e * WB;
            p.bias[nb] = bb + e * HIDD;
            p.C[nb] = B5 + BOFF[e] * HIDD;
            nb++;
        }
        for (int j = 0; j < 2; j++) {
            int e = LRe[t][j];
            if (e < 0) break;
            p.W[nb] = WR + (size_t)e * WB;
            p.bias[nb] = nullptr;
            p.C[nb] = P5 + POFF[e] * HIDD;
            nb++;
        }
        const __nv_bfloat16* Ahi;
        const __nv_bfloat16* Alo;
        if (layer == 0) {
            Ahi = Xs + XB[t];
            Alo = Xs + XB[t] + (size_t)nn[t] * K1S;
        } else {
            Ahi = H1s + R0[t] * K2S;
            Alo = H1s + H1SLO + R0[t] * K2S;
        }
        gemm_mma_multi<<<dim3(NBLK[t], (nn[t] + 127) / 128), 256, SMEM_TOT>>>(
            Ahi, Alo, p, nn[t], S);
    };

    // --- launches 1-5: feature + W1 splits ---
    for (int t = 0; t < 3; t++)
        splitA_feat<<<nn[t], 256>>>(
            x[t], Xs + XB[t], Xs + XB[t] + (size_t)nn[t] * K1S, FEATD, K1S);
    split2_W<<<640, 256>>>(c1llw, W1L, FEATD, K1S);
    split2_W<<<640, 256>>>(c1lrw, W1R, FEATD, K1S);

    // --- launch 6: ent layer-1 GEMM (ncu -s 5 -c 1 captures this) ---
    launch_gemm(0, 1);
    launch_gemm(0, 0);
    launch_gemm(0, 2);

    // --- CSR build + W2 splits (overlap-ish after GEMM issue) ---
    EdgePtrs ep;
    for (int i = 0; i < 5; i++) ep.e[i] = ei[i];
    cudaMemsetAsync(CUR, 0, 500000 * sizeof(int));
    count5_k<<<dim3((NEDGE + 255) / 256, 5), 256>>>(ep, CUR, NEDGE);
    scan5_k<<<5, 1024>>>(CUR, OFFS);
    cudaMemsetAsync(CUR, 0, 500000 * sizeof(int));
    fill5_k<<<dim3((NEDGE + 255) / 256, 5), 256>>>(ep, OFFS, CUR, SRCA, NEDGE);
    split2_W<<<640, 128>>>(c2llw, W2L, HIDD, K2S);
    split2_W<<<640, 128>>>(c2lrw, W2R, HIDD, K2S);

    // --- layer-1 combines ---
    combine2<false, false><<<(N_ART + 7) / 8, 256>>>(
        B5 + BOFF[2] * HIDD, P5 + POFF[2] * HIDD, OFFS + 2 * 100032, SRCA + 2 * 200000,
        nullptr, nullptr, nullptr, nullptr, h1p[0], N_ART);
    combine2<false, true><<<(N_ENT + 7) / 8, 256>>>(
        B5 + BOFF[0] * HIDD, P5 + POFF[0] * HIDD, OFFS + 0 * 100032, SRCA + 0 * 200000,
        B5 + BOFF[4] * HIDD, P5 + POFF[4] * HIDD, OFFS + 4 * 100032, SRCA + 4 * 200000,
        h1p[1], N_ENT);
    combine2<false, true><<<(N_FACT + 7) / 8, 256>>>(
        B5 + BOFF[1] * HIDD, P5 + POFF[1] * HIDD, OFFS + 1 * 100032, SRCA + 1 * 200000,
        B5 + BOFF[3] * HIDD, P5 + POFF[3] * HIDD, OFFS + 3 * 100032, SRCA + 3 * 200000,
        h1p[2], N_FACT);

    // --- relu + split h1 ---
    splitA_h1<<<(200000 + 7) / 8, 256>>>(H1, H1s, H1s + H1SLO, 200000);

    // --- layer-2 GEMMs ---
    launch_gemm(1, 1);
    launch_gemm(1, 0);
    launch_gemm(1, 2);

    // --- layer-2 combines (relu fused) ---
    combine2<true, false><<<(N_ART + 7) / 8, 256>>>(
        B5 + BOFF[2] * HIDD, P5 + POFF[2] * HIDD, OFFS + 2 * 100032, SRCA + 2 * 200000,
        nullptr, nullptr, nullptr, nullptr, h2p[0], N_ART);
    combine2<true, true><<<(N_ENT + 7) / 8, 256>>>(
        B5 + BOFF[0] * HIDD, P5 + POFF[0] * HIDD, OFFS + 0 * 100032, SRCA + 0 * 200000,
        B5 + BOFF[4] * HIDD, P5 + POFF[4] * HIDD, OFFS + 4 * 100032, SRCA + 4 * 200000,
        h2p[1], N_ENT);
    combine2<true, true><<<(N_FACT + 7) / 8, 256>>>(
        B5 + BOFF[1] * HIDD, P5 + POFF[1] * HIDD, OFFS + 1 * 100032, SRCA + 1 * 200000,
        B5 + BOFF[3] * HIDD, P5 + POFF[3] * HIDD, OFFS + 3 * 100032, SRCA + 3 * 200000,
        h2p[2], N_FACT);

    // --- head MLP ---
    gemm_tn<true><<<dim3(1, (N_ART + 127) / 128), 256>>>(
        out + 100000, hw1, hb1, Z, N_ART, 64, HIDD);
    head2_k<<<(N_ART + 255) / 256, 256>>>(Z, hw2, hb2, out, N_ART);
}

// round 10
// speedup vs baseline: 4.1710x; 1.2236x over previous
#include <cuda_runtime.h>
#include <cuda_bf16.h>
#include <cuda_fp16.h>
#include <math.h>
#include <stdint.h>

#define N_ART 50000
#define N_ENT 100000
#define N_FACT 50000
#define NEDGE 200000
#define FEATD 769
#define HIDD 128

#define K1S 800
#define K2S 128

// ---------------------------------------------------------------------------
// Scratch
// ---------------------------------------------------------------------------
__device__ float g_B5[44800000];                // 5 lin_l outputs (dst rows)
__device__ float g_P5[44800000];                // 5 lin_r outputs (src rows)
__device__ float g_h1[25600000];
__device__ float g_z[3200000];
__device__ __half g_Xh[160000000];              // fp16 features: 200k x 800
__device__ __nv_bfloat16 g_H1s[51200000];       // relu(h1) bf16 planes [hi|lo]
__device__ __half g_W1L[1024000];               // c1 lin_l fp16 rows [hi(800)|lo(800)]
__device__ __half g_W1R[1024000];
__device__ __nv_bfloat16 g_W2L[163840];         // c2 bf16 rows [hi|lo]
__device__ __nv_bfloat16 g_W2R[163840];
__device__ int g_cursor[500000];
__device__ int g_off[500160];                   // per-type CSR offsets (stride 100032)
__device__ int g_srcA[1000000];                 // per-type CSR src lists (stride 200000)

// ---------------------------------------------------------------------------
__device__ __forceinline__ uint32_t smem_u32(const void* p) {
    uint32_t a;
    asm("{ .reg .u64 t; cvta.to.shared.u64 t, %1; cvt.u32.u64 %0, t; }"
        : "=r"(a) : "l"(p));
    return a;
}

#define CP_ASYNC16(dst, src) \
    asm volatile("cp.async.cg.shared.global [%0], [%1], 16;" :: "r"(dst), "l"(src))
#define CP_COMMIT() asm volatile("cp.async.commit_group;" ::: "memory")
#define CP_WAIT1()  asm volatile("cp.async.wait_group 1;" ::: "memory")

#define SSTRB 80

struct MultiOut {
    const void* W[4];
    const float* bias[4];
    float* C[4];
};

// ---------------------------------------------------------------------------
// ldmatrix / mma helpers
// ---------------------------------------------------------------------------
#define LDMX4(r0, r1, r2, r3, addr) \
    asm volatile("ldmatrix.sync.aligned.m8n8.x4.shared.b16 {%0,%1,%2,%3}, [%4];" \
                 : "=r"(r0), "=r"(r1), "=r"(r2), "=r"(r3) : "r"(addr))

#define MMA_BF16(acc, a, b) \
    asm volatile("mma.sync.aligned.m16n8k16.row.col.f32.bf16.bf16.f32 " \
                 "{%0,%1,%2,%3}, {%4,%5,%6,%7}, {%8,%9}, {%0,%1,%2,%3};" \
                 : "+f"((acc)[0]), "+f"((acc)[1]), "+f"((acc)[2]), "+f"((acc)[3]) \
                 : "r"((a)[0]), "r"((a)[1]), "r"((a)[2]), "r"((a)[3]), \
                   "r"((b)[0]), "r"((b)[1]))

#define MMA_FP16(acc, a, b) \
    asm volatile("mma.sync.aligned.m16n8k16.row.col.f32.f16.f16.f32 " \
                 "{%0,%1,%2,%3}, {%4,%5,%6,%7}, {%8,%9}, {%0,%1,%2,%3};" \
                 : "+f"((acc)[0]), "+f"((acc)[1]), "+f"((acc)[2]), "+f"((acc)[3]) \
                 : "r"((a)[0]), "r"((a)[1]), "r"((a)[2]), "r"((a)[3]), \
                   "r"((b)[0]), "r"((b)[1]))

// ---------------------------------------------------------------------------
// Layer-1 GEMM: fp16 2-pass. A[M,S] single fp16 plane; W rows [hi(S)|lo(S)].
//   C = A@Whi^T + A@Wlo^T (+bias). grid = (NBLK, ceil(M/128)), 256 thr.
// SMEM planes: A(2x10240) | WHI(2x10240) | WLO(2x10240) = 61440 B
// ---------------------------------------------------------------------------
#define F_OFF_A   0
#define F_OFF_WHI 20480
#define F_OFF_WLO 40960
#define SMEM_FP16 61440

__global__ __launch_bounds__(256) void gemm_fp16_multi(
    const __half* __restrict__ A, MultiOut p, int M, int S)
{
    extern __shared__ char sm[];
    const uint32_t sb = smem_u32(sm);
    const int tid = threadIdx.x, lane = tid & 31, warp = tid >> 5;
    const int mQ = warp >> 1, nH = warp & 1;
    const int rowBase = blockIdx.y * 128;
    const __half* __restrict__ W = (const __half*)p.W[blockIdx.x];
    const float* __restrict__ bias = p.bias[blockIdx.x];
    float* __restrict__ C = p.C[blockIdx.x];
    const int NC = S >> 5;
    const int W2S = 2 * S;

    float acc[2][8][4];
#pragma unroll
    for (int i = 0; i < 2; i++)
#pragma unroll
        for (int j = 0; j < 8; j++)
#pragma unroll
            for (int q = 0; q < 4; q++) acc[i][j][q] = 0.f;

    const int lr4 = tid >> 2, lq4 = tid & 3;

#define FLOAD(c, buf) do { \
    int k0 = (c) * 32; \
    _Pragma("unroll") \
    for (int i = 0; i < 2; i++) { \
        int r = lr4 + i * 64; \
        int ga = rowBase + r; if (ga >= M) ga = M - 1; \
        uint32_t so = (buf) * 10240 + r * SSTRB + lq4 * 16; \
        CP_ASYNC16(sb + F_OFF_A + so, A + (size_t)ga * S + k0 + lq4 * 8); \
        CP_ASYNC16(sb + F_OFF_WHI + so, W + (size_t)r * W2S + k0 + lq4 * 8); \
        CP_ASYNC16(sb + F_OFF_WLO + so, W + (size_t)r * W2S + S + k0 + lq4 * 8); \
    } } while (0)

    FLOAD(0, 0); CP_COMMIT();
    if (NC > 1) { FLOAD(1, 1); }
    CP_COMMIT();

    const int a_row = lane & 15;
    const int a_sel = (lane >> 4) & 1;
    const int b_row = (lane & 7) + ((lane & 16) >> 1);
    const int b_sel = (lane >> 3) & 1;

    auto do_pass = [&](uint32_t abase, uint32_t wbase) {
#pragma unroll
        for (int kh = 0; kh < 2; kh++) {
            uint32_t ar[2][4], br[8][2];
#pragma unroll
            for (int mi = 0; mi < 2; mi++) {
                uint32_t addr = abase + (mQ * 32 + mi * 16 + a_row) * SSTRB
                                + kh * 32 + a_sel * 16;
                LDMX4(ar[mi][0], ar[mi][1], ar[mi][2], ar[mi][3], addr);
            }
#pragma unroll
            for (int pi = 0; pi < 4; pi++) {
                uint32_t addr = wbase + (nH * 64 + pi * 16 + b_row) * SSTRB
                                + kh * 32 + b_sel * 16;
                LDMX4(br[2 * pi][0], br[2 * pi][1],
                      br[2 * pi + 1][0], br[2 * pi + 1][1], addr);
            }
#pragma unroll
            for (int mi = 0; mi < 2; mi++)
#pragma unroll
                for (int ni = 0; ni < 8; ni++)
                    MMA_FP16(acc[mi][ni], ar[mi], br[ni]);
        }
    };

    for (int c = 0; c < NC; c++) {
        CP_WAIT1();
        __syncthreads();
        uint32_t bo = (uint32_t)(c & 1) * 10240;
        do_pass(sb + F_OFF_A + bo, sb + F_OFF_WHI + bo);
        do_pass(sb + F_OFF_A + bo, sb + F_OFF_WLO + bo);
        __syncthreads();
        if (c + 2 < NC) FLOAD(c + 2, c & 1);
        CP_COMMIT();
    }
#undef FLOAD

    const int g = lane >> 2, t = lane & 3;
#pragma unroll
    for (int mi = 0; mi < 2; mi++) {
        int r0 = rowBase + mQ * 32 + mi * 16 + g;
#pragma unroll
        for (int ni = 0; ni < 8; ni++) {
            int col = nH * 64 + ni * 8 + t * 2;
            float bx = 0.f, by2 = 0.f;
            if (bias) { bx = bias[col]; by2 = bias[col + 1]; }
            if (r0 < M) {
                float2 v = make_float2(acc[mi][ni][0] + bx, acc[mi][ni][1] + by2);
                *(float2*)(C + (size_t)r0 * 128 + col) = v;
            }
            if (r0 + 8 < M) {
                float2 v = make_float2(acc[mi][ni][2] + bx, acc[mi][ni][3] + by2);
                *(float2*)(C + (size_t)(r0 + 8) * 128 + col) = v;
            }
        }
    }
}

// ---------------------------------------------------------------------------
// Layer-2 GEMM: proven bf16 3-pass (Ahi/Alo planes, W rows [hi|lo])
// ---------------------------------------------------------------------------
#define OFF_AHI 0
#define OFF_ALO 20480
#define OFF_WHI 40960
#define OFF_WLO 61440
#define SMEM_TOT 81920

__global__ __launch_bounds__(256) void gemm_mma_multi(
    const __nv_bfloat16* __restrict__ Ahi, const __nv_bfloat16* __restrict__ Alo,
    MultiOut p, int M, int S)
{
    extern __shared__ char sm[];
    const uint32_t sb = smem_u32(sm);
    const int tid = threadIdx.x, lane = tid & 31, warp = tid >> 5;
    const int mQ = warp >> 1, nH = warp & 1;
    const int rowBase = blockIdx.y * 128;
    const __nv_bfloat16* __restrict__ W = (const __nv_bfloat16*)p.W[blockIdx.x];
    const float* __restrict__ bias = p.bias[blockIdx.x];
    float* __restrict__ C = p.C[blockIdx.x];
    const int NC = S >> 5;
    const int W2S = 2 * S;

    float acc[2][8][4];
#pragma unroll
    for (int i = 0; i < 2; i++)
#pragma unroll
        for (int j = 0; j < 8; j++)
#pragma unroll
            for (int q = 0; q < 4; q++) acc[i][j][q] = 0.f;

    const int lr4 = tid >> 2, lq4 = tid & 3;

#define LOAD_CHUNK(c, buf) do { \
    int k0 = (c) * 32; \
    _Pragma("unroll") \
    for (int i = 0; i < 2; i++) { \
        int r = lr4 + i * 64; \
        int ga = rowBase + r; if (ga >= M) ga = M - 1; \
        uint32_t so = (buf) * 10240 + r * SSTRB + lq4 * 16; \
        CP_ASYNC16(sb + OFF_AHI + so, Ahi + (size_t)ga * S + k0 + lq4 * 8); \
        CP_ASYNC16(sb + OFF_ALO + so, Alo + (size_t)ga * S + k0 + lq4 * 8); \
        CP_ASYNC16(sb + OFF_WHI + so, W + (size_t)r * W2S + k0 + lq4 * 8); \
        CP_ASYNC16(sb + OFF_WLO + so, W + (size_t)r * W2S + S + k0 + lq4 * 8); \
    } } while (0)

    LOAD_CHUNK(0, 0); CP_COMMIT();
    if (NC > 1) { LOAD_CHUNK(1, 1); }
    CP_COMMIT();

    const int a_row = lane & 15;
    const int a_sel = (lane >> 4) & 1;
    const int b_row = (lane & 7) + ((lane & 16) >> 1);
    const int b_sel = (lane >> 3) & 1;

    auto do_pass = [&](uint32_t abase, uint32_t wbase) {
#pragma unroll
        for (int kh = 0; kh < 2; kh++) {
            uint32_t ar[2][4], br[8][2];
#pragma unroll
            for (int mi = 0; mi < 2; mi++) {
                uint32_t addr = abase + (mQ * 32 + mi * 16 + a_row) * SSTRB
                                + kh * 32 + a_sel * 16;
                LDMX4(ar[mi][0], ar[mi][1], ar[mi][2], ar[mi][3], addr);
            }
#pragma unroll
            for (int pi = 0; pi < 4; pi++) {
                uint32_t addr = wbase + (nH * 64 + pi * 16 + b_row) * SSTRB
                                + kh * 32 + b_sel * 16;
                LDMX4(br[2 * pi][0], br[2 * pi][1],
                      br[2 * pi + 1][0], br[2 * pi + 1][1], addr);
            }
#pragma unroll
            for (int mi = 0; mi < 2; mi++)
#pragma unroll
                for (int ni = 0; ni < 8; ni++)
                    MMA_BF16(acc[mi][ni], ar[mi], br[ni]);
        }
    };

    for (int c = 0; c < NC; c++) {
        CP_WAIT1();
        __syncthreads();
        uint32_t bo = (uint32_t)(c & 1) * 10240;
        do_pass(sb + OFF_AHI + bo, sb + OFF_WHI + bo);
        do_pass(sb + OFF_ALO + bo, sb + OFF_WHI + bo);
        do_pass(sb + OFF_AHI + bo, sb + OFF_WLO + bo);
        __syncthreads();
        if (c + 2 < NC) LOAD_CHUNK(c + 2, c & 1);
        CP_COMMIT();
    }
#undef LOAD_CHUNK

    const int g = lane >> 2, t = lane & 3;
#pragma unroll
    for (int mi = 0; mi < 2; mi++) {
        int r0 = rowBase + mQ * 32 + mi * 16 + g;
#pragma unroll
        for (int ni = 0; ni < 8; ni++) {
            int col = nH * 64 + ni * 8 + t * 2;
            float bx = 0.f, by2 = 0.f;
            if (bias) { bx = bias[col]; by2 = bias[col + 1]; }
            if (r0 < M) {
                float2 v = make_float2(acc[mi][ni][0] + bx, acc[mi][ni][1] + by2);
                *(float2*)(C + (size_t)r0 * 128 + col) = v;
            }
            if (r0 + 8 < M) {
                float2 v = make_float2(acc[mi][ni][2] + bx, acc[mi][ni][3] + by2);
                *(float2*)(C + (size_t)(r0 + 8) * 128 + col) = v;
            }
        }
    }
}

// ---------------------------------------------------------------------------
// Splits
// ---------------------------------------------------------------------------
// features -> single fp16 plane (pads zeroed); block per row, 4 cols/thread
__global__ void splitA_fp16(const float* __restrict__ in,
                            __half* __restrict__ outA, int K, int S)
{
    int row = blockIdx.x;
    int k = threadIdx.x * 4;
    if (k >= S) return;
    const float* src = in + (size_t)row * K;
    __half h[4];
#pragma unroll
    for (int j = 0; j < 4; j++) {
        int kk = k + j;
        h[j] = __float2half((kk < K) ? src[kk] : 0.f);
    }
    *(uint2*)(outA + (size_t)row * S + k) = *(uint2*)h;
}

// W -> fp16 rows [hi(S)|lo(S)]
__global__ void splitW_fp16(const float* __restrict__ in, __half* __restrict__ out,
                            int K, int S)
{
    int row = blockIdx.x;
    const float* src = in + (size_t)row * K;
    __half* d = out + (size_t)row * (2 * S);
    for (int k = threadIdx.x; k < S; k += blockDim.x) {
        __half hi = __float2half(0.f), lo = hi;
        if (k < K) {
            float v = src[k];
            hi = __float2half(v);
            lo = __float2half(v - __half2float(hi));
        }
        d[k] = hi;
        d[S + k] = lo;
    }
}

// h1 -> bf16 hi/lo planes with relu (layer 2, proven path)
__global__ void splitA_h1(const float* __restrict__ in,
                          __nv_bfloat16* __restrict__ outHi,
                          __nv_bfloat16* __restrict__ outLo, int M)
{
    int w = (blockIdx.x * blockDim.x + threadIdx.x) >> 5;
    int lane = threadIdx.x & 31;
    if (w >= M) return;
    size_t o = (size_t)w * 128 + lane * 4;
    float4 v = *(const float4*)(in + o);
    float vv[4] = {fmaxf(v.x, 0.f), fmaxf(v.y, 0.f), fmaxf(v.z, 0.f), fmaxf(v.w, 0.f)};
    __nv_bfloat16 h[4], l[4];
#pragma unroll
    for (int j = 0; j < 4; j++) {
        h[j] = __float2bfloat16(vv[j]);
        l[j] = __float2bfloat16(vv[j] - __bfloat162float(h[j]));
    }
    *(uint2*)(outHi + o) = *(uint2*)h;
    *(uint2*)(outLo + o) = *(uint2*)l;
}

__global__ void split2_W(const float* __restrict__ in, __nv_bfloat16* __restrict__ out,
                         int K, int S)
{
    int row = blockIdx.x;
    const float* src = in + (size_t)row * K;
    __nv_bfloat16* d = out + (size_t)row * (2 * S);
    for (int k = threadIdx.x; k < S; k += blockDim.x) {
        __nv_bfloat16 hi = __float2bfloat16(0.f), lo = hi;
        if (k < K) {
            float v = src[k];
            hi = __float2bfloat16(v);
            lo = __float2bfloat16(v - __bfloat162float(hi));
        }
        d[k] = hi;
        d[S + k] = lo;
    }
}

// ---------------------------------------------------------------------------
// CSR build
// ---------------------------------------------------------------------------
struct EdgePtrs { const int* e[5]; };

__global__ void count5_k(EdgePtrs ep, int* __restrict__ cnt, int E)
{
    int i = blockIdx.y;
    int e = blockIdx.x * blockDim.x + threadIdx.x;
    if (e < E) atomicAdd(&cnt[i * 100000 + ep.e[i][E + e]], 1);
}

__constant__ int c_dstN[5] = {100000, 50000, 50000, 50000, 100000};

__global__ void scan5_k(const int* __restrict__ cnt, int* __restrict__ off)
{
    __shared__ int sh[32];
    __shared__ int carry;
    int type = blockIdx.x;
    const int n = c_dstN[type];
    const int* c = cnt + type * 100000;
    int* o = off + type * 100032;
    int tid = threadIdx.x, lane = tid & 31, w = tid >> 5;
    if (tid == 0) carry = 0;
    __syncthreads();
    for (int base = 0; base < n; base += 1024) {
        int i = base + tid;
        int v = (i < n) ? c[i] : 0;
        int x = v;
#pragma unroll
        for (int d = 1; d < 32; d <<= 1) {
            int y = __shfl_up_sync(0xffffffffu, x, d);
            if (lane >= d) x += y;
        }
        if (lane == 31) sh[w] = x;
        __syncthreads();
        if (w == 0) {
            int s = sh[lane];
#pragma unroll
            for (int d = 1; d < 32; d <<= 1) {
                int y = __shfl_up_sync(0xffffffffu, s, d);
                if (lane >= d) s += y;
            }
            sh[lane] = s;
        }
        __syncthreads();
        int excl = x - v + (w > 0 ? sh[w - 1] : 0) + carry;
        if (i < n) o[i] = excl;
        __syncthreads();
        if (tid == 1023) carry = excl + v;
        __syncthreads();
    }
    if (tid == 0) o[n] = carry;
}

__global__ void fill5_k(EdgePtrs ep, const int* __restrict__ off, int* __restrict__ cursor,
                        int* __restrict__ srcA, int E)
{
    int i = blockIdx.y;
    int e = blockIdx.x * blockDim.x + threadIdx.x;
    if (e >= E) return;
    int d = ep.e[i][E + e];
    int pos = atomicAdd(&cursor[i * 100000 + d], 1);
    srcA[i * 200000 + off[i * 100032 + d] + pos] = ep.e[i][e];
}

// ---------------------------------------------------------------------------
// Fused gather + mean + lin_l + L2-normalize + sum over <=2 edge types
// ---------------------------------------------------------------------------
template<bool RELU, bool TWO>
__global__ void combine2(
    const float* __restrict__ B0, const float* __restrict__ P0,
    const int* __restrict__ off0, const int* __restrict__ src0,
    const float* __restrict__ B1, const float* __restrict__ P1,
    const int* __restrict__ off1, const int* __restrict__ src1,
    float* __restrict__ out, int n)
{
    int w = (blockIdx.x * blockDim.x + threadIdx.x) >> 5;
    int lane = threadIdx.x & 31;
    if (w >= n) return;
    size_t o = (size_t)w * HIDD + lane * 4;
    float4 r = make_float4(0.f, 0.f, 0.f, 0.f);

    {
        float4 b = *(const float4*)(B0 + o);
        int beg = __ldg(off0 + w), end = __ldg(off0 + w + 1);
        float4 a = make_float4(0.f, 0.f, 0.f, 0.f);
        for (int e = beg; e < end; e++) {
            int s = __ldg(src0 + e);
            float4 p = *(const float4*)(P0 + (size_t)s * HIDD + lane * 4);
            a.x += p.x; a.y += p.y; a.z += p.z; a.w += p.w;
        }
        float inv = 1.0f / fmaxf((float)(end - beg), 1.0f);
        float4 t;
        t.x = b.x + a.x * inv; t.y = b.y + a.y * inv;
        t.z = b.z + a.z * inv; t.w = b.w + a.w * inv;
        float ss = t.x * t.x + t.y * t.y + t.z * t.z + t.w * t.w;
#pragma unroll
        for (int sh = 16; sh; sh >>= 1) ss += __shfl_xor_sync(0xffffffffu, ss, sh);
        float sc = 1.0f / fmaxf(sqrtf(ss), 1e-12f);
        r.x += t.x * sc; r.y += t.y * sc; r.z += t.z * sc; r.w += t.w * sc;
    }
    if (TWO) {
        float4 b = *(const float4*)(B1 + o);
        int beg = __ldg(off1 + w), end = __ldg(off1 + w + 1);
        float4 a = make_float4(0.f, 0.f, 0.f, 0.f);
        for (int e = beg; e < end; e++) {
            int s = __ldg(src1 + e);
            float4 p = *(const float4*)(P1 + (size_t)s * HIDD + lane * 4);
            a.x += p.x; a.y += p.y; a.z += p.z; a.w += p.w;
        }
        float inv = 1.0f / fmaxf((float)(end - beg), 1.0f);
        float4 t;
        t.x = b.x + a.x * inv; t.y = b.y + a.y * inv;
        t.z = b.z + a.z * inv; t.w = b.w + a.w * inv;
        float ss = t.x * t.x + t.y * t.y + t.z * t.z + t.w * t.w;
#pragma unroll
        for (int sh = 16; sh; sh >>= 1) ss += __shfl_xor_sync(0xffffffffu, ss, sh);
        float sc = 1.0f / fmaxf(sqrtf(ss), 1e-12f);
        r.x += t.x * sc; r.y += t.y * sc; r.z += t.z * sc; r.w += t.w * sc;
    }
    if (RELU) {
        r.x = fmaxf(r.x, 0.f); r.y = fmaxf(r.y, 0.f);
        r.z = fmaxf(r.z, 0.f); r.w = fmaxf(r.w, 0.f);
    }
    *(float4*)(out + o) = r;
}

// ---------------------------------------------------------------------------
// SIMT GEMM for the 64-wide head
// ---------------------------------------------------------------------------
template<bool RELU_OUT>
__global__ __launch_bounds__(256) void gemm_tn(
    const float* __restrict__ A, const float* __restrict__ W,
    const float* __restrict__ bias, float* __restrict__ C,
    int M, int N, int K)
{
    __shared__ float As[8][128];
    __shared__ float Ws[8][128];
    const int tid = threadIdx.x;
    const int tx = tid & 15, ty = tid >> 4;
    const int rowBase = blockIdx.y * 128;

    float acc[8][8];
#pragma unroll
    for (int i = 0; i < 8; i++)
#pragma unroll
        for (int j = 0; j < 8; j++) acc[i][j] = 0.f;

    for (int k0 = 0; k0 < K; k0 += 8) {
#pragma unroll
        for (int t = 0; t < 4; t++) {
            int idx = tid + t * 256;
            int k = idx & 7, r = idx >> 3;
            int row = rowBase + r, kk = k0 + k;
            float v = 0.f;
            if (row < M && kk < K) v = A[(size_t)row * K + kk];
            As[k][r] = v;
        }
#pragma unroll
        for (int t = 0; t < 4; t++) {
            int idx = tid + t * 256;
            int k = idx & 7, c = idx >> 3;
            int kk = k0 + k;
            float v = 0.f;
            if (c < N && kk < K) v = W[(size_t)c * K + kk];
            Ws[k][c] = v;
        }
        __syncthreads();
#pragma unroll
        for (int k = 0; k < 8; k++) {
            float4 a0 = *(const float4*)&As[k][ty * 8];
            float4 a1 = *(const float4*)&As[k][ty * 8 + 4];
            float4 b0 = *(const float4*)&Ws[k][tx * 8];
            float4 b1 = *(const float4*)&Ws[k][tx * 8 + 4];
            float av[8] = {a0.x, a0.y, a0.z, a0.w, a1.x, a1.y, a1.z, a1.w};
            float bv[8] = {b0.x, b0.y, b0.z, b0.w, b1.x, b1.y, b1.z, b1.w};
#pragma unroll
            for (int i = 0; i < 8; i++)
#pragma unroll
                for (int j = 0; j < 8; j++) acc[i][j] += av[i] * bv[j];
        }
        __syncthreads();
    }

#pragma unroll
    for (int i = 0; i < 8; i++) {
        int row = rowBase + ty * 8 + i;
        if (row < M) {
#pragma unroll
            for (int j = 0; j < 8; j++) {
                int col = tx * 8 + j;
                if (col < N) {
                    float v = acc[i][j] + bias[col];
                    if (RELU_OUT) v = fmaxf(v, 0.f);
                    C[(size_t)row * N + col] = v;
                }
            }
        }
    }
}

__global__ void head2_k(const float* __restrict__ Z, const float* __restrict__ W2,
                        const float* __restrict__ b2, float* __restrict__ out, int n)
{
    int row = blockIdx.x * blockDim.x + threadIdx.x;
    if (row >= n) return;
    float acc0 = b2[0], acc1 = b2[1];
    const float* z = Z + (size_t)row * 64;
#pragma unroll
    for (int k = 0; k < 64; k++) {
        float zv = z[k];
        acc0 += zv * __ldg(W2 + k);
        acc1 += zv * __ldg(W2 + 64 + k);
    }
    out[row * 2 + 0] = acc0;
    out[row * 2 + 1] = acc1;
}

// ---------------------------------------------------------------------------
extern "C" void kernel_launch(void* const* d_in, const int* in_sizes, int n_in,
                              void* d_out_, int out_size)
{
    const float* x[3] = {(const float*)d_in[0], (const float*)d_in[1], (const float*)d_in[2]};
    const int nn[3] = {N_ART, N_ENT, N_FACT};
    const int* ei[5];
    for (int i = 0; i < 5; i++) ei[i] = (const int*)d_in[3 + i];
    const float* c1llw = (const float*)d_in[8];
    const float* c1llb = (const float*)d_in[9];
    const float* c1lrw = (const float*)d_in[10];
    const float* c2llw = (const float*)d_in[11];
    const float* c2llb = (const float*)d_in[12];
    const float* c2lrw = (const float*)d_in[13];
    const float* hw1 = (const float*)d_in[14];
    const float* hb1 = (const float*)d_in[15];
    const float* hw2 = (const float*)d_in[16];
    const float* hb2 = (const float*)d_in[17];
    float* out = (float*)d_out_;

    static const size_t BOFF[5] = {0, 100000, 150000, 200000, 250000};
    static const size_t POFF[5] = {0, 50000, 100000, 200000, 300000};
    const size_t WB1 = (size_t)128 * 2 * K1S;
    const size_t WB2 = (size_t)128 * 2 * K2S;

    float *B5, *P5, *H1, *Z;
    __half *Xh, *W1L, *W1R;
    __nv_bfloat16 *H1s, *W2L, *W2R;
    int *CUR, *OFFS, *SRCA;
    cudaGetSymbolAddress((void**)&B5, g_B5);
    cudaGetSymbolAddress((void**)&P5, g_P5);
    cudaGetSymbolAddress((void**)&H1, g_h1);
    cudaGetSymbolAddress((void**)&Z, g_z);
    cudaGetSymbolAddress((void**)&Xh, g_Xh);
    cudaGetSymbolAddress((void**)&H1s, g_H1s);
    cudaGetSymbolAddress((void**)&W1L, g_W1L);
    cudaGetSymbolAddress((void**)&W1R, g_W1R);
    cudaGetSymbolAddress((void**)&W2L, g_W2L);
    cudaGetSymbolAddress((void**)&W2R, g_W2R);
    cudaGetSymbolAddress((void**)&CUR, g_cursor);
    cudaGetSymbolAddress((void**)&OFFS, g_off);
    cudaGetSymbolAddress((void**)&SRCA, g_srcA);

    cudaFuncSetAttribute(gemm_mma_multi, cudaFuncAttributeMaxDynamicSharedMemorySize, SMEM_TOT);
    cudaFuncSetAttribute(gemm_fp16_multi, cudaFuncAttributeMaxDynamicSharedMemorySize, SMEM_FP16);

    const size_t XHB[3] = {0, (size_t)N_ART * K1S, (size_t)(N_ART + N_ENT) * K1S};
    const size_t H1SLO = (size_t)200000 * K2S;
    const size_t R0[3] = {0, (size_t)N_ART, (size_t)(N_ART + N_ENT)};

    float* h1p[3] = {H1, H1 + (size_t)N_ART * HIDD, H1 + (size_t)(N_ART + N_ENT) * HIDD};
    float* h2p[3] = {out + 100000,
                     out + 100000 + (size_t)N_ART * HIDD,
                     out + 100000 + (size_t)(N_ART + N_ENT) * HIDD};

    const int NBLK[3] = {3, 4, 3};
    const int LLe[3][2] = {{2, -1}, {0, 4}, {1, 3}};
    const int LRe[3][2] = {{0, 1}, {2, 3}, {4, -1}};

    auto make_outs = [&](int layer, int t) {
        MultiOut p;
        const void* WL = layer ? (const void*)W2L : (const void*)W1L;
        const void* WR = layer ? (const void*)W2R : (const void*)W1R;
        const float* bb = layer ? c2llb : c1llb;
        const size_t WB = layer ? WB2 : WB1;
        int nb = 0;
        for (int j = 0; j < 2; j++) {
            int e = LLe[t][j];
            if (e < 0) break;
            p.W[nb] = (const char*)WL + (size_t)e * WB * 2;  // elems*2 bytes
            p.bias[nb] = bb + e * HIDD;
            p.C[nb] = B5 + BOFF[e] * HIDD;
            nb++;
        }
        for (int j = 0; j < 2; j++) {
            int e = LRe[t][j];
            if (e < 0) break;
            p.W[nb] = (const char*)WR + (size_t)e * WB * 2;
            p.bias[nb] = nullptr;
            p.C[nb] = P5 + POFF[e] * HIDD;
            nb++;
        }
        return p;
    };

    // --- splits: features (fp16) + W1 (fp16) ---
    for (int t = 0; t < 3; t++)
        splitA_fp16<<<nn[t], 256>>>(x[t], Xh + XHB[t], FEATD, K1S);
    splitW_fp16<<<640, 256>>>(c1llw, W1L, FEATD, K1S);
    splitW_fp16<<<640, 256>>>(c1lrw, W1R, FEATD, K1S);

    // --- layer-1 GEMMs (fp16 2-pass) ---
    for (int t = 1; t >= 0; t--) {  // ent first (biggest), then art
        MultiOut p = make_outs(0, t);
        gemm_fp16_multi<<<dim3(NBLK[t], (nn[t] + 127) / 128), 256, SMEM_FP16>>>(
            Xh + XHB[t], p, nn[t], K1S);
    }
    {
        MultiOut p = make_outs(0, 2);
        gemm_fp16_multi<<<dim3(NBLK[2], (nn[2] + 127) / 128), 256, SMEM_FP16>>>(
            Xh + XHB[2], p, nn[2], K1S);
    }

    // --- CSR build + W2 splits ---
    EdgePtrs ep;
    for (int i = 0; i < 5; i++) ep.e[i] = ei[i];
    cudaMemsetAsync(CUR, 0, 500000 * sizeof(int));
    count5_k<<<dim3((NEDGE + 255) / 256, 5), 256>>>(ep, CUR, NEDGE);
    scan5_k<<<5, 1024>>>(CUR, OFFS);
    cudaMemsetAsync(CUR, 0, 500000 * sizeof(int));
    fill5_k<<<dim3((NEDGE + 255) / 256, 5), 256>>>(ep, OFFS, CUR, SRCA, NEDGE);
    split2_W<<<640, 128>>>(c2llw, W2L, HIDD, K2S);
    split2_W<<<640, 128>>>(c2lrw, W2R, HIDD, K2S);

    // --- layer-1 combines ---
    combine2<false, false><<<(N_ART + 7) / 8, 256>>>(
        B5 + BOFF[2] * HIDD, P5 + POFF[2] * HIDD, OFFS + 2 * 100032, SRCA + 2 * 200000,
        nullptr, nullptr, nullptr, nullptr, h1p[0], N_ART);
    combine2<false, true><<<(N_ENT + 7) / 8, 256>>>(
        B5 + BOFF[0] * HIDD, P5 + POFF[0] * HIDD, OFFS + 0 * 100032, SRCA + 0 * 200000,
        B5 + BOFF[4] * HIDD, P5 + POFF[4] * HIDD, OFFS + 4 * 100032, SRCA + 4 * 200000,
        h1p[1], N_ENT);
    combine2<false, true><<<(N_FACT + 7) / 8, 256>>>(
        B5 + BOFF[1] * HIDD, P5 + POFF[1] * HIDD, OFFS + 1 * 100032, SRCA + 1 * 200000,
        B5 + BOFF[3] * HIDD, P5 + POFF[3] * HIDD, OFFS + 3 * 100032, SRCA + 3 * 200000,
        h1p[2], N_FACT);

    // --- relu + split h1 (bf16 hi/lo) ---
    splitA_h1<<<(200000 + 7) / 8, 256>>>(H1, H1s, H1s + H1SLO, 200000);

    // --- layer-2 GEMMs (bf16 3-pass) ---
    for (int t = 1; t >= 0; t--) {
        MultiOut p = make_outs(1, t);
        gemm_mma_multi<<<dim3(NBLK[t], (nn[t] + 127) / 128), 256, SMEM_TOT>>>(
            H1s + R0[t] * K2S, H1s + H1SLO + R0[t] * K2S, p, nn[t], K2S);
    }
    {
        MultiOut p = make_outs(1, 2);
        gemm_mma_multi<<<dim3(NBLK[2], (nn[2] + 127) / 128), 256, SMEM_TOT>>>(
            H1s + R0[2] * K2S, H1s + H1SLO + R0[2] * K2S, p, nn[2], K2S);
    }

    // --- layer-2 combines (relu fused) ---
    combine2<true, false><<<(N_ART + 7) / 8, 256>>>(
        B5 + BOFF[2] * HIDD, P5 + POFF[2] * HIDD, OFFS + 2 * 100032, SRCA + 2 * 200000,
        nullptr, nullptr, nullptr, nullptr, h2p[0], N_ART);
    combine2<true, true><<<(N_ENT + 7) / 8, 256>>>(
        B5 + BOFF[0] * HIDD, P5 + POFF[0] * HIDD, OFFS + 0 * 100032, SRCA + 0 * 200000,
        B5 + BOFF[4] * HIDD, P5 + POFF[4] * HIDD, OFFS + 4 * 100032, SRCA + 4 * 200000,
        h2p[1], N_ENT);
    combine2<true, true><<<(N_FACT + 7) / 8, 256>>>(
        B5 + BOFF[1] * HIDD, P5 + POFF[1] * HIDD, OFFS + 1 * 100032, SRCA + 1 * 200000,
        B5 + BOFF[3] * HIDD, P5 + POFF[3] * HIDD, OFFS + 3 * 100032, SRCA + 3 * 200000,
        h2p[2], N_FACT);

    // --- head MLP ---
    gemm_tn<true><<<dim3(1, (N_ART + 127) / 128), 256>>>(
        out + 100000, hw1, hb1, Z, N_ART, 64, HIDD);
    head2_k<<<(N_ART + 255) / 256, 256>>>(Z, hw2, hb2, out, N_ART);
}

// round 11
// speedup vs baseline: 5.9474x; 1.4259x over previous
#include <cuda_runtime.h>
#include <cuda_fp16.h>
#include <math.h>
#include <stdint.h>

#define N_ART 50000
#define N_ENT 100000
#define N_FACT 50000
#define NEDGE 200000
#define FEATD 769
#define HIDD 128

#define K1S 800
#define K2S 128

// ---------------------------------------------------------------------------
// Scratch
// ---------------------------------------------------------------------------
__device__ float g_B5[44800000];                // 5 lin_l outputs (dst rows)
__device__ float g_P5[44800000];                // 5 lin_r outputs (src rows)
__device__ float g_h1[25600000];
__device__ float g_z[3200000];
__device__ __half g_Xh[160000000];              // fp16 features: 200k x 800
__device__ __half g_H1h[25600000];              // fp16 relu(h1): 200k x 128
__device__ __half g_W1L[512000];                // c1 lin_l fp16: 640 x 800
__device__ __half g_W1R[512000];
__device__ __half g_W2L[163840];                // c2 fp16 rows [hi(128)|lo(128)]
__device__ __half g_W2R[163840];
__device__ int g_cursor[500000];
__device__ int g_off[500160];                   // per-type CSR offsets (stride 100032)
__device__ int g_srcA[1000000];                 // per-type CSR src lists (stride 200000)

// ---------------------------------------------------------------------------
__device__ __forceinline__ uint32_t smem_u32(const void* p) {
    uint32_t a;
    asm("{ .reg .u64 t; cvta.to.shared.u64 t, %1; cvt.u32.u64 %0, t; }"
        : "=r"(a) : "l"(p));
    return a;
}

#define CP_ASYNC16(dst, src) \
    asm volatile("cp.async.cg.shared.global [%0], [%1], 16;" :: "r"(dst), "l"(src))
#define CP_COMMIT() asm volatile("cp.async.commit_group;" ::: "memory")
#define CP_WAIT1()  asm volatile("cp.async.wait_group 1;" ::: "memory")

#define SSTRB 80

struct MultiOut {
    const void* W[4];
    const float* bias[4];
    float* C[4];
};

#define LDMX4(r0, r1, r2, r3, addr) \
    asm volatile("ldmatrix.sync.aligned.m8n8.x4.shared.b16 {%0,%1,%2,%3}, [%4];" \
                 : "=r"(r0), "=r"(r1), "=r"(r2), "=r"(r3) : "r"(addr))

#define MMA_FP16(acc, a, b) \
    asm volatile("mma.sync.aligned.m16n8k16.row.col.f32.f16.f16.f32 " \
                 "{%0,%1,%2,%3}, {%4,%5,%6,%7}, {%8,%9}, {%0,%1,%2,%3};" \
                 : "+f"((acc)[0]), "+f"((acc)[1]), "+f"((acc)[2]), "+f"((acc)[3]) \
                 : "r"((a)[0]), "r"((a)[1]), "r"((a)[2]), "r"((a)[3]), \
                   "r"((b)[0]), "r"((b)[1]))

// ---------------------------------------------------------------------------
// Layer-1 GEMM: plain fp16 single-pass. A[M,S], W[128,S] (row stride S).
// grid = (NBLK, ceil(M/128)), 256 threads, K-chunk 32, double-buffered.
// ---------------------------------------------------------------------------
#define P1_OFF_A 0
#define P1_OFF_W 20480
#define SMEM_1P  40960

__global__ __launch_bounds__(256) void gemm_fp16_1p(
    const __half* __restrict__ A, MultiOut p, int M, int S)
{
    extern __shared__ char sm[];
    const uint32_t sb = smem_u32(sm);
    const int tid = threadIdx.x, lane = tid & 31, warp = tid >> 5;
    const int mQ = warp >> 1, nH = warp & 1;
    const int rowBase = blockIdx.y * 128;
    const __half* __restrict__ W = (const __half*)p.W[blockIdx.x];
    const float* __restrict__ bias = p.bias[blockIdx.x];
    float* __restrict__ C = p.C[blockIdx.x];
    const int NC = S >> 5;

    float acc[2][8][4];
#pragma unroll
    for (int i = 0; i < 2; i++)
#pragma unroll
        for (int j = 0; j < 8; j++)
#pragma unroll
            for (int q = 0; q < 4; q++) acc[i][j][q] = 0.f;

    const int lr4 = tid >> 2, lq4 = tid & 3;

#define LOAD1(c, buf) do { \
    int k0 = (c) * 32; \
    _Pragma("unroll") \
    for (int i = 0; i < 2; i++) { \
        int r = lr4 + i * 64; \
        int ga = rowBase + r; if (ga >= M) ga = M - 1; \
        uint32_t so = (buf) * 10240 + r * SSTRB + lq4 * 16; \
        CP_ASYNC16(sb + P1_OFF_A + so, A + (size_t)ga * S + k0 + lq4 * 8); \
        CP_ASYNC16(sb + P1_OFF_W + so, W + (size_t)r * S + k0 + lq4 * 8); \
    } } while (0)

    LOAD1(0, 0); CP_COMMIT();
    if (NC > 1) { LOAD1(1, 1); }
    CP_COMMIT();

    const int a_row = lane & 15;
    const int a_sel = (lane >> 4) & 1;
    const int b_row = (lane & 7) + ((lane & 16) >> 1);
    const int b_sel = (lane >> 3) & 1;

    for (int c = 0; c < NC; c++) {
        CP_WAIT1();
        __syncthreads();
        uint32_t bo = (uint32_t)(c & 1) * 10240;
        uint32_t abase = sb + P1_OFF_A + bo;
        uint32_t wbase = sb + P1_OFF_W + bo;
#pragma unroll
        for (int kh = 0; kh < 2; kh++) {
            uint32_t ar[2][4], br[8][2];
#pragma unroll
            for (int mi = 0; mi < 2; mi++) {
                uint32_t addr = abase + (mQ * 32 + mi * 16 + a_row) * SSTRB
                                + kh * 32 + a_sel * 16;
                LDMX4(ar[mi][0], ar[mi][1], ar[mi][2], ar[mi][3], addr);
            }
#pragma unroll
            for (int pi = 0; pi < 4; pi++) {
                uint32_t addr = wbase + (nH * 64 + pi * 16 + b_row) * SSTRB
                                + kh * 32 + b_sel * 16;
                LDMX4(br[2 * pi][0], br[2 * pi][1],
                      br[2 * pi + 1][0], br[2 * pi + 1][1], addr);
            }
#pragma unroll
            for (int mi = 0; mi < 2; mi++)
#pragma unroll
                for (int ni = 0; ni < 8; ni++)
                    MMA_FP16(acc[mi][ni], ar[mi], br[ni]);
        }
        __syncthreads();
        if (c + 2 < NC) LOAD1(c + 2, c & 1);
        CP_COMMIT();
    }
#undef LOAD1

    const int g = lane >> 2, t = lane & 3;
#pragma unroll
    for (int mi = 0; mi < 2; mi++) {
        int r0 = rowBase + mQ * 32 + mi * 16 + g;
#pragma unroll
        for (int ni = 0; ni < 8; ni++) {
            int col = nH * 64 + ni * 8 + t * 2;
            float bx = 0.f, by2 = 0.f;
            if (bias) { bx = bias[col]; by2 = bias[col + 1]; }
            if (r0 < M) {
                float2 v = make_float2(acc[mi][ni][0] + bx, acc[mi][ni][1] + by2);
                *(float2*)(C + (size_t)r0 * 128 + col) = v;
            }
            if (r0 + 8 < M) {
                float2 v = make_float2(acc[mi][ni][2] + bx, acc[mi][ni][3] + by2);
                *(float2*)(C + (size_t)(r0 + 8) * 128 + col) = v;
            }
        }
    }
}

// ---------------------------------------------------------------------------
// Layer-2 GEMM: fp16 2-pass. A[M,S] single plane; W rows [hi(S)|lo(S)].
// ---------------------------------------------------------------------------
#define F_OFF_A   0
#define F_OFF_WHI 20480
#define F_OFF_WLO 40960
#define SMEM_FP16 61440

__global__ __launch_bounds__(256) void gemm_fp16_multi(
    const __half* __restrict__ A, MultiOut p, int M, int S)
{
    extern __shared__ char sm[];
    const uint32_t sb = smem_u32(sm);
    const int tid = threadIdx.x, lane = tid & 31, warp = tid >> 5;
    const int mQ = warp >> 1, nH = warp & 1;
    const int rowBase = blockIdx.y * 128;
    const __half* __restrict__ W = (const __half*)p.W[blockIdx.x];
    const float* __restrict__ bias = p.bias[blockIdx.x];
    float* __restrict__ C = p.C[blockIdx.x];
    const int NC = S >> 5;
    const int W2S = 2 * S;

    float acc[2][8][4];
#pragma unroll
    for (int i = 0; i < 2; i++)
#pragma unroll
        for (int j = 0; j < 8; j++)
#pragma unroll
            for (int q = 0; q < 4; q++) acc[i][j][q] = 0.f;

    const int lr4 = tid >> 2, lq4 = tid & 3;

#define FLOAD(c, buf) do { \
    int k0 = (c) * 32; \
    _Pragma("unroll") \
    for (int i = 0; i < 2; i++) { \
        int r = lr4 + i * 64; \
        int ga = rowBase + r; if (ga >= M) ga = M - 1; \
        uint32_t so = (buf) * 10240 + r * SSTRB + lq4 * 16; \
        CP_ASYNC16(sb + F_OFF_A + so, A + (size_t)ga * S + k0 + lq4 * 8); \
        CP_ASYNC16(sb + F_OFF_WHI + so, W + (size_t)r * W2S + k0 + lq4 * 8); \
        CP_ASYNC16(sb + F_OFF_WLO + so, W + (size_t)r * W2S + S + k0 + lq4 * 8); \
    } } while (0)

    FLOAD(0, 0); CP_COMMIT();
    if (NC > 1) { FLOAD(1, 1); }
    CP_COMMIT();

    const int a_row = lane & 15;
    const int a_sel = (lane >> 4) & 1;
    const int b_row = (lane & 7) + ((lane & 16) >> 1);
    const int b_sel = (lane >> 3) & 1;

    auto do_pass = [&](uint32_t abase, uint32_t wbase) {
#pragma unroll
        for (int kh = 0; kh < 2; kh++) {
            uint32_t ar[2][4], br[8][2];
#pragma unroll
            for (int mi = 0; mi < 2; mi++) {
                uint32_t addr = abase + (mQ * 32 + mi * 16 + a_row) * SSTRB
                                + kh * 32 + a_sel * 16;
                LDMX4(ar[mi][0], ar[mi][1], ar[mi][2], ar[mi][3], addr);
            }
#pragma unroll
            for (int pi = 0; pi < 4; pi++) {
                uint32_t addr = wbase + (nH * 64 + pi * 16 + b_row) * SSTRB
                                + kh * 32 + b_sel * 16;
                LDMX4(br[2 * pi][0], br[2 * pi][1],
                      br[2 * pi + 1][0], br[2 * pi + 1][1], addr);
            }
#pragma unroll
            for (int mi = 0; mi < 2; mi++)
#pragma unroll
                for (int ni = 0; ni < 8; ni++)
                    MMA_FP16(acc[mi][ni], ar[mi], br[ni]);
        }
    };

    for (int c = 0; c < NC; c++) {
        CP_WAIT1();
        __syncthreads();
        uint32_t bo = (uint32_t)(c & 1) * 10240;
        do_pass(sb + F_OFF_A + bo, sb + F_OFF_WHI + bo);
        do_pass(sb + F_OFF_A + bo, sb + F_OFF_WLO + bo);
        __syncthreads();
        if (c + 2 < NC) FLOAD(c + 2, c & 1);
        CP_COMMIT();
    }
#undef FLOAD

    const int g = lane >> 2, t = lane & 3;
#pragma unroll
    for (int mi = 0; mi < 2; mi++) {
        int r0 = rowBase + mQ * 32 + mi * 16 + g;
#pragma unroll
        for (int ni = 0; ni < 8; ni++) {
            int col = nH * 64 + ni * 8 + t * 2;
            float bx = 0.f, by2 = 0.f;
            if (bias) { bx = bias[col]; by2 = bias[col + 1]; }
            if (r0 < M) {
                float2 v = make_float2(acc[mi][ni][0] + bx, acc[mi][ni][1] + by2);
                *(float2*)(C + (size_t)r0 * 128 + col) = v;
            }
            if (r0 + 8 < M) {
                float2 v = make_float2(acc[mi][ni][2] + bx, acc[mi][ni][3] + by2);
                *(float2*)(C + (size_t)(r0 + 8) * 128 + col) = v;
            }
        }
    }
}

// ---------------------------------------------------------------------------
// Splits / converts
// ---------------------------------------------------------------------------
// fp32 [rows x K] -> fp16 [rows x S], pads zeroed; block per row, 4 cols/thread
__global__ void conv_fp16(const float* __restrict__ in,
                          __half* __restrict__ outA, int K, int S)
{
    int row = blockIdx.x;
    int k = threadIdx.x * 4;
    if (k >= S) return;
    const float* src = in + (size_t)row * K;
    __half h[4];
#pragma unroll
    for (int j = 0; j < 4; j++) {
        int kk = k + j;
        h[j] = __float2half((kk < K) ? src[kk] : 0.f);
    }
    *(uint2*)(outA + (size_t)row * S + k) = *(uint2*)h;
}

// W -> fp16 rows [hi(S)|lo(S)] (layer 2)
__global__ void splitW_fp16(const float* __restrict__ in, __half* __restrict__ out,
                            int K, int S)
{
    int row = blockIdx.x;
    const float* src = in + (size_t)row * K;
    __half* d = out + (size_t)row * (2 * S);
    for (int k = threadIdx.x; k < S; k += blockDim.x) {
        __half hi = __float2half(0.f), lo = hi;
        if (k < K) {
            float v = src[k];
            hi = __float2half(v);
            lo = __float2half(v - __half2float(hi));
        }
        d[k] = hi;
        d[S + k] = lo;
    }
}

// relu(h1) -> fp16 plane; warp per row (128 cols)
__global__ void convA_h1(const float* __restrict__ in, __half* __restrict__ outA, int M)
{
    int w = (blockIdx.x * blockDim.x + threadIdx.x) >> 5;
    int lane = threadIdx.x & 31;
    if (w >= M) return;
    size_t o = (size_t)w * 128 + lane * 4;
    float4 v = *(const float4*)(in + o);
    __half h[4];
    h[0] = __float2half(fmaxf(v.x, 0.f));
    h[1] = __float2half(fmaxf(v.y, 0.f));
    h[2] = __float2half(fmaxf(v.z, 0.f));
    h[3] = __float2half(fmaxf(v.w, 0.f));
    *(uint2*)(outA + o) = *(uint2*)h;
}

// ---------------------------------------------------------------------------
// CSR build
// ---------------------------------------------------------------------------
struct EdgePtrs { const int* e[5]; };

__global__ void count5_k(EdgePtrs ep, int* __restrict__ cnt, int E)
{
    int i = blockIdx.y;
    int e = blockIdx.x * blockDim.x + threadIdx.x;
    if (e < E) atomicAdd(&cnt[i * 100000 + ep.e[i][E + e]], 1);
}

__constant__ int c_dstN[5] = {100000, 50000, 50000, 50000, 100000};

__global__ void scan5_k(const int* __restrict__ cnt, int* __restrict__ off)
{
    __shared__ int sh[32];
    __shared__ int carry;
    int type = blockIdx.x;
    const int n = c_dstN[type];
    const int* c = cnt + type * 100000;
    int* o = off + type * 100032;
    int tid = threadIdx.x, lane = tid & 31, w = tid >> 5;
    if (tid == 0) carry = 0;
    __syncthreads();
    for (int base = 0; base < n; base += 1024) {
        int i = base + tid;
        int v = (i < n) ? c[i] : 0;
        int x = v;
#pragma unroll
        for (int d = 1; d < 32; d <<= 1) {
            int y = __shfl_up_sync(0xffffffffu, x, d);
            if (lane >= d) x += y;
        }
        if (lane == 31) sh[w] = x;
        __syncthreads();
        if (w == 0) {
            int s = sh[lane];
#pragma unroll
            for (int d = 1; d < 32; d <<= 1) {
                int y = __shfl_up_sync(0xffffffffu, s, d);
                if (lane >= d) s += y;
            }
            sh[lane] = s;
        }
        __syncthreads();
        int excl = x - v + (w > 0 ? sh[w - 1] : 0) + carry;
        if (i < n) o[i] = excl;
        __syncthreads();
        if (tid == 1023) carry = excl + v;
        __syncthreads();
    }
    if (tid == 0) o[n] = carry;
}

__global__ void fill5_k(EdgePtrs ep, const int* __restrict__ off, int* __restrict__ cursor,
                        int* __restrict__ srcA, int E)
{
    int i = blockIdx.y;
    int e = blockIdx.x * blockDim.x + threadIdx.x;
    if (e >= E) return;
    int d = ep.e[i][E + e];
    int pos = atomicAdd(&cursor[i * 100000 + d], 1);
    srcA[i * 200000 + off[i * 100032 + d] + pos] = ep.e[i][e];
}

// ---------------------------------------------------------------------------
// Fused gather + mean + lin_l + L2-normalize + sum over <=2 edge types
// ---------------------------------------------------------------------------
template<bool RELU, bool TWO>
__global__ void combine2(
    const float* __restrict__ B0, const float* __restrict__ P0,
    const int* __restrict__ off0, const int* __restrict__ src0,
    const float* __restrict__ B1, const float* __restrict__ P1,
    const int* __restrict__ off1, const int* __restrict__ src1,
    float* __restrict__ out, int n)
{
    int w = (blockIdx.x * blockDim.x + threadIdx.x) >> 5;
    int lane = threadIdx.x & 31;
    if (w >= n) return;
    size_t o = (size_t)w * HIDD + lane * 4;
    float4 r = make_float4(0.f, 0.f, 0.f, 0.f);

    {
        float4 b = *(const float4*)(B0 + o);
        int beg = __ldg(off0 + w), end = __ldg(off0 + w + 1);
        float4 a = make_float4(0.f, 0.f, 0.f, 0.f);
        for (int e = beg; e < end; e++) {
            int s = __ldg(src0 + e);
            float4 p = *(const float4*)(P0 + (size_t)s * HIDD + lane * 4);
            a.x += p.x; a.y += p.y; a.z += p.z; a.w += p.w;
        }
        float inv = 1.0f / fmaxf((float)(end - beg), 1.0f);
        float4 t;
        t.x = b.x + a.x * inv; t.y = b.y + a.y * inv;
        t.z = b.z + a.z * inv; t.w = b.w + a.w * inv;
        float ss = t.x * t.x + t.y * t.y + t.z * t.z + t.w * t.w;
#pragma unroll
        for (int sh = 16; sh; sh >>= 1) ss += __shfl_xor_sync(0xffffffffu, ss, sh);
        float sc = 1.0f / fmaxf(sqrtf(ss), 1e-12f);
        r.x += t.x * sc; r.y += t.y * sc; r.z += t.z * sc; r.w += t.w * sc;
    }
    if (TWO) {
        float4 b = *(const float4*)(B1 + o);
        int beg = __ldg(off1 + w), end = __ldg(off1 + w + 1);
        float4 a = make_float4(0.f, 0.f, 0.f, 0.f);
        for (int e = beg; e < end; e++) {
            int s = __ldg(src1 + e);
            float4 p = *(const float4*)(P1 + (size_t)s * HIDD + lane * 4);
            a.x += p.x; a.y += p.y; a.z += p.z; a.w += p.w;
        }
        float inv = 1.0f / fmaxf((float)(end - beg), 1.0f);
        float4 t;
        t.x = b.x + a.x * inv; t.y = b.y + a.y * inv;
        t.z = b.z + a.z * inv; t.w = b.w + a.w * inv;
        float ss = t.x * t.x + t.y * t.y + t.z * t.z + t.w * t.w;
#pragma unroll
        for (int sh = 16; sh; sh >>= 1) ss += __shfl_xor_sync(0xffffffffu, ss, sh);
        float sc = 1.0f / fmaxf(sqrtf(ss), 1e-12f);
        r.x += t.x * sc; r.y += t.y * sc; r.z += t.z * sc; r.w += t.w * sc;
    }
    if (RELU) {
        r.x = fmaxf(r.x, 0.f); r.y = fmaxf(r.y, 0.f);
        r.z = fmaxf(r.z, 0.f); r.w = fmaxf(r.w, 0.f);
    }
    *(float4*)(out + o) = r;
}

// ---------------------------------------------------------------------------
// SIMT GEMM for the 64-wide head
// ---------------------------------------------------------------------------
template<bool RELU_OUT>
__global__ __launch_bounds__(256) void gemm_tn(
    const float* __restrict__ A, const float* __restrict__ W,
    const float* __restrict__ bias, float* __restrict__ C,
    int M, int N, int K)
{
    __shared__ float As[8][128];
    __shared__ float Ws[8][128];
    const int tid = threadIdx.x;
    const int tx = tid & 15, ty = tid >> 4;
    const int rowBase = blockIdx.y * 128;

    float acc[8][8];
#pragma unroll
    for (int i = 0; i < 8; i++)
#pragma unroll
        for (int j = 0; j < 8; j++) acc[i][j] = 0.f;

    for (int k0 = 0; k0 < K; k0 += 8) {
#pragma unroll
        for (int t = 0; t < 4; t++) {
            int idx = tid + t * 256;
            int k = idx & 7, r = idx >> 3;
            int row = rowBase + r, kk = k0 + k;
            float v = 0.f;
            if (row < M && kk < K) v = A[(size_t)row * K + kk];
            As[k][r] = v;
        }
#pragma unroll
        for (int t = 0; t < 4; t++) {
            int idx = tid + t * 256;
            int k = idx & 7, c = idx >> 3;
            int kk = k0 + k;
            float v = 0.f;
            if (c < N && kk < K) v = W[(size_t)c * K + kk];
            Ws[k][c] = v;
        }
        __syncthreads();
#pragma unroll
        for (int k = 0; k < 8; k++) {
            float4 a0 = *(const float4*)&As[k][ty * 8];
            float4 a1 = *(const float4*)&As[k][ty * 8 + 4];
            float4 b0 = *(const float4*)&Ws[k][tx * 8];
            float4 b1 = *(const float4*)&Ws[k][tx * 8 + 4];
            float av[8] = {a0.x, a0.y, a0.z, a0.w, a1.x, a1.y, a1.z, a1.w};
            float bv[8] = {b0.x, b0.y, b0.z, b0.w, b1.x, b1.y, b1.z, b1.w};
#pragma unroll
            for (int i = 0; i < 8; i++)
#pragma unroll
                for (int j = 0; j < 8; j++) acc[i][j] += av[i] * bv[j];
        }
        __syncthreads();
    }

#pragma unroll
    for (int i = 0; i < 8; i++) {
        int row = rowBase + ty * 8 + i;
        if (row < M) {
#pragma unroll
            for (int j = 0; j < 8; j++) {
                int col = tx * 8 + j;
                if (col < N) {
                    float v = acc[i][j] + bias[col];
                    if (RELU_OUT) v = fmaxf(v, 0.f);
                    C[(size_t)row * N + col] = v;
                }
            }
        }
    }
}

__global__ void head2_k(const float* __restrict__ Z, const float* __restrict__ W2,
                        const float* __restrict__ b2, float* __restrict__ out, int n)
{
    int row = blockIdx.x * blockDim.x + threadIdx.x;
    if (row >= n) return;
    float acc0 = b2[0], acc1 = b2[1];
    const float* z = Z + (size_t)row * 64;
#pragma unroll
    for (int k = 0; k < 64; k++) {
        float zv = z[k];
        acc0 += zv * __ldg(W2 + k);
        acc1 += zv * __ldg(W2 + 64 + k);
    }
    out[row * 2 + 0] = acc0;
    out[row * 2 + 1] = acc1;
}

// ---------------------------------------------------------------------------
extern "C" void kernel_launch(void* const* d_in, const int* in_sizes, int n_in,
                              void* d_out_, int out_size)
{
    const float* x[3] = {(const float*)d_in[0], (const float*)d_in[1], (const float*)d_in[2]};
    const int nn[3] = {N_ART, N_ENT, N_FACT};
    const int* ei[5];
    for (int i = 0; i < 5; i++) ei[i] = (const int*)d_in[3 + i];
    const float* c1llw = (const float*)d_in[8];
    const float* c1llb = (const float*)d_in[9];
    const float* c1lrw = (const float*)d_in[10];
    const float* c2llw = (const float*)d_in[11];
    const float* c2llb = (const float*)d_in[12];
    const float* c2lrw = (const float*)d_in[13];
    const float* hw1 = (const float*)d_in[14];
    const float* hb1 = (const float*)d_in[15];
    const float* hw2 = (const float*)d_in[16];
    const float* hb2 = (const float*)d_in[17];
    float* out = (float*)d_out_;

    static const size_t BOFF[5] = {0, 100000, 150000, 200000, 250000};
    static const size_t POFF[5] = {0, 50000, 100000, 200000, 300000};

    float *B5, *P5, *H1, *Z;
    __half *Xh, *H1h, *W1L, *W1R, *W2L, *W2R;
    int *CUR, *OFFS, *SRCA;
    cudaGetSymbolAddress((void**)&B5, g_B5);
    cudaGetSymbolAddress((void**)&P5, g_P5);
    cudaGetSymbolAddress((void**)&H1, g_h1);
    cudaGetSymbolAddress((void**)&Z, g_z);
    cudaGetSymbolAddress((void**)&Xh, g_Xh);
    cudaGetSymbolAddress((void**)&H1h, g_H1h);
    cudaGetSymbolAddress((void**)&W1L, g_W1L);
    cudaGetSymbolAddress((void**)&W1R, g_W1R);
    cudaGetSymbolAddress((void**)&W2L, g_W2L);
    cudaGetSymbolAddress((void**)&W2R, g_W2R);
    cudaGetSymbolAddress((void**)&CUR, g_cursor);
    cudaGetSymbolAddress((void**)&OFFS, g_off);
    cudaGetSymbolAddress((void**)&SRCA, g_srcA);

    cudaFuncSetAttribute(gemm_fp16_1p, cudaFuncAttributeMaxDynamicSharedMemorySize, SMEM_1P);
    cudaFuncSetAttribute(gemm_fp16_multi, cudaFuncAttributeMaxDynamicSharedMemorySize, SMEM_FP16);

    const size_t XHB[3] = {0, (size_t)N_ART * K1S, (size_t)(N_ART + N_ENT) * K1S};
    const size_t R0[3] = {0, (size_t)N_ART, (size_t)(N_ART + N_ENT)};

    float* h1p[3] = {H1, H1 + (size_t)N_ART * HIDD, H1 + (size_t)(N_ART + N_ENT) * HIDD};
    float* h2p[3] = {out + 100000,
                     out + 100000 + (size_t)N_ART * HIDD,
                     out + 100000 + (size_t)(N_ART + N_ENT) * HIDD};

    const int NBLK[3] = {3, 4, 3};
    const int LLe[3][2] = {{2, -1}, {0, 4}, {1, 3}};
    const int LRe[3][2] = {{0, 1}, {2, 3}, {4, -1}};

    // W block strides (bytes): layer 1 single plane 128*800 halves;
    // layer 2 hi/lo rows 128*256 halves.
    const size_t WB1B = (size_t)128 * K1S * 2;
    const size_t WB2B = (size_t)128 * 2 * K2S * 2;

    auto make_outs = [&](int layer, int t) {
        MultiOut p;
        const char* WL = layer ? (const char*)W2L : (const char*)W1L;
        const char* WR = layer ? (const char*)W2R : (const char*)W1R;
        const float* bb = layer ? c2llb : c1llb;
        const size_t WBB = layer ? WB2B : WB1B;
        int nb = 0;
        for (int j = 0; j < 2; j++) {
            int e = LLe[t][j];
            if (e < 0) break;
            p.W[nb] = WL + (size_t)e * WBB;
            p.bias[nb] = bb + e * HIDD;
            p.C[nb] = B5 + BOFF[e] * HIDD;
            nb++;
        }
        for (int j = 0; j < 2; j++) {
            int e = LRe[t][j];
            if (e < 0) break;
            p.W[nb] = WR + (size_t)e * WBB;
            p.bias[nb] = nullptr;
            p.C[nb] = P5 + POFF[e] * HIDD;
            nb++;
        }
        return p;
    };

    // --- converts: features + W1 (plain fp16) ---
    for (int t = 0; t < 3; t++)
        conv_fp16<<<nn[t], 256>>>(x[t], Xh + XHB[t], FEATD, K1S);
    conv_fp16<<<640, 256>>>(c1llw, W1L, FEATD, K1S);
    conv_fp16<<<640, 256>>>(c1lrw, W1R, FEATD, K1S);

    // --- layer-1 GEMMs (fp16 single-pass) ---
    for (int t = 1; t >= 0; t--) {
        MultiOut p = make_outs(0, t);
        gemm_fp16_1p<<<dim3(NBLK[t], (nn[t] + 127) / 128), 256, SMEM_1P>>>(
            Xh + XHB[t], p, nn[t], K1S);
    }
    {
        MultiOut p = make_outs(0, 2);
        gemm_fp16_1p<<<dim3(NBLK[2], (nn[2] + 127) / 128), 256, SMEM_1P>>>(
            Xh + XHB[2], p, nn[2], K1S);
    }

    // --- CSR build + W2 splits ---
    EdgePtrs ep;
    for (int i = 0; i < 5; i++) ep.e[i] = ei[i];
    cudaMemsetAsync(CUR, 0, 500000 * sizeof(int));
    count5_k<<<dim3((NEDGE + 255) / 256, 5), 256>>>(ep, CUR, NEDGE);
    scan5_k<<<5, 1024>>>(CUR, OFFS);
    cudaMemsetAsync(CUR, 0, 500000 * sizeof(int));
    fill5_k<<<dim3((NEDGE + 255) / 256, 5), 256>>>(ep, OFFS, CUR, SRCA, NEDGE);
    splitW_fp16<<<640, 128>>>(c2llw, W2L, HIDD, K2S);
    splitW_fp16<<<640, 128>>>(c2lrw, W2R, HIDD, K2S);

    // --- layer-1 combines ---
    combine2<false, false><<<(N_ART + 7) / 8, 256>>>(
        B5 + BOFF[2] * HIDD, P5 + POFF[2] * HIDD, OFFS + 2 * 100032, SRCA + 2 * 200000,
        nullptr, nullptr, nullptr, nullptr, h1p[0], N_ART);
    combine2<false, true><<<(N_ENT + 7) / 8, 256>>>(
        B5 + BOFF[0] * HIDD, P5 + POFF[0] * HIDD, OFFS + 0 * 100032, SRCA + 0 * 200000,
        B5 + BOFF[4] * HIDD, P5 + POFF[4] * HIDD, OFFS + 4 * 100032, SRCA + 4 * 200000,
        h1p[1], N_ENT);
    combine2<false, true><<<(N_FACT + 7) / 8, 256>>>(
        B5 + BOFF[1] * HIDD, P5 + POFF[1] * HIDD, OFFS + 1 * 100032, SRCA + 1 * 200000,
        B5 + BOFF[3] * HIDD, P5 + POFF[3] * HIDD, OFFS + 3 * 100032, SRCA + 3 * 200000,
        h1p[2], N_FACT);

    // --- relu + fp16 convert h1 ---
    convA_h1<<<(200000 + 7) / 8, 256>>>(H1, H1h, 200000);

    // --- layer-2 GEMMs (fp16 2-pass) ---
    for (int t = 1; t >= 0; t--) {
        MultiOut p = make_outs(1, t);
        gemm_fp16_multi<<<dim3(NBLK[t], (nn[t] + 127) / 128), 256, SMEM_FP16>>>(
            H1h + R0[t] * K2S, p, nn[t], K2S);
    }
    {
        MultiOut p = make_outs(1, 2);
        gemm_fp16_multi<<<dim3(NBLK[2], (nn[2] + 127) / 128), 256, SMEM_FP16>>>(
            H1h + R0[2] * K2S, p, nn[2], K2S);
    }

    // --- layer-2 combines (relu fused) ---
    combine2<true, false><<<(N_ART + 7) / 8, 256>>>(
        B5 + BOFF[2] * HIDD, P5 + POFF[2] * HIDD, OFFS + 2 * 100032, SRCA + 2 * 200000,
        nullptr, nullptr, nullptr, nullptr, h2p[0], N_ART);
    combine2<true, true><<<(N_ENT + 7) / 8, 256>>>(
        B5 + BOFF[0] * HIDD, P5 + POFF[0] * HIDD, OFFS + 0 * 100032, SRCA + 0 * 200000,
        B5 + BOFF[4] * HIDD, P5 + POFF[4] * HIDD, OFFS + 4 * 100032, SRCA + 4 * 200000,
        h2p[1], N_ENT);
    combine2<true, true><<<(N_FACT + 7) / 8, 256>>>(
        B5 + BOFF[1] * HIDD, P5 + POFF[1] * HIDD, OFFS + 1 * 100032, SRCA + 1 * 200000,
        B5 + BOFF[3] * HIDD, P5 + POFF[3] * HIDD, OFFS + 3 * 100032, SRCA + 3 * 200000,
        h2p[2], N_FACT);

    // --- head MLP ---
    gemm_tn<true><<<dim3(1, (N_ART + 127) / 128), 256>>>(
        out + 100000, hw1, hb1, Z, N_ART, 64, HIDD);
    head2_k<<<(N_ART + 255) / 256, 256>>>(Z, hw2, hb2, out, N_ART);
}

// round 12
// speedup vs baseline: 6.4166x; 1.0789x over previous
#include <cuda_runtime.h>
#include <cuda_fp16.h>
#include <math.h>
#include <stdint.h>

#define N_ART 50000
#define N_ENT 100000
#define N_FACT 50000
#define NEDGE 200000
#define FEATD 769
#define HIDD 128

#define K1S 800
#define K2S 128

// ---------------------------------------------------------------------------
// Scratch
// ---------------------------------------------------------------------------
__device__ float g_B5[44800000];                // 5 lin_l outputs (dst rows)
__device__ float g_P5[44800000];                // 5 lin_r outputs (src rows)
__device__ float g_h1[25600000];
__device__ float g_z[3200000];
__device__ __half g_Xh[160000000];              // fp16 features: 200k x 800 (art|ent|fact)
__device__ __half g_H1h[25600000];              // fp16 relu(h1): 200k x 128
__device__ __half g_W1L[512000];                // c1 lin_l fp16: 640 x 800
__device__ __half g_W1R[512000];
__device__ __half g_W2L[81920];                 // c2 lin_l fp16: 640 x 128
__device__ __half g_W2R[81920];
__device__ int g_cursor[500000];
__device__ int g_off[500160];                   // per-type CSR offsets (stride 100032)
__device__ int g_srcA[1000000];                 // per-type CSR src lists (stride 200000)

// ---------------------------------------------------------------------------
__device__ __forceinline__ uint32_t smem_u32(const void* p) {
    uint32_t a;
    asm("{ .reg .u64 t; cvta.to.shared.u64 t, %1; cvt.u32.u64 %0, t; }"
        : "=r"(a) : "l"(p));
    return a;
}

#define CP_ASYNC16(dst, src) \
    asm volatile("cp.async.cg.shared.global [%0], [%1], 16;" :: "r"(dst), "l"(src))
#define CP_COMMIT() asm volatile("cp.async.commit_group;" ::: "memory")
#define CP_WAIT1()  asm volatile("cp.async.wait_group 1;" ::: "memory")

#define SSTRB 80

struct MultiOut {
    const void* W[4];
    const float* bias[4];
    float* C[4];
};

#define LDMX4(r0, r1, r2, r3, addr) \
    asm volatile("ldmatrix.sync.aligned.m8n8.x4.shared.b16 {%0,%1,%2,%3}, [%4];" \
                 : "=r"(r0), "=r"(r1), "=r"(r2), "=r"(r3) : "r"(addr))

#define MMA_FP16(acc, a, b) \
    asm volatile("mma.sync.aligned.m16n8k16.row.col.f32.f16.f16.f32 " \
                 "{%0,%1,%2,%3}, {%4,%5,%6,%7}, {%8,%9}, {%0,%1,%2,%3};" \
                 : "+f"((acc)[0]), "+f"((acc)[1]), "+f"((acc)[2]), "+f"((acc)[3]) \
                 : "r"((a)[0]), "r"((a)[1]), "r"((a)[2]), "r"((a)[3]), \
                   "r"((b)[0]), "r"((b)[1]))

// ---------------------------------------------------------------------------
// fp16 single-pass multi-output GEMM: C_b[M,128] = A[M,S] @ W_b[128,S]^T (+bias)
// grid = (NBLK, ceil(M/128)), 256 threads, K-chunk 32, double-buffered.
// ---------------------------------------------------------------------------
#define P1_OFF_A 0
#define P1_OFF_W 20480
#define SMEM_1P  40960

__global__ __launch_bounds__(256) void gemm_fp16_1p(
    const __half* __restrict__ A, MultiOut p, int M, int S)
{
    extern __shared__ char sm[];
    const uint32_t sb = smem_u32(sm);
    const int tid = threadIdx.x, lane = tid & 31, warp = tid >> 5;
    const int mQ = warp >> 1, nH = warp & 1;
    const int rowBase = blockIdx.y * 128;
    const __half* __restrict__ W = (const __half*)p.W[blockIdx.x];
    const float* __restrict__ bias = p.bias[blockIdx.x];
    float* __restrict__ C = p.C[blockIdx.x];
    const int NC = S >> 5;

    float acc[2][8][4];
#pragma unroll
    for (int i = 0; i < 2; i++)
#pragma unroll
        for (int j = 0; j < 8; j++)
#pragma unroll
            for (int q = 0; q < 4; q++) acc[i][j][q] = 0.f;

    const int lr4 = tid >> 2, lq4 = tid & 3;

#define LOAD1(c, buf) do { \
    int k0 = (c) * 32; \
    _Pragma("unroll") \
    for (int i = 0; i < 2; i++) { \
        int r = lr4 + i * 64; \
        int ga = rowBase + r; if (ga >= M) ga = M - 1; \
        uint32_t so = (buf) * 10240 + r * SSTRB + lq4 * 16; \
        CP_ASYNC16(sb + P1_OFF_A + so, A + (size_t)ga * S + k0 + lq4 * 8); \
        CP_ASYNC16(sb + P1_OFF_W + so, W + (size_t)r * S + k0 + lq4 * 8); \
    } } while (0)

    LOAD1(0, 0); CP_COMMIT();
    if (NC > 1) { LOAD1(1, 1); }
    CP_COMMIT();

    const int a_row = lane & 15;
    const int a_sel = (lane >> 4) & 1;
    const int b_row = (lane & 7) + ((lane & 16) >> 1);
    const int b_sel = (lane >> 3) & 1;

    for (int c = 0; c < NC; c++) {
        CP_WAIT1();
        __syncthreads();
        uint32_t bo = (uint32_t)(c & 1) * 10240;
        uint32_t abase = sb + P1_OFF_A + bo;
        uint32_t wbase = sb + P1_OFF_W + bo;
#pragma unroll
        for (int kh = 0; kh < 2; kh++) {
            uint32_t ar[2][4], br[8][2];
#pragma unroll
            for (int mi = 0; mi < 2; mi++) {
                uint32_t addr = abase + (mQ * 32 + mi * 16 + a_row) * SSTRB
                                + kh * 32 + a_sel * 16;
                LDMX4(ar[mi][0], ar[mi][1], ar[mi][2], ar[mi][3], addr);
            }
#pragma unroll
            for (int pi = 0; pi < 4; pi++) {
                uint32_t addr = wbase + (nH * 64 + pi * 16 + b_row) * SSTRB
                                + kh * 32 + b_sel * 16;
                LDMX4(br[2 * pi][0], br[2 * pi][1],
                      br[2 * pi + 1][0], br[2 * pi + 1][1], addr);
            }
#pragma unroll
            for (int mi = 0; mi < 2; mi++)
#pragma unroll
                for (int ni = 0; ni < 8; ni++)
                    MMA_FP16(acc[mi][ni], ar[mi], br[ni]);
        }
        __syncthreads();
        if (c + 2 < NC) LOAD1(c + 2, c & 1);
        CP_COMMIT();
    }
#undef LOAD1

    const int g = lane >> 2, t = lane & 3;
#pragma unroll
    for (int mi = 0; mi < 2; mi++) {
        int r0 = rowBase + mQ * 32 + mi * 16 + g;
#pragma unroll
        for (int ni = 0; ni < 8; ni++) {
            int col = nH * 64 + ni * 8 + t * 2;
            float bx = 0.f, by2 = 0.f;
            if (bias) { bx = bias[col]; by2 = bias[col + 1]; }
            if (r0 < M) {
                float2 v = make_float2(acc[mi][ni][0] + bx, acc[mi][ni][1] + by2);
                *(float2*)(C + (size_t)r0 * 128 + col) = v;
            }
            if (r0 + 8 < M) {
                float2 v = make_float2(acc[mi][ni][2] + bx, acc[mi][ni][3] + by2);
                *(float2*)(C + (size_t)(r0 + 8) * 128 + col) = v;
            }
        }
    }
}

// ---------------------------------------------------------------------------
// Converts
// ---------------------------------------------------------------------------
// all 3 feature matrices -> one contiguous fp16 buffer (row-range select)
__global__ void conv_feat3(const float* __restrict__ x0, const float* __restrict__ x1,
                           const float* __restrict__ x2, __half* __restrict__ outA)
{
    int row = blockIdx.x;
    int k = threadIdx.x * 4;
    if (k >= K1S) return;
    const float* src;
    if (row < N_ART) src = x0 + (size_t)row * FEATD;
    else if (row < N_ART + N_ENT) src = x1 + (size_t)(row - N_ART) * FEATD;
    else src = x2 + (size_t)(row - N_ART - N_ENT) * FEATD;
    __half h[4];
#pragma unroll
    for (int j = 0; j < 4; j++) {
        int kk = k + j;
        h[j] = __float2half((kk < FEATD) ? src[kk] : 0.f);
    }
    *(uint2*)(outA + (size_t)row * K1S + k) = *(uint2*)h;
}

// generic fp32 [rows x K] -> fp16 [rows x S] (pads zeroed)
__global__ void conv_fp16(const float* __restrict__ in,
                          __half* __restrict__ outA, int K, int S)
{
    int row = blockIdx.x;
    int k = threadIdx.x * 4;
    if (k >= S) return;
    const float* src = in + (size_t)row * K;
    __half h[4];
#pragma unroll
    for (int j = 0; j < 4; j++) {
        int kk = k + j;
        h[j] = __float2half((kk < K) ? src[kk] : 0.f);
    }
    *(uint2*)(outA + (size_t)row * S + k) = *(uint2*)h;
}

// relu(h1) -> fp16 plane; warp per row (128 cols)
__global__ void convA_h1(const float* __restrict__ in, __half* __restrict__ outA, int M)
{
    int w = (blockIdx.x * blockDim.x + threadIdx.x) >> 5;
    int lane = threadIdx.x & 31;
    if (w >= M) return;
    size_t o = (size_t)w * 128 + lane * 4;
    float4 v = *(const float4*)(in + o);
    __half h[4];
    h[0] = __float2half(fmaxf(v.x, 0.f));
    h[1] = __float2half(fmaxf(v.y, 0.f));
    h[2] = __float2half(fmaxf(v.z, 0.f));
    h[3] = __float2half(fmaxf(v.w, 0.f));
    *(uint2*)(outA + o) = *(uint2*)h;
}

// ---------------------------------------------------------------------------
// CSR build
// ---------------------------------------------------------------------------
struct EdgePtrs { const int* e[5]; };

__global__ void count5_k(EdgePtrs ep, int* __restrict__ cnt, int E)
{
    int i = blockIdx.y;
    int e = blockIdx.x * blockDim.x + threadIdx.x;
    if (e < E) atomicAdd(&cnt[i * 100000 + ep.e[i][E + e]], 1);
}

__constant__ int c_dstN[5] = {100000, 50000, 50000, 50000, 100000};

__global__ void scan5_k(const int* __restrict__ cnt, int* __restrict__ off)
{
    __shared__ int sh[32];
    __shared__ int carry;
    int type = blockIdx.x;
    const int n = c_dstN[type];
    const int* c = cnt + type * 100000;
    int* o = off + type * 100032;
    int tid = threadIdx.x, lane = tid & 31, w = tid >> 5;
    if (tid == 0) carry = 0;
    __syncthreads();
    for (int base = 0; base < n; base += 1024) {
        int i = base + tid;
        int v = (i < n) ? c[i] : 0;
        int x = v;
#pragma unroll
        for (int d = 1; d < 32; d <<= 1) {
            int y = __shfl_up_sync(0xffffffffu, x, d);
            if (lane >= d) x += y;
        }
        if (lane == 31) sh[w] = x;
        __syncthreads();
        if (w == 0) {
            int s = sh[lane];
#pragma unroll
            for (int d = 1; d < 32; d <<= 1) {
                int y = __shfl_up_sync(0xffffffffu, s, d);
                if (lane >= d) s += y;
            }
            sh[lane] = s;
        }
        __syncthreads();
        int excl = x - v + (w > 0 ? sh[w - 1] : 0) + carry;
        if (i < n) o[i] = excl;
        __syncthreads();
        if (tid == 1023) carry = excl + v;
        __syncthreads();
    }
    if (tid == 0) o[n] = carry;
}

__global__ void fill5_k(EdgePtrs ep, const int* __restrict__ off, int* __restrict__ cursor,
                        int* __restrict__ srcA, int E)
{
    int i = blockIdx.y;
    int e = blockIdx.x * blockDim.x + threadIdx.x;
    if (e >= E) return;
    int d = ep.e[i][E + e];
    int pos = atomicAdd(&cursor[i * 100000 + d], 1);
    srcA[i * 200000 + off[i * 100032 + d] + pos] = ep.e[i][e];
}

// ---------------------------------------------------------------------------
// Fused gather + mean + lin_l + L2-normalize + sum over <=2 edge types
// ---------------------------------------------------------------------------
template<bool RELU, bool TWO>
__global__ void combine2(
    const float* __restrict__ B0, const float* __restrict__ P0,
    const int* __restrict__ off0, const int* __restrict__ src0,
    const float* __restrict__ B1, const float* __restrict__ P1,
    const int* __restrict__ off1, const int* __restrict__ src1,
    float* __restrict__ out, int n)
{
    int w = (blockIdx.x * blockDim.x + threadIdx.x) >> 5;
    int lane = threadIdx.x & 31;
    if (w >= n) return;
    size_t o = (size_t)w * HIDD + lane * 4;
    float4 r = make_float4(0.f, 0.f, 0.f, 0.f);

    {
        float4 b = *(const float4*)(B0 + o);
        int beg = __ldg(off0 + w), end = __ldg(off0 + w + 1);
        float4 a = make_float4(0.f, 0.f, 0.f, 0.f);
        for (int e = beg; e < end; e++) {
            int s = __ldg(src0 + e);
            float4 p = *(const float4*)(P0 + (size_t)s * HIDD + lane * 4);
            a.x += p.x; a.y += p.y; a.z += p.z; a.w += p.w;
        }
        float inv = 1.0f / fmaxf((float)(end - beg), 1.0f);
        float4 t;
        t.x = b.x + a.x * inv; t.y = b.y + a.y * inv;
        t.z = b.z + a.z * inv; t.w = b.w + a.w * inv;
        float ss = t.x * t.x + t.y * t.y + t.z * t.z + t.w * t.w;
#pragma unroll
        for (int sh = 16; sh; sh >>= 1) ss += __shfl_xor_sync(0xffffffffu, ss, sh);
        float sc = 1.0f / fmaxf(sqrtf(ss), 1e-12f);
        r.x += t.x * sc; r.y += t.y * sc; r.z += t.z * sc; r.w += t.w * sc;
    }
    if (TWO) {
        float4 b = *(const float4*)(B1 + o);
        int beg = __ldg(off1 + w), end = __ldg(off1 + w + 1);
        float4 a = make_float4(0.f, 0.f, 0.f, 0.f);
        for (int e = beg; e < end; e++) {
            int s = __ldg(src1 + e);
            float4 p = *(const float4*)(P1 + (size_t)s * HIDD + lane * 4);
            a.x += p.x; a.y += p.y; a.z += p.z; a.w += p.w;
        }
        float inv = 1.0f / fmaxf((float)(end - beg), 1.0f);
        float4 t;
        t.x = b.x + a.x * inv; t.y = b.y + a.y * inv;
        t.z = b.z + a.z * inv; t.w = b.w + a.w * inv;
        float ss = t.x * t.x + t.y * t.y + t.z * t.z + t.w * t.w;
#pragma unroll
        for (int sh = 16; sh; sh >>= 1) ss += __shfl_xor_sync(0xffffffffu, ss, sh);
        float sc = 1.0f / fmaxf(sqrtf(ss), 1e-12f);
        r.x += t.x * sc; r.y += t.y * sc; r.z += t.z * sc; r.w += t.w * sc;
    }
    if (RELU) {
        r.x = fmaxf(r.x, 0.f); r.y = fmaxf(r.y, 0.f);
        r.z = fmaxf(r.z, 0.f); r.w = fmaxf(r.w, 0.f);
    }
    *(float4*)(out + o) = r;
}

// ---------------------------------------------------------------------------
// SIMT GEMM for the 64-wide head
// ---------------------------------------------------------------------------
template<bool RELU_OUT>
__global__ __launch_bounds__(256) void gemm_tn(
    const float* __restrict__ A, const float* __restrict__ W,
    const float* __restrict__ bias, float* __restrict__ C,
    int M, int N, int K)
{
    __shared__ float As[8][128];
    __shared__ float Ws[8][128];
    const int tid = threadIdx.x;
    const int tx = tid & 15, ty = tid >> 4;
    const int rowBase = blockIdx.y * 128;

    float acc[8][8];
#pragma unroll
    for (int i = 0; i < 8; i++)
#pragma unroll
        for (int j = 0; j < 8; j++) acc[i][j] = 0.f;

    for (int k0 = 0; k0 < K; k0 += 8) {
#pragma unroll
        for (int t = 0; t < 4; t++) {
            int idx = tid + t * 256;
            int k = idx & 7, r = idx >> 3;
            int row = rowBase + r, kk = k0 + k;
            float v = 0.f;
            if (row < M && kk < K) v = A[(size_t)row * K + kk];
            As[k][r] = v;
        }
#pragma unroll
        for (int t = 0; t < 4; t++) {
            int idx = tid + t * 256;
            int k = idx & 7, c = idx >> 3;
            int kk = k0 + k;
            float v = 0.f;
            if (c < N && kk < K) v = W[(size_t)c * K + kk];
            Ws[k][c] = v;
        }
        __syncthreads();
#pragma unroll
        for (int k = 0; k < 8; k++) {
            float4 a0 = *(const float4*)&As[k][ty * 8];
            float4 a1 = *(const float4*)&As[k][ty * 8 + 4];
            float4 b0 = *(const float4*)&Ws[k][tx * 8];
            float4 b1 = *(const float4*)&Ws[k][tx * 8 + 4];
            float av[8] = {a0.x, a0.y, a0.z, a0.w, a1.x, a1.y, a1.z, a1.w};
            float bv[8] = {b0.x, b0.y, b0.z, b0.w, b1.x, b1.y, b1.z, b1.w};
#pragma unroll
            for (int i = 0; i < 8; i++)
#pragma unroll
                for (int j = 0; j < 8; j++) acc[i][j] += av[i] * bv[j];
        }
        __syncthreads();
    }

#pragma unroll
    for (int i = 0; i < 8; i++) {
        int row = rowBase + ty * 8 + i;
        if (row < M) {
#pragma unroll
            for (int j = 0; j < 8; j++) {
                int col = tx * 8 + j;
                if (col < N) {
                    float v = acc[i][j] + bias[col];
                    if (RELU_OUT) v = fmaxf(v, 0.f);
                    C[(size_t)row * N + col] = v;
                }
            }
        }
    }
}

__global__ void head2_k(const float* __restrict__ Z, const float* __restrict__ W2,
                        const float* __restrict__ b2, float* __restrict__ out, int n)
{
    int row = blockIdx.x * blockDim.x + threadIdx.x;
    if (row >= n) return;
    float acc0 = b2[0], acc1 = b2[1];
    const float* z = Z + (size_t)row * 64;
#pragma unroll
    for (int k = 0; k < 64; k++) {
        float zv = z[k];
        acc0 += zv * __ldg(W2 + k);
        acc1 += zv * __ldg(W2 + 64 + k);
    }
    out[row * 2 + 0] = acc0;
    out[row * 2 + 1] = acc1;
}

// ---------------------------------------------------------------------------
extern "C" void kernel_launch(void* const* d_in, const int* in_sizes, int n_in,
                              void* d_out_, int out_size)
{
    const float* x[3] = {(const float*)d_in[0], (const float*)d_in[1], (const float*)d_in[2]};
    const int nn[3] = {N_ART, N_ENT, N_FACT};
    const int* ei[5];
    for (int i = 0; i < 5; i++) ei[i] = (const int*)d_in[3 + i];
    const float* c1llw = (const float*)d_in[8];
    const float* c1llb = (const float*)d_in[9];
    const float* c1lrw = (const float*)d_in[10];
    const float* c2llw = (const float*)d_in[11];
    const float* c2llb = (const float*)d_in[12];
    const float* c2lrw = (const float*)d_in[13];
    const float* hw1 = (const float*)d_in[14];
    const float* hb1 = (const float*)d_in[15];
    const float* hw2 = (const float*)d_in[16];
    const float* hb2 = (const float*)d_in[17];
    float* out = (float*)d_out_;

    static const size_t BOFF[5] = {0, 100000, 150000, 200000, 250000};
    static const size_t POFF[5] = {0, 50000, 100000, 200000, 300000};

    float *B5, *P5, *H1, *Z;
    __half *Xh, *H1h, *W1L, *W1R, *W2L, *W2R;
    int *CUR, *OFFS, *SRCA;
    cudaGetSymbolAddress((void**)&B5, g_B5);
    cudaGetSymbolAddress((void**)&P5, g_P5);
    cudaGetSymbolAddress((void**)&H1, g_h1);
    cudaGetSymbolAddress((void**)&Z, g_z);
    cudaGetSymbolAddress((void**)&Xh, g_Xh);
    cudaGetSymbolAddress((void**)&H1h, g_H1h);
    cudaGetSymbolAddress((void**)&W1L, g_W1L);
    cudaGetSymbolAddress((void**)&W1R, g_W1R);
    cudaGetSymbolAddress((void**)&W2L, g_W2L);
    cudaGetSymbolAddress((void**)&W2R, g_W2R);
    cudaGetSymbolAddress((void**)&CUR, g_cursor);
    cudaGetSymbolAddress((void**)&OFFS, g_off);
    cudaGetSymbolAddress((void**)&SRCA, g_srcA);

    cudaFuncSetAttribute(gemm_fp16_1p, cudaFuncAttributeMaxDynamicSharedMemorySize, SMEM_1P);

    const size_t XHB[3] = {0, (size_t)N_ART * K1S, (size_t)(N_ART + N_ENT) * K1S};
    const size_t R0[3] = {0, (size_t)N_ART, (size_t)(N_ART + N_ENT)};

    float* h1p[3] = {H1, H1 + (size_t)N_ART * HIDD, H1 + (size_t)(N_ART + N_ENT) * HIDD};
    float* h2p[3] = {out + 100000,
                     out + 100000 + (size_t)N_ART * HIDD,
                     out + 100000 + (size_t)(N_ART + N_ENT) * HIDD};

    const int NBLK[3] = {3, 4, 3};
    const int LLe[3][2] = {{2, -1}, {0, 4}, {1, 3}};
    const int LRe[3][2] = {{0, 1}, {2, 3}, {4, -1}};

    // W block strides (bytes): single fp16 plane each layer
    const size_t WB1B = (size_t)128 * K1S * 2;
    const size_t WB2B = (size_t)128 * K2S * 2;

    auto make_outs = [&](int layer, int t) {
        MultiOut p;
        const char* WL = layer ? (const char*)W2L : (const char*)W1L;
        const char* WR = layer ? (const char*)W2R : (const char*)W1R;
        const float* bb = layer ? c2llb : c1llb;
        const size_t WBB = layer ? WB2B : WB1B;
        int nb = 0;
        for (int j = 0; j < 2; j++) {
            int e = LLe[t][j];
            if (e < 0) break;
            p.W[nb] = WL + (size_t)e * WBB;
            p.bias[nb] = bb + e * HIDD;
            p.C[nb] = B5 + BOFF[e] * HIDD;
            nb++;
        }
        for (int j = 0; j < 2; j++) {
            int e = LRe[t][j];
            if (e < 0) break;
            p.W[nb] = WR + (size_t)e * WBB;
            p.bias[nb] = nullptr;
            p.C[nb] = P5 + POFF[e] * HIDD;
            nb++;
        }
        return p;
    };

    // --- launches 0-4: converts (feat merged, W1 x2, W2 x2) ---
    conv_feat3<<<200000, 256>>>(x[0], x[1], x[2], Xh);
    conv_fp16<<<640, 256>>>(c1llw, W1L, FEATD, K1S);
    conv_fp16<<<640, 256>>>(c1lrw, W1R, FEATD, K1S);
    conv_fp16<<<640, 32>>>(c2llw, W2L, HIDD, K2S);
    conv_fp16<<<640, 32>>>(c2lrw, W2R, HIDD, K2S);

    // --- launch 5: ent layer-1 GEMM (ncu -s 5 -c 1 captures this) ---
    for (int t = 1; t >= 0; t--) {
        MultiOut p = make_outs(0, t);
        gemm_fp16_1p<<<dim3(NBLK[t], (nn[t] + 127) / 128), 256, SMEM_1P>>>(
            Xh + XHB[t], p, nn[t], K1S);
    }
    {
        MultiOut p = make_outs(0, 2);
        gemm_fp16_1p<<<dim3(NBLK[2], (nn[2] + 127) / 128), 256, SMEM_1P>>>(
            Xh + XHB[2], p, nn[2], K1S);
    }

    // --- CSR build ---
    EdgePtrs ep;
    for (int i = 0; i < 5; i++) ep.e[i] = ei[i];
    cudaMemsetAsync(CUR, 0, 500000 * sizeof(int));
    count5_k<<<dim3((NEDGE + 255) / 256, 5), 256>>>(ep, CUR, NEDGE);
    scan5_k<<<5, 1024>>>(CUR, OFFS);
    cudaMemsetAsync(CUR, 0, 500000 * sizeof(int));
    fill5_k<<<dim3((NEDGE + 255) / 256, 5), 256>>>(ep, OFFS, CUR, SRCA, NEDGE);

    // --- layer-1 combines ---
    combine2<false, false><<<(N_ART + 7) / 8, 256>>>(
        B5 + BOFF[2] * HIDD, P5 + POFF[2] * HIDD, OFFS + 2 * 100032, SRCA + 2 * 200000,
        nullptr, nullptr, nullptr, nullptr, h1p[0], N_ART);
    combine2<false, true><<<(N_ENT + 7) / 8, 256>>>(
        B5 + BOFF[0] * HIDD, P5 + POFF[0] * HIDD, OFFS + 0 * 100032, SRCA + 0 * 200000,
        B5 + BOFF[4] * HIDD, P5 + POFF[4] * HIDD, OFFS + 4 * 100032, SRCA + 4 * 200000,
        h1p[1], N_ENT);
    combine2<false, true><<<(N_FACT + 7) / 8, 256>>>(
        B5 + BOFF[1] * HIDD, P5 + POFF[1] * HIDD, OFFS + 1 * 100032, SRCA + 1 * 200000,
        B5 + BOFF[3] * HIDD, P5 + POFF[3] * HIDD, OFFS + 3 * 100032, SRCA + 3 * 200000,
        h1p[2], N_FACT);

    // --- relu + fp16 convert h1 ---
    convA_h1<<<(200000 + 7) / 8, 256>>>(H1, H1h, 200000);

    // --- layer-2 GEMMs (fp16 single-pass) ---
    for (int t = 1; t >= 0; t--) {
        MultiOut p = make_outs(1, t);
        gemm_fp16_1p<<<dim3(NBLK[t], (nn[t] + 127) / 128), 256, SMEM_1P>>>(
            H1h + R0[t] * K2S, p, nn[t], K2S);
    }
    {
        MultiOut p = make_outs(1, 2);
        gemm_fp16_1p<<<dim3(NBLK[2], (nn[2] + 127) / 128), 256, SMEM_1P>>>(
            H1h + R0[2] * K2S, p, nn[2], K2S);
    }

    // --- layer-2 combines (relu fused) ---
    combine2<true, false><<<(N_ART + 7) / 8, 256>>>(
        B5 + BOFF[2] * HIDD, P5 + POFF[2] * HIDD, OFFS + 2 * 100032, SRCA + 2 * 200000,
        nullptr, nullptr, nullptr, nullptr, h2p[0], N_ART);
    combine2<true, true><<<(N_ENT + 7) / 8, 256>>>(
        B5 + BOFF[0] * HIDD, P5 + POFF[0] * HIDD, OFFS + 0 * 100032, SRCA + 0 * 200000,
        B5 + BOFF[4] * HIDD, P5 + POFF[4] * HIDD, OFFS + 4 * 100032, SRCA + 4 * 200000,
        h2p[1], N_ENT);
    combine2<true, true><<<(N_FACT + 7) / 8, 256>>>(
        B5 + BOFF[1] * HIDD, P5 + POFF[1] * HIDD, OFFS + 1 * 100032, SRCA + 1 * 200000,
        B5 + BOFF[3] * HIDD, P5 + POFF[3] * HIDD, OFFS + 3 * 100032, SRCA + 3 * 200000,
        h2p[2], N_FACT);

    // --- head MLP ---
    gemm_tn<true><<<dim3(1, (N_ART + 127) / 128), 256>>>(
        out + 100000, hw1, hb1, Z, N_ART, 64, HIDD);
    head2_k<<<(N_ART + 255) / 256, 256>>>(Z, hw2, hb2, out, N_ART);
}

// round 13
// speedup vs baseline: 6.9649x; 1.0854x over previous
#include <cuda_runtime.h>
#include <cuda_fp16.h>
#include <math.h>
#include <stdint.h>

#define N_ART 50000
#define N_ENT 100000
#define N_FACT 50000
#define NEDGE 200000
#define FEATD 769
#define HIDD 128

#define K1S 800
#define K2S 128

// ---------------------------------------------------------------------------
// Scratch
// ---------------------------------------------------------------------------
__device__ __half g_B5[44800000];               // 5 lin_l outputs (dst rows), fp16
__device__ __half g_P5[44800000];               // 5 lin_r outputs (src rows), fp16
__device__ float g_z[3200000];
__device__ __half g_Xh[160000000];              // fp16 features: 200k x 800 (art|ent|fact)
__device__ __half g_H1h[25600000];              // fp16 relu(h1): 200k x 128
__device__ __half g_W1L[512000];                // c1 lin_l fp16: 640 x 800
__device__ __half g_W1R[512000];
__device__ __half g_W2L[81920];                 // c2 lin_l fp16: 640 x 128
__device__ __half g_W2R[81920];
__device__ int g_cursor[500000];
__device__ int g_off[500160];                   // per-type CSR offsets (stride 100032)
__device__ int g_srcA[1000000];                 // per-type CSR src lists (stride 200000)

// ---------------------------------------------------------------------------
__device__ __forceinline__ uint32_t smem_u32(const void* p) {
    uint32_t a;
    asm("{ .reg .u64 t; cvta.to.shared.u64 t, %1; cvt.u32.u64 %0, t; }"
        : "=r"(a) : "l"(p));
    return a;
}

#define CP_ASYNC16(dst, src) \
    asm volatile("cp.async.cg.shared.global [%0], [%1], 16;" :: "r"(dst), "l"(src))
#define CP_COMMIT() asm volatile("cp.async.commit_group;" ::: "memory")
#define CP_WAIT1()  asm volatile("cp.async.wait_group 1;" ::: "memory")

#define SSTRB 80

struct MultiOut {
    const void* W[4];
    const float* bias[4];
    __half* C[4];
};

#define LDMX4(r0, r1, r2, r3, addr) \
    asm volatile("ldmatrix.sync.aligned.m8n8.x4.shared.b16 {%0,%1,%2,%3}, [%4];" \
                 : "=r"(r0), "=r"(r1), "=r"(r2), "=r"(r3) : "r"(addr))

#define MMA_FP16(acc, a, b) \
    asm volatile("mma.sync.aligned.m16n8k16.row.col.f32.f16.f16.f32 " \
                 "{%0,%1,%2,%3}, {%4,%5,%6,%7}, {%8,%9}, {%0,%1,%2,%3};" \
                 : "+f"((acc)[0]), "+f"((acc)[1]), "+f"((acc)[2]), "+f"((acc)[3]) \
                 : "r"((a)[0]), "r"((a)[1]), "r"((a)[2]), "r"((a)[3]), \
                   "r"((b)[0]), "r"((b)[1]))

// ---------------------------------------------------------------------------
// fp16 single-pass multi-output GEMM: C_b[M,128] = A[M,S] @ W_b[128,S]^T (+bias)
// fp16 output. grid = (NBLK, ceil(M/128)), 256 threads, double-buffered.
// ---------------------------------------------------------------------------
#define P1_OFF_A 0
#define P1_OFF_W 20480
#define SMEM_1P  40960

__global__ __launch_bounds__(256) void gemm_fp16_1p(
    const __half* __restrict__ A, MultiOut p, int M, int S)
{
    extern __shared__ char sm[];
    const uint32_t sb = smem_u32(sm);
    const int tid = threadIdx.x, lane = tid & 31, warp = tid >> 5;
    const int mQ = warp >> 1, nH = warp & 1;
    const int rowBase = blockIdx.y * 128;
    const __half* __restrict__ W = (const __half*)p.W[blockIdx.x];
    const float* __restrict__ bias = p.bias[blockIdx.x];
    __half* __restrict__ C = p.C[blockIdx.x];
    const int NC = S >> 5;

    float acc[2][8][4];
#pragma unroll
    for (int i = 0; i < 2; i++)
#pragma unroll
        for (int j = 0; j < 8; j++)
#pragma unroll
            for (int q = 0; q < 4; q++) acc[i][j][q] = 0.f;

    const int lr4 = tid >> 2, lq4 = tid & 3;

#define LOAD1(c, buf) do { \
    int k0 = (c) * 32; \
    _Pragma("unroll") \
    for (int i = 0; i < 2; i++) { \
        int r = lr4 + i * 64; \
        int ga = rowBase + r; if (ga >= M) ga = M - 1; \
        uint32_t so = (buf) * 10240 + r * SSTRB + lq4 * 16; \
        CP_ASYNC16(sb + P1_OFF_A + so, A + (size_t)ga * S + k0 + lq4 * 8); \
        CP_ASYNC16(sb + P1_OFF_W + so, W + (size_t)r * S + k0 + lq4 * 8); \
    } } while (0)

    LOAD1(0, 0); CP_COMMIT();
    if (NC > 1) { LOAD1(1, 1); }
    CP_COMMIT();

    const int a_row = lane & 15;
    const int a_sel = (lane >> 4) & 1;
    const int b_row = (lane & 7) + ((lane & 16) >> 1);
    const int b_sel = (lane >> 3) & 1;

    for (int c = 0; c < NC; c++) {
        CP_WAIT1();
        __syncthreads();
        uint32_t bo = (uint32_t)(c & 1) * 10240;
        uint32_t abase = sb + P1_OFF_A + bo;
        uint32_t wbase = sb + P1_OFF_W + bo;
#pragma unroll
        for (int kh = 0; kh < 2; kh++) {
            uint32_t ar[2][4], br[8][2];
#pragma unroll
            for (int mi = 0; mi < 2; mi++) {
                uint32_t addr = abase + (mQ * 32 + mi * 16 + a_row) * SSTRB
                                + kh * 32 + a_sel * 16;
                LDMX4(ar[mi][0], ar[mi][1], ar[mi][2], ar[mi][3], addr);
            }
#pragma unroll
            for (int pi = 0; pi < 4; pi++) {
                uint32_t addr = wbase + (nH * 64 + pi * 16 + b_row) * SSTRB
                                + kh * 32 + b_sel * 16;
                LDMX4(br[2 * pi][0], br[2 * pi][1],
                      br[2 * pi + 1][0], br[2 * pi + 1][1], addr);
            }
#pragma unroll
            for (int mi = 0; mi < 2; mi++)
#pragma unroll
                for (int ni = 0; ni < 8; ni++)
                    MMA_FP16(acc[mi][ni], ar[mi], br[ni]);
        }
        __syncthreads();
        if (c + 2 < NC) LOAD1(c + 2, c & 1);
        CP_COMMIT();
    }
#undef LOAD1

    const int g = lane >> 2, t = lane & 3;
#pragma unroll
    for (int mi = 0; mi < 2; mi++) {
        int r0 = rowBase + mQ * 32 + mi * 16 + g;
#pragma unroll
        for (int ni = 0; ni < 8; ni++) {
            int col = nH * 64 + ni * 8 + t * 2;
            float bx = 0.f, by2 = 0.f;
            if (bias) { bx = bias[col]; by2 = bias[col + 1]; }
            if (r0 < M) {
                __half2 v = __floats2half2_rn(acc[mi][ni][0] + bx, acc[mi][ni][1] + by2);
                *(__half2*)(C + (size_t)r0 * 128 + col) = v;
            }
            if (r0 + 8 < M) {
                __half2 v = __floats2half2_rn(acc[mi][ni][2] + bx, acc[mi][ni][3] + by2);
                *(__half2*)(C + (size_t)(r0 + 8) * 128 + col) = v;
            }
        }
    }
}

// ---------------------------------------------------------------------------
// Converts
// ---------------------------------------------------------------------------
__global__ void conv_feat3(const float* __restrict__ x0, const float* __restrict__ x1,
                           const float* __restrict__ x2, __half* __restrict__ outA)
{
    int row = blockIdx.x;
    int k = threadIdx.x * 4;
    if (k >= K1S) return;
    const float* src;
    if (row < N_ART) src = x0 + (size_t)row * FEATD;
    else if (row < N_ART + N_ENT) src = x1 + (size_t)(row - N_ART) * FEATD;
    else src = x2 + (size_t)(row - N_ART - N_ENT) * FEATD;
    __half h[4];
#pragma unroll
    for (int j = 0; j < 4; j++) {
        int kk = k + j;
        h[j] = __float2half((kk < FEATD) ? src[kk] : 0.f);
    }
    *(uint2*)(outA + (size_t)row * K1S + k) = *(uint2*)h;
}

__global__ void conv_fp16(const float* __restrict__ in,
                          __half* __restrict__ outA, int K, int S)
{
    int row = blockIdx.x;
    int k = threadIdx.x * 4;
    if (k >= S) return;
    const float* src = in + (size_t)row * K;
    __half h[4];
#pragma unroll
    for (int j = 0; j < 4; j++) {
        int kk = k + j;
        h[j] = __float2half((kk < K) ? src[kk] : 0.f);
    }
    *(uint2*)(outA + (size_t)row * S + k) = *(uint2*)h;
}

// ---------------------------------------------------------------------------
// CSR build
// ---------------------------------------------------------------------------
struct EdgePtrs { const int* e[5]; };

__global__ void count5_k(EdgePtrs ep, int* __restrict__ cnt, int E)
{
    int i = blockIdx.y;
    int e = blockIdx.x * blockDim.x + threadIdx.x;
    if (e < E) atomicAdd(&cnt[i * 100000 + ep.e[i][E + e]], 1);
}

__constant__ int c_dstN[5] = {100000, 50000, 50000, 50000, 100000};

__global__ void scan5_k(const int* __restrict__ cnt, int* __restrict__ off)
{
    __shared__ int sh[32];
    __shared__ int carry;
    int type = blockIdx.x;
    const int n = c_dstN[type];
    const int* c = cnt + type * 100000;
    int* o = off + type * 100032;
    int tid = threadIdx.x, lane = tid & 31, w = tid >> 5;
    if (tid == 0) carry = 0;
    __syncthreads();
    for (int base = 0; base < n; base += 1024) {
        int i = base + tid;
        int v = (i < n) ? c[i] : 0;
        int x = v;
#pragma unroll
        for (int d = 1; d < 32; d <<= 1) {
            int y = __shfl_up_sync(0xffffffffu, x, d);
            if (lane >= d) x += y;
        }
        if (lane == 31) sh[w] = x;
        __syncthreads();
        if (w == 0) {
            int s = sh[lane];
#pragma unroll
            for (int d = 1; d < 32; d <<= 1) {
                int y = __shfl_up_sync(0xffffffffu, s, d);
                if (lane >= d) s += y;
            }
            sh[lane] = s;
        }
        __syncthreads();
        int excl = x - v + (w > 0 ? sh[w - 1] : 0) + carry;
        if (i < n) o[i] = excl;
        __syncthreads();
        if (tid == 1023) carry = excl + v;
        __syncthreads();
    }
    if (tid == 0) o[n] = carry;
}

__global__ void fill5_k(EdgePtrs ep, const int* __restrict__ off, int* __restrict__ cursor,
                        int* __restrict__ srcA, int E)
{
    int i = blockIdx.y;
    int e = blockIdx.x * blockDim.x + threadIdx.x;
    if (e >= E) return;
    int d = ep.e[i][E + e];
    int pos = atomicAdd(&cursor[i * 100000 + d], 1);
    srcA[i * 200000 + off[i * 100032 + d] + pos] = ep.e[i][e];
}

// ---------------------------------------------------------------------------
// Fused gather + mean + lin_l + L2-normalize + relu + sum over <=2 edge types
// fp16 inputs; fp32 math; output fp16 (layer 1) or fp32 (layer 2, to d_out)
// ---------------------------------------------------------------------------
__device__ __forceinline__ float4 ld_half4(const __half* p) {
    uint2 raw = *(const uint2*)p;
    __half2 h0 = *(__half2*)&raw.x;
    __half2 h1 = *(__half2*)&raw.y;
    float2 f0 = __half22float2(h0);
    float2 f1 = __half22float2(h1);
    return make_float4(f0.x, f0.y, f1.x, f1.y);
}

template<bool TWO, bool OUT_HALF>
__global__ void combine2(
    const __half* __restrict__ B0, const __half* __restrict__ P0,
    const int* __restrict__ off0, const int* __restrict__ src0,
    const __half* __restrict__ B1, const __half* __restrict__ P1,
    const int* __restrict__ off1, const int* __restrict__ src1,
    void* __restrict__ out, int n)
{
    int w = (blockIdx.x * blockDim.x + threadIdx.x) >> 5;
    int lane = threadIdx.x & 31;
    if (w >= n) return;
    size_t o = (size_t)w * HIDD + lane * 4;
    float4 r = make_float4(0.f, 0.f, 0.f, 0.f);

    {
        float4 b = ld_half4(B0 + o);
        int beg = __ldg(off0 + w), end = __ldg(off0 + w + 1);
        float4 a = make_float4(0.f, 0.f, 0.f, 0.f);
        for (int e = beg; e < end; e++) {
            int s = __ldg(src0 + e);
            float4 p = ld_half4(P0 + (size_t)s * HIDD + lane * 4);
            a.x += p.x; a.y += p.y; a.z += p.z; a.w += p.w;
        }
        float inv = 1.0f / fmaxf((float)(end - beg), 1.0f);
        float4 t;
        t.x = b.x + a.x * inv; t.y = b.y + a.y * inv;
        t.z = b.z + a.z * inv; t.w = b.w + a.w * inv;
        float ss = t.x * t.x + t.y * t.y + t.z * t.z + t.w * t.w;
#pragma unroll
        for (int sh = 16; sh; sh >>= 1) ss += __shfl_xor_sync(0xffffffffu, ss, sh);
        float sc = 1.0f / fmaxf(sqrtf(ss), 1e-12f);
        r.x += t.x * sc; r.y += t.y * sc; r.z += t.z * sc; r.w += t.w * sc;
    }
    if (TWO) {
        float4 b = ld_half4(B1 + o);
        int beg = __ldg(off1 + w), end = __ldg(off1 + w + 1);
        float4 a = make_float4(0.f, 0.f, 0.f, 0.f);
        for (int e = beg; e < end; e++) {
            int s = __ldg(src1 + e);
            float4 p = ld_half4(P1 + (size_t)s * HIDD + lane * 4);
            a.x += p.x; a.y += p.y; a.z += p.z; a.w += p.w;
        }
        float inv = 1.0f / fmaxf((float)(end - beg), 1.0f);
        float4 t;
        t.x = b.x + a.x * inv; t.y = b.y + a.y * inv;
        t.z = b.z + a.z * inv; t.w = b.w + a.w * inv;
        float ss = t.x * t.x + t.y * t.y + t.z * t.z + t.w * t.w;
#pragma unroll
        for (int sh = 16; sh; sh >>= 1) ss += __shfl_xor_sync(0xffffffffu, ss, sh);
        float sc = 1.0f / fmaxf(sqrtf(ss), 1e-12f);
        r.x += t.x * sc; r.y += t.y * sc; r.z += t.z * sc; r.w += t.w * sc;
    }
    // relu (applies after both layers in the reference)
    r.x = fmaxf(r.x, 0.f); r.y = fmaxf(r.y, 0.f);
    r.z = fmaxf(r.z, 0.f); r.w = fmaxf(r.w, 0.f);

    if (OUT_HALF) {
        __half h[4];
        h[0] = __float2half(r.x); h[1] = __float2half(r.y);
        h[2] = __float2half(r.z); h[3] = __float2half(r.w);
        *(uint2*)((__half*)out + o) = *(uint2*)h;
    } else {
        *(float4*)((float*)out + o) = r;
    }
}

// ---------------------------------------------------------------------------
// SIMT GEMM for the 64-wide head
// ---------------------------------------------------------------------------
template<bool RELU_OUT>
__global__ __launch_bounds__(256) void gemm_tn(
    const float* __restrict__ A, const float* __restrict__ W,
    const float* __restrict__ bias, float* __restrict__ C,
    int M, int N, int K)
{
    __shared__ float As[8][128];
    __shared__ float Ws[8][128];
    const int tid = threadIdx.x;
    const int tx = tid & 15, ty = tid >> 4;
    const int rowBase = blockIdx.y * 128;

    float acc[8][8];
#pragma unroll
    for (int i = 0; i < 8; i++)
#pragma unroll
        for (int j = 0; j < 8; j++) acc[i][j] = 0.f;

    for (int k0 = 0; k0 < K; k0 += 8) {
#pragma unroll
        for (int t = 0; t < 4; t++) {
            int idx = tid + t * 256;
            int k = idx & 7, r = idx >> 3;
            int row = rowBase + r, kk = k0 + k;
            float v = 0.f;
            if (row < M && kk < K) v = A[(size_t)row * K + kk];
            As[k][r] = v;
        }
#pragma unroll
        for (int t = 0; t < 4; t++) {
            int idx = tid + t * 256;
            int k = idx & 7, c = idx >> 3;
            int kk = k0 + k;
            float v = 0.f;
            if (c < N && kk < K) v = W[(size_t)c * K + kk];
            Ws[k][c] = v;
        }
        __syncthreads();
#pragma unroll
        for (int k = 0; k < 8; k++) {
            float4 a0 = *(const float4*)&As[k][ty * 8];
            float4 a1 = *(const float4*)&As[k][ty * 8 + 4];
            float4 b0 = *(const float4*)&Ws[k][tx * 8];
            float4 b1 = *(const float4*)&Ws[k][tx * 8 + 4];
            float av[8] = {a0.x, a0.y, a0.z, a0.w, a1.x, a1.y, a1.z, a1.w};
            float bv[8] = {b0.x, b0.y, b0.z, b0.w, b1.x, b1.y, b1.z, b1.w};
#pragma unroll
            for (int i = 0; i < 8; i++)
#pragma unroll
                for (int j = 0; j < 8; j++) acc[i][j] += av[i] * bv[j];
        }
        __syncthreads();
    }

#pragma unroll
    for (int i = 0; i < 8; i++) {
        int row = rowBase + ty * 8 + i;
        if (row < M) {
#pragma unroll
            for (int j = 0; j < 8; j++) {
                int col = tx * 8 + j;
                if (col < N) {
                    float v = acc[i][j] + bias[col];
                    if (RELU_OUT) v = fmaxf(v, 0.f);
                    C[(size_t)row * N + col] = v;
                }
            }
        }
    }
}

__global__ void head2_k(const float* __restrict__ Z, const float* __restrict__ W2,
                        const float* __restrict__ b2, float* __restrict__ out, int n)
{
    int row = blockIdx.x * blockDim.x + threadIdx.x;
    if (row >= n) return;
    float acc0 = b2[0], acc1 = b2[1];
    const float* z = Z + (size_t)row * 64;
#pragma unroll
    for (int k = 0; k < 64; k++) {
        float zv = z[k];
        acc0 += zv * __ldg(W2 + k);
        acc1 += zv * __ldg(W2 + 64 + k);
    }
    out[row * 2 + 0] = acc0;
    out[row * 2 + 1] = acc1;
}

// ---------------------------------------------------------------------------
extern "C" void kernel_launch(void* const* d_in, const int* in_sizes, int n_in,
                              void* d_out_, int out_size)
{
    const float* x[3] = {(const float*)d_in[0], (const float*)d_in[1], (const float*)d_in[2]};
    const int nn[3] = {N_ART, N_ENT, N_FACT};
    const int* ei[5];
    for (int i = 0; i < 5; i++) ei[i] = (const int*)d_in[3 + i];
    const float* c1llw = (const float*)d_in[8];
    const float* c1llb = (const float*)d_in[9];
    const float* c1lrw = (const float*)d_in[10];
    const float* c2llw = (const float*)d_in[11];
    const float* c2llb = (const float*)d_in[12];
    const float* c2lrw = (const float*)d_in[13];
    const float* hw1 = (const float*)d_in[14];
    const float* hb1 = (const float*)d_in[15];
    const float* hw2 = (const float*)d_in[16];
    const float* hb2 = (const float*)d_in[17];
    float* out = (float*)d_out_;

    static const size_t BOFF[5] = {0, 100000, 150000, 200000, 250000};
    static const size_t POFF[5] = {0, 50000, 100000, 200000, 300000};

    float *Z;
    __half *B5, *P5, *Xh, *H1h, *W1L, *W1R, *W2L, *W2R;
    int *CUR, *OFFS, *SRCA;
    cudaGetSymbolAddress((void**)&B5, g_B5);
    cudaGetSymbolAddress((void**)&P5, g_P5);
    cudaGetSymbolAddress((void**)&Z, g_z);
    cudaGetSymbolAddress((void**)&Xh, g_Xh);
    cudaGetSymbolAddress((void**)&H1h, g_H1h);
    cudaGetSymbolAddress((void**)&W1L, g_W1L);
    cudaGetSymbolAddress((void**)&W1R, g_W1R);
    cudaGetSymbolAddress((void**)&W2L, g_W2L);
    cudaGetSymbolAddress((void**)&W2R, g_W2R);
    cudaGetSymbolAddress((void**)&CUR, g_cursor);
    cudaGetSymbolAddress((void**)&OFFS, g_off);
    cudaGetSymbolAddress((void**)&SRCA, g_srcA);

    cudaFuncSetAttribute(gemm_fp16_1p, cudaFuncAttributeMaxDynamicSharedMemorySize, SMEM_1P);

    const size_t XHB[3] = {0, (size_t)N_ART * K1S, (size_t)(N_ART + N_ENT) * K1S};
    const size_t R0[3] = {0, (size_t)N_ART, (size_t)(N_ART + N_ENT)};

    __half* h1p[3] = {H1h, H1h + (size_t)N_ART * HIDD, H1h + (size_t)(N_ART + N_ENT) * HIDD};
    float* h2p[3] = {out + 100000,
                     out + 100000 + (size_t)N_ART * HIDD,
                     out + 100000 + (size_t)(N_ART + N_ENT) * HIDD};

    const int NBLK[3] = {3, 4, 3};
    const int LLe[3][2] = {{2, -1}, {0, 4}, {1, 3}};
    const int LRe[3][2] = {{0, 1}, {2, 3}, {4, -1}};

    const size_t WB1B = (size_t)128 * K1S * 2;
    const size_t WB2B = (size_t)128 * K2S * 2;

    auto make_outs = [&](int layer, int t) {
        MultiOut p;
        const char* WL = layer ? (const char*)W2L : (const char*)W1L;
        const char* WR = layer ? (const char*)W2R : (const char*)W1R;
        const float* bb = layer ? c2llb : c1llb;
        const size_t WBB = layer ? WB2B : WB1B;
        int nb = 0;
        for (int j = 0; j < 2; j++) {
            int e = LLe[t][j];
            if (e < 0) break;
            p.W[nb] = WL + (size_t)e * WBB;
            p.bias[nb] = bb + e * HIDD;
            p.C[nb] = B5 + BOFF[e] * HIDD;
            nb++;
        }
        for (int j = 0; j < 2; j++) {
            int e = LRe[t][j];
            if (e < 0) break;
            p.W[nb] = WR + (size_t)e * WBB;
            p.bias[nb] = nullptr;
            p.C[nb] = P5 + POFF[e] * HIDD;
            nb++;
        }
        return p;
    };

    // --- launches 0-2: converts needed for layer-1 GEMMs ---
    conv_feat3<<<200000, 256>>>(x[0], x[1], x[2], Xh);
    conv_fp16<<<640, 256>>>(c1llw, W1L, FEATD, K1S);
    conv_fp16<<<640, 256>>>(c1lrw, W1R, FEATD, K1S);

    // --- launches 3-5: layer-1 GEMMs (ncu capture lands here) ---
    for (int t = 1; t >= 0; t--) {
        MultiOut p = make_outs(0, t);
        gemm_fp16_1p<<<dim3(NBLK[t], (nn[t] + 127) / 128), 256, SMEM_1P>>>(
            Xh + XHB[t], p, nn[t], K1S);
    }
    {
        MultiOut p = make_outs(0, 2);
        gemm_fp16_1p<<<dim3(NBLK[2], (nn[2] + 127) / 128), 256, SMEM_1P>>>(
            Xh + XHB[2], p, nn[2], K1S);
    }

    // --- CSR build + W2 converts ---
    EdgePtrs ep;
    for (int i = 0; i < 5; i++) ep.e[i] = ei[i];
    cudaMemsetAsync(CUR, 0, 500000 * sizeof(int));
    count5_k<<<dim3((NEDGE + 255) / 256, 5), 256>>>(ep, CUR, NEDGE);
    scan5_k<<<5, 1024>>>(CUR, OFFS);
    cudaMemsetAsync(CUR, 0, 500000 * sizeof(int));
    fill5_k<<<dim3((NEDGE + 255) / 256, 5), 256>>>(ep, OFFS, CUR, SRCA, NEDGE);
    conv_fp16<<<640, 32>>>(c2llw, W2L, HIDD, K2S);
    conv_fp16<<<640, 32>>>(c2lrw, W2R, HIDD, K2S);

    // --- layer-1 combines: relu fused, fp16 out directly into H1h ---
    combine2<false, true><<<(N_ART + 7) / 8, 256>>>(
        B5 + BOFF[2] * HIDD, P5 + POFF[2] * HIDD, OFFS + 2 * 100032, SRCA + 2 * 200000,
        nullptr, nullptr, nullptr, nullptr, h1p[0], N_ART);
    combine2<true, true><<<(N_ENT + 7) / 8, 256>>>(
        B5 + BOFF[0] * HIDD, P5 + POFF[0] * HIDD, OFFS + 0 * 100032, SRCA + 0 * 200000,
        B5 + BOFF[4] * HIDD, P5 + POFF[4] * HIDD, OFFS + 4 * 100032, SRCA + 4 * 200000,
        h1p[1], N_ENT);
    combine2<true, true><<<(N_FACT + 7) / 8, 256>>>(
        B5 + BOFF[1] * HIDD, P5 + POFF[1] * HIDD, OFFS + 1 * 100032, SRCA + 1 * 200000,
        B5 + BOFF[3] * HIDD, P5 + POFF[3] * HIDD, OFFS + 3 * 100032, SRCA + 3 * 200000,
        h1p[2], N_FACT);

    // --- layer-2 GEMMs (fp16 single-pass) ---
    for (int t = 1; t >= 0; t--) {
        MultiOut p = make_outs(1, t);
        gemm_fp16_1p<<<dim3(NBLK[t], (nn[t] + 127) / 128), 256, SMEM_1P>>>(
            H1h + R0[t] * K2S, p, nn[t], K2S);
    }
    {
        MultiOut p = make_outs(1, 2);
        gemm_fp16_1p<<<dim3(NBLK[2], (nn[2] + 127) / 128), 256, SMEM_1P>>>(
            H1h + R0[2] * K2S, p, nn[2], K2S);
    }

    // --- layer-2 combines: relu fused, fp32 out (d_out dtype) ---
    combine2<false, false><<<(N_ART + 7) / 8, 256>>>(
        B5 + BOFF[2] * HIDD, P5 + POFF[2] * HIDD, OFFS + 2 * 100032, SRCA + 2 * 200000,
        nullptr, nullptr, nullptr, nullptr, h2p[0], N_ART);
    combine2<true, false><<<(N_ENT + 7) / 8, 256>>>(
        B5 + BOFF[0] * HIDD, P5 + POFF[0] * HIDD, OFFS + 0 * 100032, SRCA + 0 * 200000,
        B5 + BOFF[4] * HIDD, P5 + POFF[4] * HIDD, OFFS + 4 * 100032, SRCA + 4 * 200000,
        h2p[1], N_ENT);
    combine2<true, false><<<(N_FACT + 7) / 8, 256>>>(
        B5 + BOFF[1] * HIDD, P5 + POFF[1] * HIDD, OFFS + 1 * 100032, SRCA + 1 * 200000,
        B5 + BOFF[3] * HIDD, P5 + POFF[3] * HIDD, OFFS + 3 * 100032, SRCA + 3 * 200000,
        h2p[2], N_FACT);

    // --- head MLP ---
    gemm_tn<true><<<dim3(1, (N_ART + 127) / 128), 256>>>(
        out + 100000, hw1, hb1, Z, N_ART, 64, HIDD);
    head2_k<<<(N_ART + 255) / 256, 256>>>(Z, hw2, hb2, out, N_ART);
}